// round 2
// baseline (speedup 1.0000x reference)
#include <cuda_runtime.h>
#include <math.h>

#define Bb 8
#define Tt 128
#define Nn 256
#define Dd 64
#define D3 192
#define BTND 16777216   // 8*128*256*64
#define MROWS 262144    // B*T*N == B*N*T

// ---------------- device scratch ----------------
__device__ float g_Q[BTND];
__device__ float g_K[BTND];
__device__ float g_V[BTND];
__device__ float g_ALN[BTND];          // aligner output, [B,T,N,D]
__device__ float g_X1[BTND];           // post-ln1, [B,N,T,D]
__device__ float g_GI[50331648];       // [B,N,T,192]
__device__ float g_GRU[BTND];          // [B,N,T,D]
__device__ float g_ADP[Nn*Nn];
__device__ float g_ADPT[Nn*Nn];

__device__ __forceinline__ float sigf(float x) { return 1.0f / (1.0f + __expf(-x)); }

// ---------------- adjacency: adp = softmax_row(relu(e1@e2)) ----------------
__global__ void k_adj(const float* __restrict__ e1, const float* __restrict__ e2) {
    int m = blockIdx.x;
    int n = threadIdx.x;            // 256 threads
    float a = 0.f;
#pragma unroll
    for (int k = 0; k < 32; k++) a = fmaf(e1[m*32 + k], e2[k*256 + n], a);
    a = fmaxf(a, 0.f);
    __shared__ float red[256];
    red[n] = a; __syncthreads();
    for (int s = 128; s > 0; s >>= 1) { if (n < s) red[n] = fmaxf(red[n], red[n+s]); __syncthreads(); }
    float mx = red[0]; __syncthreads();
    float e = expf(a - mx);
    red[n] = e; __syncthreads();
    for (int s = 128; s > 0; s >>= 1) { if (n < s) red[n] += red[n+s]; __syncthreads(); }
    float v = e / red[0];
    g_ADP[m*256 + n]  = v;
    g_ADPT[n*256 + m] = v;
}

// ---------------- generic 64-K GEMM: Y[m, n0+..] = X[m,:] @ W^T + b ----------------
__device__ __forceinline__ void gemm_body(const float* __restrict__ X,
                                          const float* __restrict__ W,
                                          const float* __restrict__ bias,
                                          float* __restrict__ Y, int ncols) {
    __shared__ float Xs[64*68];
    __shared__ float Ws[64*68];
    int m0 = blockIdx.x * 64;
    int n0 = blockIdx.y * 64;
    int tid = threadIdx.x;
    for (int idx = tid; idx < 1024; idx += 256) {
        int r = idx >> 4, c4 = idx & 15;
        float4 xv = *(const float4*)(X + (size_t)(m0 + r)*64 + c4*4);
        *(float4*)(Xs + r*68 + c4*4) = xv;
        float4 wv = *(const float4*)(W + (size_t)(n0 + r)*64 + c4*4);
        *(float4*)(Ws + r*68 + c4*4) = wv;
    }
    __syncthreads();
    int ty = tid >> 4, tx = tid & 15;
    float acc[4][4] = {};
#pragma unroll 4
    for (int k4 = 0; k4 < 16; k4++) {
        float4 xa[4], wb[4];
#pragma unroll
        for (int u = 0; u < 4; u++) xa[u] = *(const float4*)(Xs + (ty*4+u)*68 + k4*4);
#pragma unroll
        for (int v = 0; v < 4; v++) wb[v] = *(const float4*)(Ws + (tx*4+v)*68 + k4*4);
#pragma unroll
        for (int u = 0; u < 4; u++)
#pragma unroll
            for (int v = 0; v < 4; v++) {
                acc[u][v] = fmaf(xa[u].x, wb[v].x, acc[u][v]);
                acc[u][v] = fmaf(xa[u].y, wb[v].y, acc[u][v]);
                acc[u][v] = fmaf(xa[u].z, wb[v].z, acc[u][v]);
                acc[u][v] = fmaf(xa[u].w, wb[v].w, acc[u][v]);
            }
    }
    float b0 = bias[n0 + tx*4 + 0], b1 = bias[n0 + tx*4 + 1],
          b2 = bias[n0 + tx*4 + 2], b3 = bias[n0 + tx*4 + 3];
#pragma unroll
    for (int u = 0; u < 4; u++) {
        int m = m0 + ty*4 + u;
        float4 o;
        o.x = acc[u][0] + b0; o.y = acc[u][1] + b1;
        o.z = acc[u][2] + b2; o.w = acc[u][3] + b3;
        *(float4*)(Y + (size_t)m*ncols + n0 + tx*4) = o;
    }
}

__global__ void k_projQ(const float* X, const float* W, const float* b) { gemm_body(X, W, b, g_Q, 64); }
__global__ void k_projK(const float* X, const float* W, const float* b) { gemm_body(X, W, b, g_K, 64); }
__global__ void k_projV(const float* X, const float* W, const float* b) { gemm_body(X, W, b, g_V, 64); }
__global__ void k_gi(const float* W, const float* b)                    { gemm_body(g_X1, W, b, g_GI, 192); }

// ---------------- per-(b,n) temporal attention ----------------
// smem: QK region 16896 floats (Qs k-major [64][132], Ks at +8448; later Vs [128][68] overlays),
//       Ps [128][132] = 16896, biasr 128. Total 33920 floats = 135680 B.
__global__ void __launch_bounds__(256, 1) k_attn(const float* __restrict__ lg,
                                                 const float* __restrict__ lt) {
    extern __shared__ float sm[];
    float* QK    = sm;
    float* Ps    = sm + 16896;
    float* biasr = sm + 33792;

    int tid = threadIdx.x;
    int bn = blockIdx.x;
    int b = bn >> 8, n = bn & 255;

    float gamma = fmaxf(expf(*lg), 0.01f);
    float tau   = fmaxf(expf(*lt), 0.01f);
    float scale = 1.0f / (8.0f * tau);

    if (tid < 128) biasr[tid] = logf(expf(-gamma * (float)tid * (1.0f/127.0f)) + 1e-8f);

    // load Q,K transposed (k-major) into smem
    for (int idx = tid; idx < 2048; idx += 256) {
        int i = idx >> 4, c4 = idx & 15;
        size_t g = ((size_t)(b*Tt + i)*Nn + n)*Dd + c4*4;
        float4 q = *(const float4*)(g_Q + g);
        float4 kk = *(const float4*)(g_K + g);
        QK[(c4*4+0)*132 + i] = q.x;  QK[(c4*4+1)*132 + i] = q.y;
        QK[(c4*4+2)*132 + i] = q.z;  QK[(c4*4+3)*132 + i] = q.w;
        QK[8448 + (c4*4+0)*132 + i] = kk.x;  QK[8448 + (c4*4+1)*132 + i] = kk.y;
        QK[8448 + (c4*4+2)*132 + i] = kk.z;  QK[8448 + (c4*4+3)*132 + i] = kk.w;
    }
    __syncthreads();

    int ty = tid >> 4, tx = tid & 15;
    int i0 = ty * 8, j0 = tx * 8;
    float s[8][8] = {};
#pragma unroll 4
    for (int k = 0; k < 64; k++) {
        float4 q0 = *(const float4*)(QK + k*132 + i0);
        float4 q1 = *(const float4*)(QK + k*132 + i0 + 4);
        float4 k0 = *(const float4*)(QK + 8448 + k*132 + j0);
        float4 k1 = *(const float4*)(QK + 8448 + k*132 + j0 + 4);
        float qa[8] = {q0.x,q0.y,q0.z,q0.w,q1.x,q1.y,q1.z,q1.w};
        float kb[8] = {k0.x,k0.y,k0.z,k0.w,k1.x,k1.y,k1.z,k1.w};
#pragma unroll
        for (int u = 0; u < 8; u++)
#pragma unroll
            for (int v = 0; v < 8; v++) s[u][v] = fmaf(qa[u], kb[v], s[u][v]);
    }
    // write S with scale + temporal bias
#pragma unroll
    for (int u = 0; u < 8; u++) {
        int i = i0 + u;
#pragma unroll
        for (int v = 0; v < 8; v++) {
            int j = j0 + v;
            int dd = i - j; dd = dd < 0 ? -dd : dd;
            Ps[i*132 + j] = s[u][v]*scale + biasr[dd];
        }
    }
    __syncthreads();

    // load V (row-major [128][68]) overlaying QK region
    for (int idx = tid; idx < 2048; idx += 256) {
        int i = idx >> 4, c4 = idx & 15;
        float4 v = *(const float4*)(g_V + ((size_t)(b*Tt + i)*Nn + n)*Dd + c4*4);
        *(float4*)(QK + i*68 + c4*4) = v;
    }
    // softmax rows (warp per 16 rows)
    int w = tid >> 5, lane = tid & 31;
    for (int rr = 0; rr < 16; rr++) {
        int i = w*16 + rr;
        float v0 = Ps[i*132 + lane], v1 = Ps[i*132 + lane + 32],
              v2 = Ps[i*132 + lane + 64], v3 = Ps[i*132 + lane + 96];
        float mx = fmaxf(fmaxf(v0, v1), fmaxf(v2, v3));
#pragma unroll
        for (int off = 16; off > 0; off >>= 1) mx = fmaxf(mx, __shfl_xor_sync(0xffffffff, mx, off));
        float e0 = __expf(v0 - mx), e1 = __expf(v1 - mx), e2 = __expf(v2 - mx), e3 = __expf(v3 - mx);
        float su = (e0 + e1) + (e2 + e3);
#pragma unroll
        for (int off = 16; off > 0; off >>= 1) su += __shfl_xor_sync(0xffffffff, su, off);
        float inv = 1.0f / su;
        Ps[i*132 + lane]      = e0 * inv;
        Ps[i*132 + lane + 32] = e1 * inv;
        Ps[i*132 + lane + 64] = e2 * inv;
        Ps[i*132 + lane + 96] = e3 * inv;
    }
    __syncthreads();

    // out = P @ V  (thread: 8 i x 4 d)
    int d0 = tx * 4;
    float4 acc[8];
#pragma unroll
    for (int u = 0; u < 8; u++) acc[u] = make_float4(0.f, 0.f, 0.f, 0.f);
#pragma unroll 4
    for (int j = 0; j < 128; j++) {
        float4 vv = *(const float4*)(QK + j*68 + d0);
#pragma unroll
        for (int u = 0; u < 8; u++) {
            float p = Ps[(i0+u)*132 + j];
            acc[u].x = fmaf(p, vv.x, acc[u].x);
            acc[u].y = fmaf(p, vv.y, acc[u].y);
            acc[u].z = fmaf(p, vv.z, acc[u].z);
            acc[u].w = fmaf(p, vv.w, acc[u].w);
        }
    }
#pragma unroll
    for (int u = 0; u < 8; u++) {
        *(float4*)(g_ALN + ((size_t)(b*Tt + i0 + u)*Nn + n)*Dd + d0) = acc[u];
    }
}

// ---------------- GCN + residual + LN1, output transposed to [B,N,T,D] ----------------
// smem: Xs [256][68] = 17408, Tmp [256][68] = 17408, U = max(adp-chunk 8192, H2 16384) = 16384
// total 51200 floats = 204800 B
__global__ void __launch_bounds__(256, 1) k_gcn(const float* __restrict__ Wg,
                                                const float* __restrict__ bg,
                                                const float* __restrict__ ln1g,
                                                const float* __restrict__ ln1b) {
    extern __shared__ float sg[];
    float* Xs  = sg;
    float* Tmp = sg + 17408;
    float* U   = sg + 34816;

    int tid = threadIdx.x;
    int bt = blockIdx.x;
    int b = bt >> 7, t = bt & 127;

    // load x_bt [256][64]
    for (int idx = tid; idx < 4096; idx += 256) {
        int r = idx >> 4, c4 = idx & 15;
        float4 v = *(const float4*)(g_ALN + (size_t)bt*16384 + r*64 + c4*4);
        *(float4*)(Xs + r*68 + c4*4) = v;
    }
    __syncthreads();

    // GEMM1: tmp[m,d] = sum_n adpT[n][m] * x[n][d]
    int ty = tid >> 4, tx = tid & 15;
    int m0 = ty*16, d0 = tx*4;
    float4 acc[16];
#pragma unroll
    for (int u = 0; u < 16; u++) acc[u] = make_float4(0.f, 0.f, 0.f, 0.f);

    for (int c = 0; c < 8; c++) {
        __syncthreads();
        for (int idx = tid; idx < 2048; idx += 256) {
            int r = idx >> 6, c4 = idx & 63;
            *(float4*)(U + r*256 + c4*4) =
                *(const float4*)(g_ADPT + (size_t)(c*32 + r)*256 + c4*4);
        }
        __syncthreads();
#pragma unroll 4
        for (int nn = 0; nn < 32; nn++) {
            float4 xv = *(const float4*)(Xs + (c*32 + nn)*68 + d0);
            float4 a0 = *(const float4*)(U + nn*256 + m0);
            float4 a1 = *(const float4*)(U + nn*256 + m0 + 4);
            float4 a2 = *(const float4*)(U + nn*256 + m0 + 8);
            float4 a3 = *(const float4*)(U + nn*256 + m0 + 12);
            float am[16] = {a0.x,a0.y,a0.z,a0.w, a1.x,a1.y,a1.z,a1.w,
                            a2.x,a2.y,a2.z,a2.w, a3.x,a3.y,a3.z,a3.w};
#pragma unroll
            for (int u = 0; u < 16; u++) {
                acc[u].x = fmaf(am[u], xv.x, acc[u].x);
                acc[u].y = fmaf(am[u], xv.y, acc[u].y);
                acc[u].z = fmaf(am[u], xv.z, acc[u].z);
                acc[u].w = fmaf(am[u], xv.w, acc[u].w);
            }
        }
    }
#pragma unroll
    for (int u = 0; u < 16; u++) *(float4*)(Tmp + (m0+u)*68 + d0) = acc[u];
    __syncthreads();

    // GEMM2: h2[m,e] = relu(sum_d tmp[m,d]*Wg[e,d] + bg[e]) -> U (H2 layout [256][64])
    int w = tid >> 5, lane = tid & 31;
    int e = ((w & 1) << 5) + lane;
    int mb = (w >> 1) << 6;
    float wc[64];
#pragma unroll
    for (int i = 0; i < 16; i++) ((float4*)wc)[i] = *(const float4*)(Wg + e*64 + i*4);
    float bge = bg[e];
    for (int mm = 0; mm < 64; mm++) {
        int m = mb + mm;
        float a = 0.f;
#pragma unroll
        for (int d4 = 0; d4 < 16; d4++) {
            float4 tv = *(const float4*)(Tmp + m*68 + d4*4);
            a = fmaf(wc[d4*4+0], tv.x, a);
            a = fmaf(wc[d4*4+1], tv.y, a);
            a = fmaf(wc[d4*4+2], tv.z, a);
            a = fmaf(wc[d4*4+3], tv.w, a);
        }
        a += bge;
        U[m*64 + e] = fmaxf(a, 0.f);
    }
    __syncthreads();

    // residual + LN1, write transposed to g_X1 [B,N,T,D]
    float gg0 = ln1g[lane], gg1 = ln1g[lane+32];
    float bb0 = ln1b[lane], bb1 = ln1b[lane+32];
    int mrow0 = w * 32;
    for (int mm = 0; mm < 32; mm++) {
        int m = mrow0 + mm;
        float u0 = Xs[m*68 + lane]      + U[m*64 + lane];
        float u1 = Xs[m*68 + lane + 32] + U[m*64 + lane + 32];
        float su = u0 + u1;
#pragma unroll
        for (int off = 16; off > 0; off >>= 1) su += __shfl_xor_sync(0xffffffff, su, off);
        float mean = su * (1.0f/64.0f);
        float dd0 = u0 - mean, dd1 = u1 - mean;
        float q = dd0*dd0 + dd1*dd1;
#pragma unroll
        for (int off = 16; off > 0; off >>= 1) q += __shfl_xor_sync(0xffffffff, q, off);
        float rs = rsqrtf(q*(1.0f/64.0f) + 1e-5f);
        size_t o = ((size_t)(b*Nn + m)*Tt + t)*Dd;
        g_X1[o + lane]      = dd0*rs*gg0 + bb0;
        g_X1[o + lane + 32] = dd1*rs*gg1 + bb1;
    }
}

// ---------------- GRU scan, one block per (b,n) sequence ----------------
__global__ void __launch_bounds__(192) k_gru(const float* __restrict__ Whh,
                                             const float* __restrict__ bhh) {
    __shared__ float h_s[64];
    __shared__ float gh_s[192];
    int tid = threadIdx.x;          // 192
    int bn = blockIdx.x;

    float w[64];
#pragma unroll
    for (int i = 0; i < 16; i++) ((float4*)w)[i] = *(const float4*)(Whh + tid*64 + i*4);
    float bh = bhh[tid];
    if (tid < 64) h_s[tid] = 0.f;

    const float* gi = g_GI + (size_t)bn * Tt * D3;
    float* out = g_GRU + (size_t)bn * Tt * Dd;
    __syncthreads();

    for (int t = 0; t < Tt; t++) {
        float a0 = 0.f, a1 = 0.f, a2 = 0.f, a3 = 0.f;
#pragma unroll
        for (int d4 = 0; d4 < 16; d4++) {
            float4 hv = ((const float4*)h_s)[d4];
            a0 = fmaf(w[d4*4+0], hv.x, a0);
            a1 = fmaf(w[d4*4+1], hv.y, a1);
            a2 = fmaf(w[d4*4+2], hv.z, a2);
            a3 = fmaf(w[d4*4+3], hv.w, a3);
        }
        gh_s[tid] = bh + ((a0 + a1) + (a2 + a3));
        __syncthreads();
        if (tid < 64) {
            const float* gt = gi + t*D3;
            float r  = sigf(gt[tid]       + gh_s[tid]);
            float z  = sigf(gt[64 + tid]  + gh_s[64 + tid]);
            float nn = tanhf(gt[128 + tid] + r * gh_s[128 + tid]);
            float hn = (1.0f - z)*nn + z*h_s[tid];
            h_s[tid] = hn;
            out[t*64 + tid] = hn;
        }
        __syncthreads();
    }
}

// ---------------- final: out = x1 + LN2(x1 + gru), transpose back ----------------
__global__ void k_final(const float* __restrict__ ln2g, const float* __restrict__ ln2b,
                        float* __restrict__ out) {
    int w = threadIdx.x >> 5, lane = threadIdx.x & 31;
    int row = blockIdx.x * 8 + w;        // < 262144, [B,N,T] order
    int b = row >> 15;
    int rem = row & 32767;
    int n = rem >> 7, t = rem & 127;
    const float* xr = g_X1 + (size_t)row*64;
    const float* gr = g_GRU + (size_t)row*64;
    float x0 = xr[lane], x1 = xr[lane+32];
    float u0 = x0 + gr[lane], u1 = x1 + gr[lane+32];
    float su = u0 + u1;
#pragma unroll
    for (int off = 16; off > 0; off >>= 1) su += __shfl_xor_sync(0xffffffff, su, off);
    float mean = su * (1.0f/64.0f);
    float d0 = u0 - mean, d1 = u1 - mean;
    float q = d0*d0 + d1*d1;
#pragma unroll
    for (int off = 16; off > 0; off >>= 1) q += __shfl_xor_sync(0xffffffff, q, off);
    float rs = rsqrtf(q*(1.0f/64.0f) + 1e-5f);
    float y0 = d0*rs*ln2g[lane]    + ln2b[lane];
    float y1 = d1*rs*ln2g[lane+32] + ln2b[lane+32];
    size_t o = ((size_t)(b*Tt + t)*Nn + n)*Dd;
    out[o + lane]      = x0 + y0;
    out[o + lane + 32] = x1 + y1;
}

// ---------------- launcher ----------------
extern "C" void kernel_launch(void* const* d_in, const int* in_sizes, int n_in,
                              void* d_out, int out_size) {
    (void)in_sizes; (void)n_in; (void)out_size;
    const float* H_i  = (const float*)d_in[0];
    const float* H_j  = (const float*)d_in[1];
    const float* Wq   = (const float*)d_in[2];
    const float* bq   = (const float*)d_in[3];
    const float* Wk   = (const float*)d_in[4];
    const float* bk   = (const float*)d_in[5];
    const float* Wv   = (const float*)d_in[6];
    const float* bv   = (const float*)d_in[7];
    const float* lgam = (const float*)d_in[8];
    const float* ltau = (const float*)d_in[9];
    const float* e1   = (const float*)d_in[10];
    const float* e2   = (const float*)d_in[11];
    const float* Wg   = (const float*)d_in[12];
    const float* bg   = (const float*)d_in[13];
    const float* ln1g = (const float*)d_in[14];
    const float* ln1b = (const float*)d_in[15];
    const float* Wih  = (const float*)d_in[16];
    const float* Whh  = (const float*)d_in[17];
    const float* bih  = (const float*)d_in[18];
    const float* bhh  = (const float*)d_in[19];
    const float* ln2g = (const float*)d_in[20];
    const float* ln2b = (const float*)d_in[21];
    float* out = (float*)d_out;

    const int ATTN_SMEM = 33920 * 4;   // 135680 B
    const int GCN_SMEM  = 51200 * 4;   // 204800 B
    cudaFuncSetAttribute(k_attn, cudaFuncAttributeMaxDynamicSharedMemorySize, ATTN_SMEM);
    cudaFuncSetAttribute(k_gcn,  cudaFuncAttributeMaxDynamicSharedMemorySize, GCN_SMEM);

    k_adj<<<256, 256>>>(e1, e2);
    k_projQ<<<dim3(MROWS/64, 1), 256>>>(H_i, Wq, bq);
    k_projK<<<dim3(MROWS/64, 1), 256>>>(H_j, Wk, bk);
    k_projV<<<dim3(MROWS/64, 1), 256>>>(H_j, Wv, bv);
    k_attn<<<Bb*Nn, 256, ATTN_SMEM>>>(lgam, ltau);
    k_gcn<<<Bb*Tt, 256, GCN_SMEM>>>(Wg, bg, ln1g, ln1b);
    k_gi<<<dim3(MROWS/64, 3), 256>>>(Wih, bih);
    k_gru<<<Bb*Nn, 192>>>(Whh, bhh);
    k_final<<<MROWS/8, 256>>>(ln2g, ln2b, out);
}

// round 3
// speedup vs baseline: 1.3062x; 1.3062x over previous
#include <cuda_runtime.h>
#include <math.h>

#define Bb 8
#define Tt 128
#define Nn 256
#define Dd 64
#define D3 192
#define BTND 16777216   // 8*128*256*64
#define MROWS 262144    // B*T*N == B*N*T

// ---------------- device scratch ----------------
__device__ float g_Q[BTND];
__device__ float g_K[BTND];
__device__ float g_V[BTND];
__device__ float g_ALN[BTND];          // aligner output, [B,T,N,D]
__device__ float g_X1[BTND];           // post-ln1, [B,N,T,D]
__device__ float g_GI[50331648];       // [B,N,T,192]
__device__ float g_GRU[BTND];          // [B,N,T,D]
__device__ float g_ADP[Nn*Nn];
__device__ float g_ADPT[Nn*Nn];

__device__ __forceinline__ float sigf(float x) { return 1.0f / (1.0f + __expf(-x)); }

// ---------------- adjacency: adp = softmax_row(relu(e1@e2)) ----------------
__global__ void k_adj(const float* __restrict__ e1, const float* __restrict__ e2) {
    int m = blockIdx.x;
    int n = threadIdx.x;            // 256 threads
    float a = 0.f;
#pragma unroll
    for (int k = 0; k < 32; k++) a = fmaf(e1[m*32 + k], e2[k*256 + n], a);
    a = fmaxf(a, 0.f);
    __shared__ float red[256];
    red[n] = a; __syncthreads();
    for (int s = 128; s > 0; s >>= 1) { if (n < s) red[n] = fmaxf(red[n], red[n+s]); __syncthreads(); }
    float mx = red[0]; __syncthreads();
    float e = expf(a - mx);
    red[n] = e; __syncthreads();
    for (int s = 128; s > 0; s >>= 1) { if (n < s) red[n] += red[n+s]; __syncthreads(); }
    float v = e / red[0];
    g_ADP[m*256 + n]  = v;
    g_ADPT[n*256 + m] = v;
}

// ---------------- linear: Y[m, n0..n0+63] = X[m,:] @ W^T + b ----------------
// tile 128 rows x 64 cols, k-major smem, micro 8x4: 3 LDS.128 per 32 FMA
__global__ void __launch_bounds__(256) k_lin(const float* __restrict__ X,
                                             const float* __restrict__ W,
                                             const float* __restrict__ bias,
                                             float* __restrict__ Y, int ncols) {
    extern __shared__ float sl[];
    float* Xs = sl;          // k-major [64][132]
    float* Ws = sl + 8448;   // k-major [64][68]
    int m0 = blockIdx.x * 128;
    int n0 = blockIdx.y * 64;
    int tid = threadIdx.x;

    for (int idx = tid; idx < 2048; idx += 256) {
        int r = idx >> 4, c4 = idx & 15;
        float4 xv = *(const float4*)(X + (size_t)(m0 + r)*64 + c4*4);
        Xs[(c4*4+0)*132 + r] = xv.x;
        Xs[(c4*4+1)*132 + r] = xv.y;
        Xs[(c4*4+2)*132 + r] = xv.z;
        Xs[(c4*4+3)*132 + r] = xv.w;
    }
    for (int idx = tid; idx < 1024; idx += 256) {
        int r = idx >> 4, c4 = idx & 15;
        float4 wv = *(const float4*)(W + (size_t)(n0 + r)*64 + c4*4);
        Ws[(c4*4+0)*68 + r] = wv.x;
        Ws[(c4*4+1)*68 + r] = wv.y;
        Ws[(c4*4+2)*68 + r] = wv.z;
        Ws[(c4*4+3)*68 + r] = wv.w;
    }
    __syncthreads();

    int ty = tid >> 4, tx = tid & 15;
    int i0 = ty * 8, j0 = tx * 4;
    float4 acc[8];
#pragma unroll
    for (int u = 0; u < 8; u++) acc[u] = make_float4(0.f, 0.f, 0.f, 0.f);

#pragma unroll 8
    for (int k = 0; k < 64; k++) {
        float4 x0 = *(const float4*)(Xs + k*132 + i0);
        float4 x1 = *(const float4*)(Xs + k*132 + i0 + 4);
        float4 wv = *(const float4*)(Ws + k*68 + j0);
        float xa[8] = {x0.x,x0.y,x0.z,x0.w,x1.x,x1.y,x1.z,x1.w};
#pragma unroll
        for (int u = 0; u < 8; u++) {
            acc[u].x = fmaf(xa[u], wv.x, acc[u].x);
            acc[u].y = fmaf(xa[u], wv.y, acc[u].y);
            acc[u].z = fmaf(xa[u], wv.z, acc[u].z);
            acc[u].w = fmaf(xa[u], wv.w, acc[u].w);
        }
    }
    float4 bv = *(const float4*)(bias + n0 + j0);
#pragma unroll
    for (int u = 0; u < 8; u++) {
        float4 o;
        o.x = acc[u].x + bv.x; o.y = acc[u].y + bv.y;
        o.z = acc[u].z + bv.z; o.w = acc[u].w + bv.w;
        *(float4*)(Y + (size_t)(m0 + i0 + u)*ncols + n0 + j0) = o;
    }
}

// ---------------- per-(b,n) temporal attention ----------------
// smem 25728 floats (103KB): Q k-major [64][132] @0, K @8448, V [128][68] @16896,
// bias @25600. P [128][132] overlays Q/K after S GEMM -> 2 blocks/SM.
__global__ void __launch_bounds__(256, 2) k_attn(const float* __restrict__ lg,
                                                 const float* __restrict__ lt) {
    extern __shared__ float sm[];
    float* Qs = sm;
    float* Ks = sm + 8448;
    float* Vs = sm + 16896;
    float* Ps = sm;                 // overlays Q/K
    float* biasr = sm + 25600;

    int tid = threadIdx.x;
    int bn = blockIdx.x;
    int b = bn >> 8, n = bn & 255;

    float gamma = fmaxf(expf(*lg), 0.01f);
    float tau   = fmaxf(expf(*lt), 0.01f);
    float scale = 1.0f / (8.0f * tau);

    if (tid < 128) biasr[tid] = logf(expf(-gamma * (float)tid * (1.0f/127.0f)) + 1e-8f);

    // load Q,K transposed (k-major), V row-major
    for (int idx = tid; idx < 2048; idx += 256) {
        int i = idx >> 4, c4 = idx & 15;
        size_t g = ((size_t)(b*Tt + i)*Nn + n)*Dd + c4*4;
        float4 q = *(const float4*)(g_Q + g);
        float4 kk = *(const float4*)(g_K + g);
        float4 vv = *(const float4*)(g_V + g);
        Qs[(c4*4+0)*132 + i] = q.x;  Qs[(c4*4+1)*132 + i] = q.y;
        Qs[(c4*4+2)*132 + i] = q.z;  Qs[(c4*4+3)*132 + i] = q.w;
        Ks[(c4*4+0)*132 + i] = kk.x; Ks[(c4*4+1)*132 + i] = kk.y;
        Ks[(c4*4+2)*132 + i] = kk.z; Ks[(c4*4+3)*132 + i] = kk.w;
        *(float4*)(Vs + i*68 + c4*4) = vv;
    }
    __syncthreads();

    int ty = tid >> 4, tx = tid & 15;
    int i0 = ty * 8, j0 = tx * 8;
    float s[8][8] = {};
#pragma unroll 4
    for (int k = 0; k < 64; k++) {
        float4 q0 = *(const float4*)(Qs + k*132 + i0);
        float4 q1 = *(const float4*)(Qs + k*132 + i0 + 4);
        float4 k0 = *(const float4*)(Ks + k*132 + j0);
        float4 k1 = *(const float4*)(Ks + k*132 + j0 + 4);
        float qa[8] = {q0.x,q0.y,q0.z,q0.w,q1.x,q1.y,q1.z,q1.w};
        float kb[8] = {k0.x,k0.y,k0.z,k0.w,k1.x,k1.y,k1.z,k1.w};
#pragma unroll
        for (int u = 0; u < 8; u++)
#pragma unroll
            for (int v = 0; v < 8; v++) s[u][v] = fmaf(qa[u], kb[v], s[u][v]);
    }
    __syncthreads();   // all S reads of Q/K done before P overlay writes

    // write P = S*scale + bias (overlaying Q/K region)
#pragma unroll
    for (int u = 0; u < 8; u++) {
        int i = i0 + u;
#pragma unroll
        for (int v = 0; v < 8; v++) {
            int j = j0 + v;
            int dd = i - j; dd = dd < 0 ? -dd : dd;
            Ps[i*132 + j] = s[u][v]*scale + biasr[dd];
        }
    }
    __syncthreads();

    // softmax rows (warp per 16 rows)
    int w = tid >> 5, lane = tid & 31;
    for (int rr = 0; rr < 16; rr++) {
        int i = w*16 + rr;
        float v0 = Ps[i*132 + lane], v1 = Ps[i*132 + lane + 32],
              v2 = Ps[i*132 + lane + 64], v3 = Ps[i*132 + lane + 96];
        float mx = fmaxf(fmaxf(v0, v1), fmaxf(v2, v3));
#pragma unroll
        for (int off = 16; off > 0; off >>= 1) mx = fmaxf(mx, __shfl_xor_sync(0xffffffff, mx, off));
        float e0 = __expf(v0 - mx), e1 = __expf(v1 - mx), e2 = __expf(v2 - mx), e3 = __expf(v3 - mx);
        float su = (e0 + e1) + (e2 + e3);
#pragma unroll
        for (int off = 16; off > 0; off >>= 1) su += __shfl_xor_sync(0xffffffff, su, off);
        float inv = 1.0f / su;
        Ps[i*132 + lane]      = e0 * inv;
        Ps[i*132 + lane + 32] = e1 * inv;
        Ps[i*132 + lane + 64] = e2 * inv;
        Ps[i*132 + lane + 96] = e3 * inv;
    }
    __syncthreads();

    // out = P @ V  (thread: 8 i x 4 d)
    int d0 = tx * 4;
    float4 acc[8];
#pragma unroll
    for (int u = 0; u < 8; u++) acc[u] = make_float4(0.f, 0.f, 0.f, 0.f);
#pragma unroll 4
    for (int j = 0; j < 128; j++) {
        float4 vv = *(const float4*)(Vs + j*68 + d0);
#pragma unroll
        for (int u = 0; u < 8; u++) {
            float p = Ps[(i0+u)*132 + j];
            acc[u].x = fmaf(p, vv.x, acc[u].x);
            acc[u].y = fmaf(p, vv.y, acc[u].y);
            acc[u].z = fmaf(p, vv.z, acc[u].z);
            acc[u].w = fmaf(p, vv.w, acc[u].w);
        }
    }
#pragma unroll
    for (int u = 0; u < 8; u++) {
        *(float4*)(g_ALN + ((size_t)(b*Tt + i0 + u)*Nn + n)*Dd + d0) = acc[u];
    }
}

// ---------------- GCN + residual + LN1 (per (b,t), m-half per block) ----------------
// smem 20992 floats (84KB): TmpT [64][132] @0; U @8448:
//   GEMM1 phase: Xc [32][68] @U+0, Ac [32][132] @U+2176
//   GEMM2 phase: Wgs [64][68] @U+0, H2 [128][64] @U+4352
__global__ void __launch_bounds__(256, 2) k_gcn(const float* __restrict__ Wg,
                                                const float* __restrict__ bg,
                                                const float* __restrict__ ln1g,
                                                const float* __restrict__ ln1b) {
    extern __shared__ float sg[];
    float* TmpT = sg;
    float* U    = sg + 8448;

    int tid = threadIdx.x;
    int blk = blockIdx.x;
    int bt = blk >> 1, half = blk & 1;
    int m0 = half * 128;
    int b = bt >> 7, t = bt & 127;
    const float* Xbt = g_ALN + (size_t)bt * 16384;

    int ty = tid >> 4, tx = tid & 15;
    int i0 = ty * 8, d0 = tx * 4;

    // GEMM1: tmp[m,d] = sum_n adp[m0+m, n] * x[n, d], streamed in 32-n chunks
    float4 acc[8];
#pragma unroll
    for (int u = 0; u < 8; u++) acc[u] = make_float4(0.f, 0.f, 0.f, 0.f);

    for (int c = 0; c < 8; c++) {
        __syncthreads();
        for (int idx = tid; idx < 512; idx += 256) {
            int nn = idx >> 4, c4 = idx & 15;
            *(float4*)(U + nn*68 + c4*4) =
                *(const float4*)(Xbt + (size_t)(c*32 + nn)*64 + c4*4);
        }
        for (int idx = tid; idx < 1024; idx += 256) {
            int nn = idx >> 5, c4 = idx & 31;
            *(float4*)(U + 2176 + nn*132 + c4*4) =
                *(const float4*)(g_ADPT + (size_t)(c*32 + nn)*256 + m0 + c4*4);
        }
        __syncthreads();
#pragma unroll 4
        for (int nn = 0; nn < 32; nn++) {
            float4 xv = *(const float4*)(U + nn*68 + d0);
            float4 a0 = *(const float4*)(U + 2176 + nn*132 + i0);
            float4 a1 = *(const float4*)(U + 2176 + nn*132 + i0 + 4);
            float am[8] = {a0.x,a0.y,a0.z,a0.w,a1.x,a1.y,a1.z,a1.w};
#pragma unroll
            for (int u = 0; u < 8; u++) {
                acc[u].x = fmaf(am[u], xv.x, acc[u].x);
                acc[u].y = fmaf(am[u], xv.y, acc[u].y);
                acc[u].z = fmaf(am[u], xv.z, acc[u].z);
                acc[u].w = fmaf(am[u], xv.w, acc[u].w);
            }
        }
    }
    // write TmpT (d-major): TmpT[d][m]
#pragma unroll
    for (int u = 0; u < 8; u++) {
        TmpT[(d0+0)*132 + i0 + u] = acc[u].x;
        TmpT[(d0+1)*132 + i0 + u] = acc[u].y;
        TmpT[(d0+2)*132 + i0 + u] = acc[u].z;
        TmpT[(d0+3)*132 + i0 + u] = acc[u].w;
    }
    __syncthreads();   // chunk buffers dead, TmpT complete

    // load Wg k-major into U[0..4352)
    for (int idx = tid; idx < 1024; idx += 256) {
        int r = idx >> 4, c4 = idx & 15;
        float4 wv = *(const float4*)(Wg + (size_t)r*64 + c4*4);
        U[(c4*4+0)*68 + r] = wv.x;
        U[(c4*4+1)*68 + r] = wv.y;
        U[(c4*4+2)*68 + r] = wv.z;
        U[(c4*4+3)*68 + r] = wv.w;
    }
    __syncthreads();

    // GEMM2: h2[m,e] = relu(sum_d tmp[m,d]*Wg[e,d] + bg[e]), e0 == d0
    float4 acc2[8];
#pragma unroll
    for (int u = 0; u < 8; u++) acc2[u] = make_float4(0.f, 0.f, 0.f, 0.f);
#pragma unroll 8
    for (int d = 0; d < 64; d++) {
        float4 t0 = *(const float4*)(TmpT + d*132 + i0);
        float4 t1 = *(const float4*)(TmpT + d*132 + i0 + 4);
        float4 wv = *(const float4*)(U + d*68 + d0);
        float tm[8] = {t0.x,t0.y,t0.z,t0.w,t1.x,t1.y,t1.z,t1.w};
#pragma unroll
        for (int u = 0; u < 8; u++) {
            acc2[u].x = fmaf(tm[u], wv.x, acc2[u].x);
            acc2[u].y = fmaf(tm[u], wv.y, acc2[u].y);
            acc2[u].z = fmaf(tm[u], wv.z, acc2[u].z);
            acc2[u].w = fmaf(tm[u], wv.w, acc2[u].w);
        }
    }
    float4 bgv = *(const float4*)(bg + d0);
#pragma unroll
    for (int u = 0; u < 8; u++) {
        float4 h;
        h.x = fmaxf(acc2[u].x + bgv.x, 0.f);
        h.y = fmaxf(acc2[u].y + bgv.y, 0.f);
        h.z = fmaxf(acc2[u].z + bgv.z, 0.f);
        h.w = fmaxf(acc2[u].w + bgv.w, 0.f);
        *(float4*)(U + 4352 + (i0+u)*64 + d0) = h;
    }
    __syncthreads();

    // residual + LN1, write transposed to g_X1 [B,N,T,D]
    int w = tid >> 5, lane = tid & 31;
    float gg0 = ln1g[lane], gg1 = ln1g[lane+32];
    float bb0 = ln1b[lane], bb1 = ln1b[lane+32];
    for (int mm = 0; mm < 16; mm++) {
        int m = w*16 + mm;
        const float* xr = Xbt + (size_t)(m0 + m)*64;
        float u0 = xr[lane]      + U[4352 + m*64 + lane];
        float u1 = xr[lane + 32] + U[4352 + m*64 + lane + 32];
        float su = u0 + u1;
#pragma unroll
        for (int off = 16; off > 0; off >>= 1) su += __shfl_xor_sync(0xffffffff, su, off);
        float mean = su * (1.0f/64.0f);
        float dd0 = u0 - mean, dd1 = u1 - mean;
        float q = dd0*dd0 + dd1*dd1;
#pragma unroll
        for (int off = 16; off > 0; off >>= 1) q += __shfl_xor_sync(0xffffffff, q, off);
        float rs = rsqrtf(q*(1.0f/64.0f) + 1e-5f);
        size_t o = ((size_t)(b*Nn + m0 + m)*Tt + t)*Dd;
        g_X1[o + lane]      = dd0*rs*gg0 + bb0;
        g_X1[o + lane + 32] = dd1*rs*gg1 + bb1;
    }
}

// ---------------- GRU scan, one block per (b,n) sequence ----------------
__global__ void __launch_bounds__(192) k_gru(const float* __restrict__ Whh,
                                             const float* __restrict__ bhh) {
    __shared__ float h_s[64];
    __shared__ float gh_s[192];
    int tid = threadIdx.x;          // 192
    int bn = blockIdx.x;

    float w[64];
#pragma unroll
    for (int i = 0; i < 16; i++) ((float4*)w)[i] = *(const float4*)(Whh + tid*64 + i*4);
    float bh = bhh[tid];
    if (tid < 64) h_s[tid] = 0.f;

    const float* gi = g_GI + (size_t)bn * Tt * D3;
    float* out = g_GRU + (size_t)bn * Tt * Dd;
    __syncthreads();

    for (int t = 0; t < Tt; t++) {
        float a0 = 0.f, a1 = 0.f, a2 = 0.f, a3 = 0.f;
#pragma unroll
        for (int d4 = 0; d4 < 16; d4++) {
            float4 hv = ((const float4*)h_s)[d4];
            a0 = fmaf(w[d4*4+0], hv.x, a0);
            a1 = fmaf(w[d4*4+1], hv.y, a1);
            a2 = fmaf(w[d4*4+2], hv.z, a2);
            a3 = fmaf(w[d4*4+3], hv.w, a3);
        }
        gh_s[tid] = bh + ((a0 + a1) + (a2 + a3));
        __syncthreads();
        if (tid < 64) {
            const float* gt = gi + t*D3;
            float r  = sigf(gt[tid]       + gh_s[tid]);
            float z  = sigf(gt[64 + tid]  + gh_s[64 + tid]);
            float nn = tanhf(gt[128 + tid] + r * gh_s[128 + tid]);
            float hn = (1.0f - z)*nn + z*h_s[tid];
            h_s[tid] = hn;
            out[t*64 + tid] = hn;
        }
        __syncthreads();
    }
}

// ---------------- final: out = x1 + LN2(x1 + gru), transpose back ----------------
__global__ void k_final(const float* __restrict__ ln2g, const float* __restrict__ ln2b,
                        float* __restrict__ out) {
    int w = threadIdx.x >> 5, lane = threadIdx.x & 31;
    int row = blockIdx.x * 8 + w;        // < 262144, [B,N,T] order
    int b = row >> 15;
    int rem = row & 32767;
    int n = rem >> 7, t = rem & 127;
    const float* xr = g_X1 + (size_t)row*64;
    const float* gr = g_GRU + (size_t)row*64;
    float x0 = xr[lane], x1 = xr[lane+32];
    float u0 = x0 + gr[lane], u1 = x1 + gr[lane+32];
    float su = u0 + u1;
#pragma unroll
    for (int off = 16; off > 0; off >>= 1) su += __shfl_xor_sync(0xffffffff, su, off);
    float mean = su * (1.0f/64.0f);
    float d0 = u0 - mean, d1 = u1 - mean;
    float q = d0*d0 + d1*d1;
#pragma unroll
    for (int off = 16; off > 0; off >>= 1) q += __shfl_xor_sync(0xffffffff, q, off);
    float rs = rsqrtf(q*(1.0f/64.0f) + 1e-5f);
    float y0 = d0*rs*ln2g[lane]    + ln2b[lane];
    float y1 = d1*rs*ln2g[lane+32] + ln2b[lane+32];
    size_t o = ((size_t)(b*Tt + t)*Nn + n)*Dd;
    out[o + lane]      = x0 + y0;
    out[o + lane + 32] = x1 + y1;
}

// ---------------- launcher ----------------
extern "C" void kernel_launch(void* const* d_in, const int* in_sizes, int n_in,
                              void* d_out, int out_size) {
    (void)in_sizes; (void)n_in; (void)out_size;
    const float* H_i  = (const float*)d_in[0];
    const float* H_j  = (const float*)d_in[1];
    const float* Wq   = (const float*)d_in[2];
    const float* bq   = (const float*)d_in[3];
    const float* Wk   = (const float*)d_in[4];
    const float* bk   = (const float*)d_in[5];
    const float* Wv   = (const float*)d_in[6];
    const float* bv   = (const float*)d_in[7];
    const float* lgam = (const float*)d_in[8];
    const float* ltau = (const float*)d_in[9];
    const float* e1   = (const float*)d_in[10];
    const float* e2   = (const float*)d_in[11];
    const float* Wg   = (const float*)d_in[12];
    const float* bg   = (const float*)d_in[13];
    const float* ln1g = (const float*)d_in[14];
    const float* ln1b = (const float*)d_in[15];
    const float* Wih  = (const float*)d_in[16];
    const float* Whh  = (const float*)d_in[17];
    const float* bih  = (const float*)d_in[18];
    const float* bhh  = (const float*)d_in[19];
    const float* ln2g = (const float*)d_in[20];
    const float* ln2b = (const float*)d_in[21];
    float* out = (float*)d_out;

    // device scratch pointers resolved at runtime
    float *pQ, *pK, *pV, *pGI, *pX1;
    cudaGetSymbolAddress((void**)&pQ,  g_Q);
    cudaGetSymbolAddress((void**)&pK,  g_K);
    cudaGetSymbolAddress((void**)&pV,  g_V);
    cudaGetSymbolAddress((void**)&pGI, g_GI);
    cudaGetSymbolAddress((void**)&pX1, g_X1);

    const int LIN_SMEM  = 12800 * 4;   // 51200 B
    const int ATTN_SMEM = 25728 * 4;   // 102912 B
    const int GCN_SMEM  = 20992 * 4;   // 83968 B
    cudaFuncSetAttribute(k_lin,  cudaFuncAttributeMaxDynamicSharedMemorySize, LIN_SMEM);
    cudaFuncSetAttribute(k_attn, cudaFuncAttributeMaxDynamicSharedMemorySize, ATTN_SMEM);
    cudaFuncSetAttribute(k_gcn,  cudaFuncAttributeMaxDynamicSharedMemorySize, GCN_SMEM);

    k_adj<<<256, 256>>>(e1, e2);
    k_lin<<<dim3(MROWS/128, 1), 256, LIN_SMEM>>>(H_i, Wq, bq, pQ, 64);
    k_lin<<<dim3(MROWS/128, 1), 256, LIN_SMEM>>>(H_j, Wk, bk, pK, 64);
    k_lin<<<dim3(MROWS/128, 1), 256, LIN_SMEM>>>(H_j, Wv, bv, pV, 64);
    k_attn<<<Bb*Nn, 256, ATTN_SMEM>>>(lgam, ltau);
    k_gcn<<<Bb*Tt*2, 256, GCN_SMEM>>>(Wg, bg, ln1g, ln1b);
    k_lin<<<dim3(MROWS/128, 3), 256, LIN_SMEM>>>(pX1, Wih, bih, pGI, 192);
    k_gru<<<Bb*Nn, 192>>>(Whh, bhh);
    k_final<<<MROWS/8, 256>>>(ln2g, ln2b, out);
}

// round 4
// speedup vs baseline: 1.3404x; 1.0262x over previous
#include <cuda_runtime.h>
#include <math.h>

#define Bb 8
#define Tt 128
#define Nn 256
#define Dd 64
#define D3 192
#define BTND 16777216   // 8*128*256*64
#define MROWS 262144    // B*T*N == B*N*T

// ---------------- device scratch ----------------
__device__ float g_Q[BTND];
__device__ float g_K[BTND];
__device__ float g_V[BTND];
__device__ float g_ALN[BTND];          // aligner output, [B,T,N,D]
__device__ float g_X1[BTND];           // post-ln1, [B,N,T,D]
__device__ float g_GI[50331648];       // [B,N,T,192]
__device__ float g_ADP[Nn*Nn];
__device__ float g_ADPT[Nn*Nn];

__device__ __forceinline__ float sigf(float x) { return 1.0f / (1.0f + __expf(-x)); }
__device__ __forceinline__ unsigned f2tf32(float f) {
    unsigned u;
    asm("cvt.rna.tf32.f32 %0, %1;" : "=r"(u) : "f"(f));
    return u;
}

// ---------------- adjacency: adp = softmax_row(relu(e1@e2)) ----------------
__global__ void k_adj(const float* __restrict__ e1, const float* __restrict__ e2) {
    int m = blockIdx.x;
    int n = threadIdx.x;            // 256 threads
    float a = 0.f;
#pragma unroll
    for (int k = 0; k < 32; k++) a = fmaf(e1[m*32 + k], e2[k*256 + n], a);
    a = fmaxf(a, 0.f);
    __shared__ float red[256];
    red[n] = a; __syncthreads();
    for (int s = 128; s > 0; s >>= 1) { if (n < s) red[n] = fmaxf(red[n], red[n+s]); __syncthreads(); }
    float mx = red[0]; __syncthreads();
    float e = expf(a - mx);
    red[n] = e; __syncthreads();
    for (int s = 128; s > 0; s >>= 1) { if (n < s) red[n] += red[n+s]; __syncthreads(); }
    float v = e / red[0];
    g_ADP[m*256 + n]  = v;
    g_ADPT[n*256 + m] = v;
}

// ---------------- tf32 tensor-core linear: Y = X @ W^T + b ----------------
// block: 128 rows x 64 cols, 8 warps; warp: 16 rows x 64 cols via m16n8k8 mma
__global__ void __launch_bounds__(256) k_lin_tf32(const float* __restrict__ X,
                                                  const float* __restrict__ W,
                                                  const float* __restrict__ bias,
                                                  float* __restrict__ Y, int ncols) {
    extern __shared__ unsigned sl[];
    unsigned* Xs = sl;              // [128][68] tf32 bits
    unsigned* Ws = sl + 128*68;     // [64][68]
    int m0 = blockIdx.x * 128;
    int n0 = blockIdx.y * 64;
    int tid = threadIdx.x;

    for (int idx = tid; idx < 2048; idx += 256) {
        int r = idx >> 4, c4 = idx & 15;
        float4 xv = *(const float4*)(X + (size_t)(m0 + r)*64 + c4*4);
        uint4 pv;
        pv.x = f2tf32(xv.x); pv.y = f2tf32(xv.y);
        pv.z = f2tf32(xv.z); pv.w = f2tf32(xv.w);
        *(uint4*)(Xs + r*68 + c4*4) = pv;
    }
    for (int idx = tid; idx < 1024; idx += 256) {
        int r = idx >> 4, c4 = idx & 15;
        float4 wv = *(const float4*)(W + (size_t)(n0 + r)*64 + c4*4);
        uint4 pv;
        pv.x = f2tf32(wv.x); pv.y = f2tf32(wv.y);
        pv.z = f2tf32(wv.z); pv.w = f2tf32(wv.w);
        *(uint4*)(Ws + r*68 + c4*4) = pv;
    }
    __syncthreads();

    int w = tid >> 5, lane = tid & 31;
    int qr = lane >> 2, kc = lane & 3;
    int mrow = w*16 + qr;

    unsigned a[8][4];
#pragma unroll
    for (int ks = 0; ks < 8; ks++) {
        a[ks][0] = Xs[mrow*68 + ks*8 + kc];
        a[ks][1] = Xs[(mrow+8)*68 + ks*8 + kc];
        a[ks][2] = Xs[mrow*68 + ks*8 + kc + 4];
        a[ks][3] = Xs[(mrow+8)*68 + ks*8 + kc + 4];
    }

#pragma unroll
    for (int nt = 0; nt < 8; nt++) {
        int ncol = nt*8 + qr;
        float c0 = 0.f, c1 = 0.f, c2 = 0.f, c3 = 0.f;
#pragma unroll
        for (int ks = 0; ks < 8; ks++) {
            unsigned b0 = Ws[ncol*68 + ks*8 + kc];
            unsigned b1 = Ws[ncol*68 + ks*8 + kc + 4];
            asm volatile("mma.sync.aligned.m16n8k8.row.col.f32.tf32.tf32.f32 "
                "{%0,%1,%2,%3}, {%4,%5,%6,%7}, {%8,%9}, {%0,%1,%2,%3};"
                : "+f"(c0), "+f"(c1), "+f"(c2), "+f"(c3)
                : "r"(a[ks][0]), "r"(a[ks][1]), "r"(a[ks][2]), "r"(a[ks][3]),
                  "r"(b0), "r"(b1));
        }
        int gc = n0 + nt*8 + 2*kc;
        float bx = bias[gc], by = bias[gc+1];
        float2 o0; o0.x = c0 + bx; o0.y = c1 + by;
        float2 o1; o1.x = c2 + bx; o1.y = c3 + by;
        *(float2*)(Y + (size_t)(m0 + mrow)*ncols + gc)     = o0;
        *(float2*)(Y + (size_t)(m0 + mrow + 8)*ncols + gc) = o1;
    }
}

// ---------------- per-(b,n) temporal attention ----------------
__global__ void __launch_bounds__(256, 2) k_attn(const float* __restrict__ lg,
                                                 const float* __restrict__ lt) {
    extern __shared__ float sm[];
    float* Qs = sm;
    float* Ks = sm + 8448;
    float* Vs = sm + 16896;
    float* Ps = sm;                 // overlays Q/K
    float* biasr = sm + 25600;

    int tid = threadIdx.x;
    int bn = blockIdx.x;
    int b = bn >> 8, n = bn & 255;

    float gamma = fmaxf(expf(*lg), 0.01f);
    float tau   = fmaxf(expf(*lt), 0.01f);
    float scale = 1.0f / (8.0f * tau);

    if (tid < 128) biasr[tid] = logf(expf(-gamma * (float)tid * (1.0f/127.0f)) + 1e-8f);

    for (int idx = tid; idx < 2048; idx += 256) {
        int i = idx >> 4, c4 = idx & 15;
        size_t g = ((size_t)(b*Tt + i)*Nn + n)*Dd + c4*4;
        float4 q = *(const float4*)(g_Q + g);
        float4 kk = *(const float4*)(g_K + g);
        float4 vv = *(const float4*)(g_V + g);
        Qs[(c4*4+0)*132 + i] = q.x;  Qs[(c4*4+1)*132 + i] = q.y;
        Qs[(c4*4+2)*132 + i] = q.z;  Qs[(c4*4+3)*132 + i] = q.w;
        Ks[(c4*4+0)*132 + i] = kk.x; Ks[(c4*4+1)*132 + i] = kk.y;
        Ks[(c4*4+2)*132 + i] = kk.z; Ks[(c4*4+3)*132 + i] = kk.w;
        *(float4*)(Vs + i*68 + c4*4) = vv;
    }
    __syncthreads();

    int ty = tid >> 4, tx = tid & 15;
    int i0 = ty * 8, j0 = tx * 8;
    float s[8][8] = {};
#pragma unroll 4
    for (int k = 0; k < 64; k++) {
        float4 q0 = *(const float4*)(Qs + k*132 + i0);
        float4 q1 = *(const float4*)(Qs + k*132 + i0 + 4);
        float4 k0 = *(const float4*)(Ks + k*132 + j0);
        float4 k1 = *(const float4*)(Ks + k*132 + j0 + 4);
        float qa[8] = {q0.x,q0.y,q0.z,q0.w,q1.x,q1.y,q1.z,q1.w};
        float kb[8] = {k0.x,k0.y,k0.z,k0.w,k1.x,k1.y,k1.z,k1.w};
#pragma unroll
        for (int u = 0; u < 8; u++)
#pragma unroll
            for (int v = 0; v < 8; v++) s[u][v] = fmaf(qa[u], kb[v], s[u][v]);
    }
    __syncthreads();

#pragma unroll
    for (int u = 0; u < 8; u++) {
        int i = i0 + u;
#pragma unroll
        for (int v = 0; v < 8; v++) {
            int j = j0 + v;
            int dd = i - j; dd = dd < 0 ? -dd : dd;
            Ps[i*132 + j] = s[u][v]*scale + biasr[dd];
        }
    }
    __syncthreads();

    int w = tid >> 5, lane = tid & 31;
    for (int rr = 0; rr < 16; rr++) {
        int i = w*16 + rr;
        float v0 = Ps[i*132 + lane], v1 = Ps[i*132 + lane + 32],
              v2 = Ps[i*132 + lane + 64], v3 = Ps[i*132 + lane + 96];
        float mx = fmaxf(fmaxf(v0, v1), fmaxf(v2, v3));
#pragma unroll
        for (int off = 16; off > 0; off >>= 1) mx = fmaxf(mx, __shfl_xor_sync(0xffffffff, mx, off));
        float e0 = __expf(v0 - mx), e1 = __expf(v1 - mx), e2 = __expf(v2 - mx), e3 = __expf(v3 - mx);
        float su = (e0 + e1) + (e2 + e3);
#pragma unroll
        for (int off = 16; off > 0; off >>= 1) su += __shfl_xor_sync(0xffffffff, su, off);
        float inv = 1.0f / su;
        Ps[i*132 + lane]      = e0 * inv;
        Ps[i*132 + lane + 32] = e1 * inv;
        Ps[i*132 + lane + 64] = e2 * inv;
        Ps[i*132 + lane + 96] = e3 * inv;
    }
    __syncthreads();

    int d0 = tx * 4;
    float4 acc[8];
#pragma unroll
    for (int u = 0; u < 8; u++) acc[u] = make_float4(0.f, 0.f, 0.f, 0.f);
#pragma unroll 4
    for (int j = 0; j < 128; j++) {
        float4 vv = *(const float4*)(Vs + j*68 + d0);
#pragma unroll
        for (int u = 0; u < 8; u++) {
            float p = Ps[(i0+u)*132 + j];
            acc[u].x = fmaf(p, vv.x, acc[u].x);
            acc[u].y = fmaf(p, vv.y, acc[u].y);
            acc[u].z = fmaf(p, vv.z, acc[u].z);
            acc[u].w = fmaf(p, vv.w, acc[u].w);
        }
    }
#pragma unroll
    for (int u = 0; u < 8; u++) {
        *(float4*)(g_ALN + ((size_t)(b*Tt + i0 + u)*Nn + n)*Dd + d0) = acc[u];
    }
}

// ---------------- GCN + residual + LN1 (per (b,t), m-half per block) ----------------
__global__ void __launch_bounds__(256, 2) k_gcn(const float* __restrict__ Wg,
                                                const float* __restrict__ bg,
                                                const float* __restrict__ ln1g,
                                                const float* __restrict__ ln1b) {
    extern __shared__ float sg[];
    float* TmpT = sg;
    float* U    = sg + 8448;

    int tid = threadIdx.x;
    int blk = blockIdx.x;
    int bt = blk >> 1, half = blk & 1;
    int m0 = half * 128;
    int b = bt >> 7, t = bt & 127;
    const float* Xbt = g_ALN + (size_t)bt * 16384;

    int ty = tid >> 4, tx = tid & 15;
    int i0 = ty * 8, d0 = tx * 4;

    float4 acc[8];
#pragma unroll
    for (int u = 0; u < 8; u++) acc[u] = make_float4(0.f, 0.f, 0.f, 0.f);

    for (int c = 0; c < 8; c++) {
        __syncthreads();
        for (int idx = tid; idx < 512; idx += 256) {
            int nn = idx >> 4, c4 = idx & 15;
            *(float4*)(U + nn*68 + c4*4) =
                *(const float4*)(Xbt + (size_t)(c*32 + nn)*64 + c4*4);
        }
        for (int idx = tid; idx < 1024; idx += 256) {
            int nn = idx >> 5, c4 = idx & 31;
            *(float4*)(U + 2176 + nn*132 + c4*4) =
                *(const float4*)(g_ADPT + (size_t)(c*32 + nn)*256 + m0 + c4*4);
        }
        __syncthreads();
#pragma unroll 4
        for (int nn = 0; nn < 32; nn++) {
            float4 xv = *(const float4*)(U + nn*68 + d0);
            float4 a0 = *(const float4*)(U + 2176 + nn*132 + i0);
            float4 a1 = *(const float4*)(U + 2176 + nn*132 + i0 + 4);
            float am[8] = {a0.x,a0.y,a0.z,a0.w,a1.x,a1.y,a1.z,a1.w};
#pragma unroll
            for (int u = 0; u < 8; u++) {
                acc[u].x = fmaf(am[u], xv.x, acc[u].x);
                acc[u].y = fmaf(am[u], xv.y, acc[u].y);
                acc[u].z = fmaf(am[u], xv.z, acc[u].z);
                acc[u].w = fmaf(am[u], xv.w, acc[u].w);
            }
        }
    }
#pragma unroll
    for (int u = 0; u < 8; u++) {
        TmpT[(d0+0)*132 + i0 + u] = acc[u].x;
        TmpT[(d0+1)*132 + i0 + u] = acc[u].y;
        TmpT[(d0+2)*132 + i0 + u] = acc[u].z;
        TmpT[(d0+3)*132 + i0 + u] = acc[u].w;
    }
    __syncthreads();

    for (int idx = tid; idx < 1024; idx += 256) {
        int r = idx >> 4, c4 = idx & 15;
        float4 wv = *(const float4*)(Wg + (size_t)r*64 + c4*4);
        U[(c4*4+0)*68 + r] = wv.x;
        U[(c4*4+1)*68 + r] = wv.y;
        U[(c4*4+2)*68 + r] = wv.z;
        U[(c4*4+3)*68 + r] = wv.w;
    }
    __syncthreads();

    float4 acc2[8];
#pragma unroll
    for (int u = 0; u < 8; u++) acc2[u] = make_float4(0.f, 0.f, 0.f, 0.f);
#pragma unroll 8
    for (int d = 0; d < 64; d++) {
        float4 t0 = *(const float4*)(TmpT + d*132 + i0);
        float4 t1 = *(const float4*)(TmpT + d*132 + i0 + 4);
        float4 wv = *(const float4*)(U + d*68 + d0);
        float tm[8] = {t0.x,t0.y,t0.z,t0.w,t1.x,t1.y,t1.z,t1.w};
#pragma unroll
        for (int u = 0; u < 8; u++) {
            acc2[u].x = fmaf(tm[u], wv.x, acc2[u].x);
            acc2[u].y = fmaf(tm[u], wv.y, acc2[u].y);
            acc2[u].z = fmaf(tm[u], wv.z, acc2[u].z);
            acc2[u].w = fmaf(tm[u], wv.w, acc2[u].w);
        }
    }
    float4 bgv = *(const float4*)(bg + d0);
#pragma unroll
    for (int u = 0; u < 8; u++) {
        float4 h;
        h.x = fmaxf(acc2[u].x + bgv.x, 0.f);
        h.y = fmaxf(acc2[u].y + bgv.y, 0.f);
        h.z = fmaxf(acc2[u].z + bgv.z, 0.f);
        h.w = fmaxf(acc2[u].w + bgv.w, 0.f);
        *(float4*)(U + 4352 + (i0+u)*64 + d0) = h;
    }
    __syncthreads();

    int w = tid >> 5, lane = tid & 31;
    float gg0 = ln1g[lane], gg1 = ln1g[lane+32];
    float bb0 = ln1b[lane], bb1 = ln1b[lane+32];
    for (int mm = 0; mm < 16; mm++) {
        int m = w*16 + mm;
        const float* xr = Xbt + (size_t)(m0 + m)*64;
        float u0 = xr[lane]      + U[4352 + m*64 + lane];
        float u1 = xr[lane + 32] + U[4352 + m*64 + lane + 32];
        float su = u0 + u1;
#pragma unroll
        for (int off = 16; off > 0; off >>= 1) su += __shfl_xor_sync(0xffffffff, su, off);
        float mean = su * (1.0f/64.0f);
        float dd0 = u0 - mean, dd1 = u1 - mean;
        float q = dd0*dd0 + dd1*dd1;
#pragma unroll
        for (int off = 16; off > 0; off >>= 1) q += __shfl_xor_sync(0xffffffff, q, off);
        float rs = rsqrtf(q*(1.0f/64.0f) + 1e-5f);
        size_t o = ((size_t)(b*Nn + m0 + m)*Tt + t)*Dd;
        g_X1[o + lane]      = dd0*rs*gg0 + bb0;
        g_X1[o + lane + 32] = dd1*rs*gg1 + bb1;
    }
}

// ---------------- GRU scan fused with LN2 + residual + final output ----------------
__global__ void __launch_bounds__(192) k_gru(const float* __restrict__ Whh,
                                             const float* __restrict__ bhh,
                                             const float* __restrict__ ln2g,
                                             const float* __restrict__ ln2b,
                                             float* __restrict__ out) {
    __shared__ float h_s[64];
    __shared__ float gh_s[192];
    __shared__ float red[4];
    int tid = threadIdx.x;          // 192
    int bn = blockIdx.x;
    int b = bn >> 8, n = bn & 255;

    float w[64];
#pragma unroll
    for (int i = 0; i < 16; i++) ((float4*)w)[i] = *(const float4*)(Whh + tid*64 + i*4);
    float bh = bhh[tid];
    float g2 = 0.f, b2 = 0.f;
    if (tid < 64) { h_s[tid] = 0.f; g2 = ln2g[tid]; b2 = ln2b[tid]; }

    const float* gi = g_GI + (size_t)bn * Tt * D3;
    const float* x1 = g_X1 + (size_t)bn * Tt * Dd;
    float* outb = out + ((size_t)b*Tt*Nn + n)*Dd;
    __syncthreads();

    for (int t = 0; t < Tt; t++) {
        float xv = (tid < 64) ? x1[t*64 + tid] : 0.f;   // overlapped with gh
        float a0 = 0.f, a1 = 0.f, a2 = 0.f, a3 = 0.f;
#pragma unroll
        for (int d4 = 0; d4 < 16; d4++) {
            float4 hv = ((const float4*)h_s)[d4];
            a0 = fmaf(w[d4*4+0], hv.x, a0);
            a1 = fmaf(w[d4*4+1], hv.y, a1);
            a2 = fmaf(w[d4*4+2], hv.z, a2);
            a3 = fmaf(w[d4*4+3], hv.w, a3);
        }
        gh_s[tid] = bh + ((a0 + a1) + (a2 + a3));
        __syncthreads();
        float u_keep = 0.f;
        if (tid < 64) {
            const float* gt = gi + t*D3;
            float r  = sigf(gt[tid]        + gh_s[tid]);
            float z  = sigf(gt[64 + tid]   + gh_s[64 + tid]);
            float nn = tanhf(gt[128 + tid] + r * gh_s[128 + tid]);
            float hn = (1.0f - z)*nn + z*h_s[tid];
            h_s[tid] = hn;
            float u = xv + hn;
            u_keep = u;
            float s = u, q = u*u;
#pragma unroll
            for (int off = 16; off > 0; off >>= 1) {
                s += __shfl_xor_sync(0xffffffff, s, off);
                q += __shfl_xor_sync(0xffffffff, q, off);
            }
            if ((tid & 31) == 0) { red[(tid>>5)*2] = s; red[(tid>>5)*2+1] = q; }
        }
        __syncthreads();
        if (tid < 64) {
            float s = red[0] + red[2], q = red[1] + red[3];
            float mean = s * (1.0f/64.0f);
            float var = q*(1.0f/64.0f) - mean*mean;
            float rs = rsqrtf(var + 1e-5f);
            float y = (u_keep - mean)*rs*g2 + b2;
            outb[(size_t)t*Nn*Dd + tid] = xv + y;
        }
    }
}

// ---------------- launcher ----------------
extern "C" void kernel_launch(void* const* d_in, const int* in_sizes, int n_in,
                              void* d_out, int out_size) {
    (void)in_sizes; (void)n_in; (void)out_size;
    const float* H_i  = (const float*)d_in[0];
    const float* H_j  = (const float*)d_in[1];
    const float* Wq   = (const float*)d_in[2];
    const float* bq   = (const float*)d_in[3];
    const float* Wk   = (const float*)d_in[4];
    const float* bk   = (const float*)d_in[5];
    const float* Wv   = (const float*)d_in[6];
    const float* bv   = (const float*)d_in[7];
    const float* lgam = (const float*)d_in[8];
    const float* ltau = (const float*)d_in[9];
    const float* e1   = (const float*)d_in[10];
    const float* e2   = (const float*)d_in[11];
    const float* Wg   = (const float*)d_in[12];
    const float* bg   = (const float*)d_in[13];
    const float* ln1g = (const float*)d_in[14];
    const float* ln1b = (const float*)d_in[15];
    const float* Wih  = (const float*)d_in[16];
    const float* Whh  = (const float*)d_in[17];
    const float* bih  = (const float*)d_in[18];
    const float* bhh  = (const float*)d_in[19];
    const float* ln2g = (const float*)d_in[20];
    const float* ln2b = (const float*)d_in[21];
    float* out = (float*)d_out;

    float *pQ, *pK, *pV, *pGI, *pX1;
    cudaGetSymbolAddress((void**)&pQ,  g_Q);
    cudaGetSymbolAddress((void**)&pK,  g_K);
    cudaGetSymbolAddress((void**)&pV,  g_V);
    cudaGetSymbolAddress((void**)&pGI, g_GI);
    cudaGetSymbolAddress((void**)&pX1, g_X1);

    const int LIN_SMEM  = (128+64)*68*4;  // 52224 B
    const int ATTN_SMEM = 25728 * 4;      // 102912 B
    const int GCN_SMEM  = 20992 * 4;      // 83968 B
    cudaFuncSetAttribute(k_lin_tf32, cudaFuncAttributeMaxDynamicSharedMemorySize, LIN_SMEM);
    cudaFuncSetAttribute(k_attn, cudaFuncAttributeMaxDynamicSharedMemorySize, ATTN_SMEM);
    cudaFuncSetAttribute(k_gcn,  cudaFuncAttributeMaxDynamicSharedMemorySize, GCN_SMEM);

    k_adj<<<256, 256>>>(e1, e2);
    k_lin_tf32<<<dim3(MROWS/128, 1), 256, LIN_SMEM>>>(H_i, Wq, bq, pQ, 64);
    k_lin_tf32<<<dim3(MROWS/128, 1), 256, LIN_SMEM>>>(H_j, Wk, bk, pK, 64);
    k_lin_tf32<<<dim3(MROWS/128, 1), 256, LIN_SMEM>>>(H_j, Wv, bv, pV, 64);
    k_attn<<<Bb*Nn, 256, ATTN_SMEM>>>(lgam, ltau);
    k_gcn<<<Bb*Tt*2, 256, GCN_SMEM>>>(Wg, bg, ln1g, ln1b);
    k_lin_tf32<<<dim3(MROWS/128, 3), 256, LIN_SMEM>>>(pX1, Wih, bih, pGI, 192);
    k_gru<<<Bb*Nn, 192>>>(Whh, bhh, ln2g, ln2b, out);
}

// round 5
// speedup vs baseline: 1.4532x; 1.0842x over previous
#include <cuda_runtime.h>
#include <math.h>

#define Bb 8
#define Tt 128
#define Nn 256
#define Dd 64
#define D3 192
#define BTND 16777216   // 8*128*256*64
#define MROWS 262144    // B*T*N == B*N*T

// ---------------- device scratch ----------------
__device__ float g_Q[BTND];
__device__ float g_K[BTND];
__device__ float g_V[BTND];
__device__ float g_ALN[BTND];          // aligner output, [B,T,N,D]
__device__ float g_X1[BTND];           // post-ln1, [B,N,T,D]
__device__ float g_GI[50331648];       // [B,N,T,192]
__device__ unsigned g_ADPu[Nn*Nn];     // adjacency, tf32 bits, row-major [m][n]

__device__ __forceinline__ float sigf(float x) { return 1.0f / (1.0f + __expf(-x)); }
__device__ __forceinline__ unsigned f2tf32(float f) {
    unsigned u;
    asm("cvt.rna.tf32.f32 %0, %1;" : "=r"(u) : "f"(f));
    return u;
}
#define MMA_TF32(c0,c1,c2,c3,a0,a1,a2,a3,b0,b1) \
    asm volatile("mma.sync.aligned.m16n8k8.row.col.f32.tf32.tf32.f32 " \
        "{%0,%1,%2,%3}, {%4,%5,%6,%7}, {%8,%9}, {%0,%1,%2,%3};" \
        : "+f"(c0), "+f"(c1), "+f"(c2), "+f"(c3) \
        : "r"(a0), "r"(a1), "r"(a2), "r"(a3), "r"(b0), "r"(b1))

// ---------------- adjacency: adp = softmax_row(relu(e1@e2)), tf32 bits ----------------
__global__ void k_adj(const float* __restrict__ e1, const float* __restrict__ e2) {
    int m = blockIdx.x;
    int n = threadIdx.x;            // 256 threads
    float a = 0.f;
#pragma unroll
    for (int k = 0; k < 32; k++) a = fmaf(e1[m*32 + k], e2[k*256 + n], a);
    a = fmaxf(a, 0.f);
    __shared__ float red[256];
    red[n] = a; __syncthreads();
    for (int s = 128; s > 0; s >>= 1) { if (n < s) red[n] = fmaxf(red[n], red[n+s]); __syncthreads(); }
    float mx = red[0]; __syncthreads();
    float e = expf(a - mx);
    red[n] = e; __syncthreads();
    for (int s = 128; s > 0; s >>= 1) { if (n < s) red[n] += red[n+s]; __syncthreads(); }
    g_ADPu[m*256 + n] = f2tf32(e / red[0]);
}

// ---------------- tf32 tensor-core linear: Y = X @ W^T + b ----------------
__global__ void __launch_bounds__(256) k_lin_tf32(const float* __restrict__ X,
                                                  const float* __restrict__ W,
                                                  const float* __restrict__ bias,
                                                  float* __restrict__ Y, int ncols) {
    extern __shared__ unsigned sl[];
    unsigned* Xs = sl;              // [128][68] tf32 bits
    unsigned* Ws = sl + 128*68;     // [64][68]
    int m0 = blockIdx.x * 128;
    int n0 = blockIdx.y * 64;
    int tid = threadIdx.x;

    for (int idx = tid; idx < 2048; idx += 256) {
        int r = idx >> 4, c4 = idx & 15;
        float4 xv = *(const float4*)(X + (size_t)(m0 + r)*64 + c4*4);
        uint4 pv;
        pv.x = f2tf32(xv.x); pv.y = f2tf32(xv.y);
        pv.z = f2tf32(xv.z); pv.w = f2tf32(xv.w);
        *(uint4*)(Xs + r*68 + c4*4) = pv;
    }
    for (int idx = tid; idx < 1024; idx += 256) {
        int r = idx >> 4, c4 = idx & 15;
        float4 wv = *(const float4*)(W + (size_t)(n0 + r)*64 + c4*4);
        uint4 pv;
        pv.x = f2tf32(wv.x); pv.y = f2tf32(wv.y);
        pv.z = f2tf32(wv.z); pv.w = f2tf32(wv.w);
        *(uint4*)(Ws + r*68 + c4*4) = pv;
    }
    __syncthreads();

    int w = tid >> 5, lane = tid & 31;
    int qr = lane >> 2, kc = lane & 3;
    int mrow = w*16 + qr;

    unsigned a[8][4];
#pragma unroll
    for (int ks = 0; ks < 8; ks++) {
        a[ks][0] = Xs[mrow*68 + ks*8 + kc];
        a[ks][1] = Xs[(mrow+8)*68 + ks*8 + kc];
        a[ks][2] = Xs[mrow*68 + ks*8 + kc + 4];
        a[ks][3] = Xs[(mrow+8)*68 + ks*8 + kc + 4];
    }

#pragma unroll
    for (int nt = 0; nt < 8; nt++) {
        int ncol = nt*8 + qr;
        float c0 = 0.f, c1 = 0.f, c2 = 0.f, c3 = 0.f;
#pragma unroll
        for (int ks = 0; ks < 8; ks++) {
            unsigned b0 = Ws[ncol*68 + ks*8 + kc];
            unsigned b1 = Ws[ncol*68 + ks*8 + kc + 4];
            MMA_TF32(c0,c1,c2,c3, a[ks][0],a[ks][1],a[ks][2],a[ks][3], b0,b1);
        }
        int gc = n0 + nt*8 + 2*kc;
        float bx = bias[gc], by = bias[gc+1];
        float2 o0; o0.x = c0 + bx; o0.y = c1 + by;
        float2 o1; o1.x = c2 + bx; o1.y = c3 + by;
        *(float2*)(Y + (size_t)(m0 + mrow)*ncols + gc)     = o0;
        *(float2*)(Y + (size_t)(m0 + mrow + 8)*ncols + gc) = o1;
    }
}

// ---------------- per-(b,n) temporal attention, tf32 tensor core ----------------
// smem words: Qs[128][68]=8704 @0, Ks @8704, Vt[64][129]=8256 @17408, biasr @25664
// Ps[128][132]=16896 fp32 overlays Qs+Ks after S is in registers. Total 25792 w = 103KB.
__global__ void __launch_bounds__(256, 2) k_attn(const float* __restrict__ lg,
                                                 const float* __restrict__ lt) {
    extern __shared__ float sm[];
    unsigned* Qs = (unsigned*)sm;
    unsigned* Ks = Qs + 8704;
    unsigned* Vt = Qs + 17408;
    float* biasr = sm + 25664;
    float* Ps = sm;

    int tid = threadIdx.x;
    int bn = blockIdx.x;
    int b = bn >> 8, n = bn & 255;

    float gamma = fmaxf(expf(*lg), 0.01f);
    float tau   = fmaxf(expf(*lt), 0.01f);
    float scale = 1.0f / (8.0f * tau);
    if (tid < 128) biasr[tid] = logf(expf(-gamma * (float)tid * (1.0f/127.0f)) + 1e-8f);

    // load Q,K row-major tf32; V transposed d-major (stride 129)
    for (int idx = tid; idx < 2048; idx += 256) {
        int i = idx >> 4, c4 = idx & 15;
        size_t g = ((size_t)(b*Tt + i)*Nn + n)*Dd + c4*4;
        float4 q  = *(const float4*)(g_Q + g);
        float4 kk = *(const float4*)(g_K + g);
        float4 vv = *(const float4*)(g_V + g);
        uint4 qp; qp.x = f2tf32(q.x); qp.y = f2tf32(q.y); qp.z = f2tf32(q.z); qp.w = f2tf32(q.w);
        uint4 kp; kp.x = f2tf32(kk.x); kp.y = f2tf32(kk.y); kp.z = f2tf32(kk.z); kp.w = f2tf32(kk.w);
        *(uint4*)(Qs + i*68 + c4*4) = qp;
        *(uint4*)(Ks + i*68 + c4*4) = kp;
        Vt[(c4*4+0)*129 + i] = f2tf32(vv.x);
        Vt[(c4*4+1)*129 + i] = f2tf32(vv.y);
        Vt[(c4*4+2)*129 + i] = f2tf32(vv.z);
        Vt[(c4*4+3)*129 + i] = f2tf32(vv.w);
    }
    __syncthreads();

    int w = tid >> 5, lane = tid & 31;
    int qr = lane >> 2, kc = lane & 3;
    int mrow = w*16 + qr;

    // ---- S = Q K^T (warp: 16 rows x 128 cols) ----
    unsigned a[8][4];
#pragma unroll
    for (int ks = 0; ks < 8; ks++) {
        a[ks][0] = Qs[mrow*68 + ks*8 + kc];
        a[ks][1] = Qs[(mrow+8)*68 + ks*8 + kc];
        a[ks][2] = Qs[mrow*68 + ks*8 + kc + 4];
        a[ks][3] = Qs[(mrow+8)*68 + ks*8 + kc + 4];
    }
    float c[16][4];
#pragma unroll
    for (int nt = 0; nt < 16; nt++) { c[nt][0]=0.f; c[nt][1]=0.f; c[nt][2]=0.f; c[nt][3]=0.f; }
#pragma unroll
    for (int nt = 0; nt < 16; nt++) {
        int ncol = nt*8 + qr;
#pragma unroll
        for (int ks = 0; ks < 8; ks++) {
            unsigned b0 = Ks[ncol*68 + ks*8 + kc];
            unsigned b1 = Ks[ncol*68 + ks*8 + kc + 4];
            MMA_TF32(c[nt][0],c[nt][1],c[nt][2],c[nt][3],
                     a[ks][0],a[ks][1],a[ks][2],a[ks][3], b0,b1);
        }
    }
    __syncthreads();   // all Q/K reads complete before P overlay

    int i1 = mrow, i2 = mrow + 8;
#pragma unroll
    for (int nt = 0; nt < 16; nt++) {
        int j0 = nt*8 + 2*kc;
        int d10 = i1 - j0;     d10 = d10 < 0 ? -d10 : d10;
        int d11 = i1 - j0 - 1; d11 = d11 < 0 ? -d11 : d11;
        int d20 = i2 - j0;     d20 = d20 < 0 ? -d20 : d20;
        int d21 = i2 - j0 - 1; d21 = d21 < 0 ? -d21 : d21;
        Ps[i1*132 + j0]     = c[nt][0]*scale + biasr[d10];
        Ps[i1*132 + j0 + 1] = c[nt][1]*scale + biasr[d11];
        Ps[i2*132 + j0]     = c[nt][2]*scale + biasr[d20];
        Ps[i2*132 + j0 + 1] = c[nt][3]*scale + biasr[d21];
    }
    __syncthreads();

    // ---- softmax rows ----
    for (int rr = 0; rr < 16; rr++) {
        int i = w*16 + rr;
        float v0 = Ps[i*132 + lane], v1 = Ps[i*132 + lane + 32],
              v2 = Ps[i*132 + lane + 64], v3 = Ps[i*132 + lane + 96];
        float mx = fmaxf(fmaxf(v0, v1), fmaxf(v2, v3));
#pragma unroll
        for (int off = 16; off > 0; off >>= 1) mx = fmaxf(mx, __shfl_xor_sync(0xffffffff, mx, off));
        float e0 = __expf(v0 - mx), e1 = __expf(v1 - mx), e2 = __expf(v2 - mx), e3 = __expf(v3 - mx);
        float su = (e0 + e1) + (e2 + e3);
#pragma unroll
        for (int off = 16; off > 0; off >>= 1) su += __shfl_xor_sync(0xffffffff, su, off);
        float inv = 1.0f / su;
        Ps[i*132 + lane]      = e0 * inv;
        Ps[i*132 + lane + 32] = e1 * inv;
        Ps[i*132 + lane + 64] = e2 * inv;
        Ps[i*132 + lane + 96] = e3 * inv;
    }
    __syncthreads();

    // ---- out = P @ V (warp: 16 rows x 64 d) ----
    float c2[8][4];
#pragma unroll
    for (int nt = 0; nt < 8; nt++) { c2[nt][0]=0.f; c2[nt][1]=0.f; c2[nt][2]=0.f; c2[nt][3]=0.f; }
#pragma unroll
    for (int ks = 0; ks < 16; ks++) {
        unsigned a0 = f2tf32(Ps[mrow*132 + ks*8 + kc]);
        unsigned a1 = f2tf32(Ps[(mrow+8)*132 + ks*8 + kc]);
        unsigned a2 = f2tf32(Ps[mrow*132 + ks*8 + kc + 4]);
        unsigned a3 = f2tf32(Ps[(mrow+8)*132 + ks*8 + kc + 4]);
#pragma unroll
        for (int nt = 0; nt < 8; nt++) {
            unsigned b0 = Vt[(nt*8+qr)*129 + ks*8 + kc];
            unsigned b1 = Vt[(nt*8+qr)*129 + ks*8 + kc + 4];
            MMA_TF32(c2[nt][0],c2[nt][1],c2[nt][2],c2[nt][3], a0,a1,a2,a3, b0,b1);
        }
    }
#pragma unroll
    for (int nt = 0; nt < 8; nt++) {
        int d = nt*8 + 2*kc;
        float2 o0; o0.x = c2[nt][0]; o0.y = c2[nt][1];
        float2 o1; o1.x = c2[nt][2]; o1.y = c2[nt][3];
        *(float2*)(g_ALN + ((size_t)(b*Tt + mrow)*Nn + n)*Dd + d)     = o0;
        *(float2*)(g_ALN + ((size_t)(b*Tt + mrow + 8)*Nn + n)*Dd + d) = o1;
    }
}

// ---------------- GCN + residual + LN1, tf32 tensor core ----------------
// per block: half of one (b,t): 128 m rows. smem words:
// As[128][68]=8704 @0 (adp chunk; later h2 fp32 [128][68]), Bs[64][65]=4160 @8704,
// Tmp[128][68]=8704 @12864, Wgs[64][68]=4352 @21568. Total 25920 w = 103.7KB.
__global__ void __launch_bounds__(256, 2) k_gcn(const float* __restrict__ Wg,
                                                const float* __restrict__ bg,
                                                const float* __restrict__ ln1g,
                                                const float* __restrict__ ln1b) {
    extern __shared__ float sg[];
    unsigned* As  = (unsigned*)sg;
    unsigned* Bs  = As + 8704;
    unsigned* Tmp = As + 12864;
    unsigned* Wgs = As + 21568;
    float* h2 = sg;   // overlays As

    int tid = threadIdx.x;
    int blk = blockIdx.x;
    int bt = blk >> 1, half = blk & 1;
    int m0g = half * 128;
    int b = bt >> 7, t = bt & 127;
    const float* Xbt = g_ALN + (size_t)bt * 16384;

    int w = tid >> 5, lane = tid & 31;
    int qr = lane >> 2, kc = lane & 3;
    int mrow = w*16 + qr;

    // load Wg tf32 (row-major [e][d])
    for (int idx = tid; idx < 1024; idx += 256) {
        int r = idx >> 4, c4 = idx & 15;
        float4 wv = *(const float4*)(Wg + (size_t)r*64 + c4*4);
        uint4 pv; pv.x = f2tf32(wv.x); pv.y = f2tf32(wv.y);
        pv.z = f2tf32(wv.z); pv.w = f2tf32(wv.w);
        *(uint4*)(Wgs + r*68 + c4*4) = pv;
    }

    // ---- GEMM1: H[m,d] = sum_n adp[m,n] x[n,d], k streamed in 4 chunks of 64 ----
    float c1[8][4];
#pragma unroll
    for (int nt = 0; nt < 8; nt++) { c1[nt][0]=0.f; c1[nt][1]=0.f; c1[nt][2]=0.f; c1[nt][3]=0.f; }

    for (int ch = 0; ch < 4; ch++) {
        __syncthreads();
        for (int idx = tid; idx < 2048; idx += 256) {
            int r = idx >> 4, c4 = idx & 15;
            *(uint4*)(As + r*68 + c4*4) =
                *(const uint4*)(g_ADPu + (size_t)(m0g + r)*256 + ch*64 + c4*4);
        }
        for (int idx = tid; idx < 1024; idx += 256) {
            int nn = idx >> 4, c4 = idx & 15;
            float4 xv = *(const float4*)(Xbt + (size_t)(ch*64 + nn)*64 + c4*4);
            Bs[(c4*4+0)*65 + nn] = f2tf32(xv.x);
            Bs[(c4*4+1)*65 + nn] = f2tf32(xv.y);
            Bs[(c4*4+2)*65 + nn] = f2tf32(xv.z);
            Bs[(c4*4+3)*65 + nn] = f2tf32(xv.w);
        }
        __syncthreads();
#pragma unroll
        for (int ks = 0; ks < 8; ks++) {
            unsigned a0 = As[mrow*68 + ks*8 + kc];
            unsigned a1 = As[(mrow+8)*68 + ks*8 + kc];
            unsigned a2 = As[mrow*68 + ks*8 + kc + 4];
            unsigned a3 = As[(mrow+8)*68 + ks*8 + kc + 4];
#pragma unroll
            for (int nt = 0; nt < 8; nt++) {
                unsigned b0 = Bs[(nt*8+qr)*65 + ks*8 + kc];
                unsigned b1 = Bs[(nt*8+qr)*65 + ks*8 + kc + 4];
                MMA_TF32(c1[nt][0],c1[nt][1],c1[nt][2],c1[nt][3], a0,a1,a2,a3, b0,b1);
            }
        }
    }

    // write Tmp tf32 [m][d]
#pragma unroll
    for (int nt = 0; nt < 8; nt++) {
        int d0 = nt*8 + 2*kc;
        Tmp[mrow*68 + d0]       = f2tf32(c1[nt][0]);
        Tmp[mrow*68 + d0 + 1]   = f2tf32(c1[nt][1]);
        Tmp[(mrow+8)*68 + d0]     = f2tf32(c1[nt][2]);
        Tmp[(mrow+8)*68 + d0 + 1] = f2tf32(c1[nt][3]);
    }
    __syncwarp();

    // ---- GEMM2: out2[m,e] = sum_d Tmp[m,d] Wg[e,d] ----
    float c2[8][4];
#pragma unroll
    for (int nt = 0; nt < 8; nt++) { c2[nt][0]=0.f; c2[nt][1]=0.f; c2[nt][2]=0.f; c2[nt][3]=0.f; }
#pragma unroll
    for (int ks = 0; ks < 8; ks++) {
        unsigned a0 = Tmp[mrow*68 + ks*8 + kc];
        unsigned a1 = Tmp[(mrow+8)*68 + ks*8 + kc];
        unsigned a2 = Tmp[mrow*68 + ks*8 + kc + 4];
        unsigned a3 = Tmp[(mrow+8)*68 + ks*8 + kc + 4];
#pragma unroll
        for (int nt = 0; nt < 8; nt++) {
            unsigned b0 = Wgs[(nt*8+qr)*68 + ks*8 + kc];
            unsigned b1 = Wgs[(nt*8+qr)*68 + ks*8 + kc + 4];
            MMA_TF32(c2[nt][0],c2[nt][1],c2[nt][2],c2[nt][3], a0,a1,a2,a3, b0,b1);
        }
    }
    __syncthreads();   // everyone done reading As before h2 overlay

    // h2 = relu(c2 + bg), fp32 [128][68]
#pragma unroll
    for (int nt = 0; nt < 8; nt++) {
        int e0 = nt*8 + 2*kc;
        float bx = bg[e0], by = bg[e0+1];
        h2[mrow*68 + e0]       = fmaxf(c2[nt][0] + bx, 0.f);
        h2[mrow*68 + e0 + 1]   = fmaxf(c2[nt][1] + by, 0.f);
        h2[(mrow+8)*68 + e0]     = fmaxf(c2[nt][2] + bx, 0.f);
        h2[(mrow+8)*68 + e0 + 1] = fmaxf(c2[nt][3] + by, 0.f);
    }
    __syncthreads();

    // residual + LN1, write transposed to g_X1 [B,N,T,D]
    float gg0 = ln1g[lane], gg1 = ln1g[lane+32];
    float bb0 = ln1b[lane], bb1 = ln1b[lane+32];
    for (int mm = 0; mm < 16; mm++) {
        int m = w*16 + mm;
        const float* xr = Xbt + (size_t)(m0g + m)*64;
        float u0 = xr[lane]      + h2[m*68 + lane];
        float u1 = xr[lane + 32] + h2[m*68 + lane + 32];
        float su = u0 + u1;
#pragma unroll
        for (int off = 16; off > 0; off >>= 1) su += __shfl_xor_sync(0xffffffff, su, off);
        float mean = su * (1.0f/64.0f);
        float dd0 = u0 - mean, dd1 = u1 - mean;
        float q = dd0*dd0 + dd1*dd1;
#pragma unroll
        for (int off = 16; off > 0; off >>= 1) q += __shfl_xor_sync(0xffffffff, q, off);
        float rs = rsqrtf(q*(1.0f/64.0f) + 1e-5f);
        size_t o = ((size_t)(b*Nn + m0g + m)*Tt + t)*Dd;
        g_X1[o + lane]      = dd0*rs*gg0 + bb0;
        g_X1[o + lane + 32] = dd1*rs*gg1 + bb1;
    }
}

// ---------------- GRU scan fused with LN2 + residual + final output ----------------
__global__ void __launch_bounds__(192) k_gru(const float* __restrict__ Whh,
                                             const float* __restrict__ bhh,
                                             const float* __restrict__ ln2g,
                                             const float* __restrict__ ln2b,
                                             float* __restrict__ out) {
    __shared__ float h_s[64];
    __shared__ float gh_s[192];
    __shared__ float red[4];
    int tid = threadIdx.x;          // 192
    int bn = blockIdx.x;
    int b = bn >> 8, n = bn & 255;

    float w[64];
#pragma unroll
    for (int i = 0; i < 16; i++) ((float4*)w)[i] = *(const float4*)(Whh + tid*64 + i*4);
    float bh = bhh[tid];
    float g2 = 0.f, b2 = 0.f;
    if (tid < 64) { h_s[tid] = 0.f; g2 = ln2g[tid]; b2 = ln2b[tid]; }

    const float* gi = g_GI + (size_t)bn * Tt * D3;
    const float* x1 = g_X1 + (size_t)bn * Tt * Dd;
    float* outb = out + ((size_t)b*Tt*Nn + n)*Dd;
    __syncthreads();

    for (int t = 0; t < Tt; t++) {
        float xv = (tid < 64) ? x1[t*64 + tid] : 0.f;
        float a0 = 0.f, a1 = 0.f, a2 = 0.f, a3 = 0.f;
#pragma unroll
        for (int d4 = 0; d4 < 16; d4++) {
            float4 hv = ((const float4*)h_s)[d4];
            a0 = fmaf(w[d4*4+0], hv.x, a0);
            a1 = fmaf(w[d4*4+1], hv.y, a1);
            a2 = fmaf(w[d4*4+2], hv.z, a2);
            a3 = fmaf(w[d4*4+3], hv.w, a3);
        }
        gh_s[tid] = bh + ((a0 + a1) + (a2 + a3));
        __syncthreads();
        float u_keep = 0.f;
        if (tid < 64) {
            const float* gt = gi + t*D3;
            float r  = sigf(gt[tid]        + gh_s[tid]);
            float z  = sigf(gt[64 + tid]   + gh_s[64 + tid]);
            float nn = tanhf(gt[128 + tid] + r * gh_s[128 + tid]);
            float hn = (1.0f - z)*nn + z*h_s[tid];
            h_s[tid] = hn;
            float u = xv + hn;
            u_keep = u;
            float s = u, q = u*u;
#pragma unroll
            for (int off = 16; off > 0; off >>= 1) {
                s += __shfl_xor_sync(0xffffffff, s, off);
                q += __shfl_xor_sync(0xffffffff, q, off);
            }
            if ((tid & 31) == 0) { red[(tid>>5)*2] = s; red[(tid>>5)*2+1] = q; }
        }
        __syncthreads();
        if (tid < 64) {
            float s = red[0] + red[2], q = red[1] + red[3];
            float mean = s * (1.0f/64.0f);
            float var = q*(1.0f/64.0f) - mean*mean;
            float rs = rsqrtf(var + 1e-5f);
            float y = (u_keep - mean)*rs*g2 + b2;
            outb[(size_t)t*Nn*Dd + tid] = xv + y;
        }
    }
}

// ---------------- launcher ----------------
extern "C" void kernel_launch(void* const* d_in, const int* in_sizes, int n_in,
                              void* d_out, int out_size) {
    (void)in_sizes; (void)n_in; (void)out_size;
    const float* H_i  = (const float*)d_in[0];
    const float* H_j  = (const float*)d_in[1];
    const float* Wq   = (const float*)d_in[2];
    const float* bq   = (const float*)d_in[3];
    const float* Wk   = (const float*)d_in[4];
    const float* bk   = (const float*)d_in[5];
    const float* Wv   = (const float*)d_in[6];
    const float* bv   = (const float*)d_in[7];
    const float* lgam = (const float*)d_in[8];
    const float* ltau = (const float*)d_in[9];
    const float* e1   = (const float*)d_in[10];
    const float* e2   = (const float*)d_in[11];
    const float* Wg   = (const float*)d_in[12];
    const float* bg   = (const float*)d_in[13];
    const float* ln1g = (const float*)d_in[14];
    const float* ln1b = (const float*)d_in[15];
    const float* Wih  = (const float*)d_in[16];
    const float* Whh  = (const float*)d_in[17];
    const float* bih  = (const float*)d_in[18];
    const float* bhh  = (const float*)d_in[19];
    const float* ln2g = (const float*)d_in[20];
    const float* ln2b = (const float*)d_in[21];
    float* out = (float*)d_out;

    float *pQ, *pK, *pV, *pGI, *pX1;
    cudaGetSymbolAddress((void**)&pQ,  g_Q);
    cudaGetSymbolAddress((void**)&pK,  g_K);
    cudaGetSymbolAddress((void**)&pV,  g_V);
    cudaGetSymbolAddress((void**)&pGI, g_GI);
    cudaGetSymbolAddress((void**)&pX1, g_X1);

    const int LIN_SMEM  = (128+64)*68*4;  // 52224 B
    const int ATTN_SMEM = 25792 * 4;      // 103168 B
    const int GCN_SMEM  = 25920 * 4;      // 103680 B
    cudaFuncSetAttribute(k_lin_tf32, cudaFuncAttributeMaxDynamicSharedMemorySize, LIN_SMEM);
    cudaFuncSetAttribute(k_attn, cudaFuncAttributeMaxDynamicSharedMemorySize, ATTN_SMEM);
    cudaFuncSetAttribute(k_gcn,  cudaFuncAttributeMaxDynamicSharedMemorySize, GCN_SMEM);

    k_adj<<<256, 256>>>(e1, e2);
    k_lin_tf32<<<dim3(MROWS/128, 1), 256, LIN_SMEM>>>(H_i, Wq, bq, pQ, 64);
    k_lin_tf32<<<dim3(MROWS/128, 1), 256, LIN_SMEM>>>(H_j, Wk, bk, pK, 64);
    k_lin_tf32<<<dim3(MROWS/128, 1), 256, LIN_SMEM>>>(H_j, Wv, bv, pV, 64);
    k_attn<<<Bb*Nn, 256, ATTN_SMEM>>>(lgam, ltau);
    k_gcn<<<Bb*Tt*2, 256, GCN_SMEM>>>(Wg, bg, ln1g, ln1b);
    k_lin_tf32<<<dim3(MROWS/128, 3), 256, LIN_SMEM>>>(pX1, Wih, bih, pGI, 192);
    k_gru<<<Bb*Nn, 192>>>(Whh, bhh, ln2g, ln2b, out);
}

// round 6
// speedup vs baseline: 2.2978x; 1.5812x over previous
#include <cuda_runtime.h>
#include <math.h>

#define Bb 8
#define Tt 128
#define Nn 256
#define Dd 64
#define D3 192
#define BTND 16777216   // 8*128*256*64
#define MROWS 262144    // B*T*N == B*N*T

// ---------------- device scratch ----------------
__device__ float g_Q[BTND];
__device__ float g_K[BTND];
__device__ float g_V[BTND];
__device__ float g_ALN[BTND];          // aligner output, [B,T,N,D]
__device__ float g_X1[BTND];           // post-ln1, [B,N,T,D]
__device__ float g_GI[50331648];       // [B,N,T,192]
__device__ unsigned g_ADPu[Nn*Nn];     // adjacency, tf32 bits, row-major [m][n]

__device__ __forceinline__ unsigned f2tf32(float f) {
    unsigned u;
    asm("cvt.rna.tf32.f32 %0, %1;" : "=r"(u) : "f"(f));
    return u;
}
__device__ __forceinline__ float tanha(float x) {
    float y;
    asm("tanh.approx.f32 %0, %1;" : "=f"(y) : "f"(x));
    return y;
}
__device__ __forceinline__ float siga(float x) { return 0.5f*tanha(0.5f*x) + 0.5f; }

#define MMA_TF32(c0,c1,c2,c3,a0,a1,a2,a3,b0,b1) \
    asm volatile("mma.sync.aligned.m16n8k8.row.col.f32.tf32.tf32.f32 " \
        "{%0,%1,%2,%3}, {%4,%5,%6,%7}, {%8,%9}, {%0,%1,%2,%3};" \
        : "+f"(c0), "+f"(c1), "+f"(c2), "+f"(c3) \
        : "r"(a0), "r"(a1), "r"(a2), "r"(a3), "r"(b0), "r"(b1))

// ---------------- adjacency: adp = softmax_row(relu(e1@e2)), tf32 bits ----------------
__global__ void k_adj(const float* __restrict__ e1, const float* __restrict__ e2) {
    int m = blockIdx.x;
    int n = threadIdx.x;            // 256 threads
    float a = 0.f;
#pragma unroll
    for (int k = 0; k < 32; k++) a = fmaf(e1[m*32 + k], e2[k*256 + n], a);
    a = fmaxf(a, 0.f);
    __shared__ float red[256];
    red[n] = a; __syncthreads();
    for (int s = 128; s > 0; s >>= 1) { if (n < s) red[n] = fmaxf(red[n], red[n+s]); __syncthreads(); }
    float mx = red[0]; __syncthreads();
    float e = expf(a - mx);
    red[n] = e; __syncthreads();
    for (int s = 128; s > 0; s >>= 1) { if (n < s) red[n] += red[n+s]; __syncthreads(); }
    g_ADPu[m*256 + n] = f2tf32(e / red[0]);
}

// ---------------- tf32 tensor-core linear: Y = X @ W^T + b ----------------
__global__ void __launch_bounds__(256) k_lin_tf32(const float* __restrict__ X,
                                                  const float* __restrict__ W,
                                                  const float* __restrict__ bias,
                                                  float* __restrict__ Y, int ncols) {
    extern __shared__ unsigned sl[];
    unsigned* Xs = sl;              // [128][68] tf32 bits
    unsigned* Ws = sl + 128*68;     // [64][68]
    int m0 = blockIdx.x * 128;
    int n0 = blockIdx.y * 64;
    int tid = threadIdx.x;

    for (int idx = tid; idx < 2048; idx += 256) {
        int r = idx >> 4, c4 = idx & 15;
        float4 xv = *(const float4*)(X + (size_t)(m0 + r)*64 + c4*4);
        uint4 pv;
        pv.x = f2tf32(xv.x); pv.y = f2tf32(xv.y);
        pv.z = f2tf32(xv.z); pv.w = f2tf32(xv.w);
        *(uint4*)(Xs + r*68 + c4*4) = pv;
    }
    for (int idx = tid; idx < 1024; idx += 256) {
        int r = idx >> 4, c4 = idx & 15;
        float4 wv = *(const float4*)(W + (size_t)(n0 + r)*64 + c4*4);
        uint4 pv;
        pv.x = f2tf32(wv.x); pv.y = f2tf32(wv.y);
        pv.z = f2tf32(wv.z); pv.w = f2tf32(wv.w);
        *(uint4*)(Ws + r*68 + c4*4) = pv;
    }
    __syncthreads();

    int w = tid >> 5, lane = tid & 31;
    int qr = lane >> 2, kc = lane & 3;
    int mrow = w*16 + qr;

    unsigned a[8][4];
#pragma unroll
    for (int ks = 0; ks < 8; ks++) {
        a[ks][0] = Xs[mrow*68 + ks*8 + kc];
        a[ks][1] = Xs[(mrow+8)*68 + ks*8 + kc];
        a[ks][2] = Xs[mrow*68 + ks*8 + kc + 4];
        a[ks][3] = Xs[(mrow+8)*68 + ks*8 + kc + 4];
    }

#pragma unroll
    for (int nt = 0; nt < 8; nt++) {
        int ncol = nt*8 + qr;
        float c0 = 0.f, c1 = 0.f, c2 = 0.f, c3 = 0.f;
#pragma unroll
        for (int ks = 0; ks < 8; ks++) {
            unsigned b0 = Ws[ncol*68 + ks*8 + kc];
            unsigned b1 = Ws[ncol*68 + ks*8 + kc + 4];
            MMA_TF32(c0,c1,c2,c3, a[ks][0],a[ks][1],a[ks][2],a[ks][3], b0,b1);
        }
        int gc = n0 + nt*8 + 2*kc;
        float bx = bias[gc], by = bias[gc+1];
        float2 o0; o0.x = c0 + bx; o0.y = c1 + by;
        float2 o1; o1.x = c2 + bx; o1.y = c3 + by;
        *(float2*)(Y + (size_t)(m0 + mrow)*ncols + gc)     = o0;
        *(float2*)(Y + (size_t)(m0 + mrow + 8)*ncols + gc) = o1;
    }
}

// ---------------- per-(b,n) temporal attention, tf32 tensor core ----------------
__global__ void __launch_bounds__(256, 2) k_attn(const float* __restrict__ lg,
                                                 const float* __restrict__ lt) {
    extern __shared__ float sm[];
    unsigned* Qs = (unsigned*)sm;
    unsigned* Ks = Qs + 8704;
    unsigned* Vt = Qs + 17408;
    float* biasr = sm + 25664;
    float* Ps = sm;
    unsigned* Pu = (unsigned*)sm;

    int tid = threadIdx.x;
    int bn = blockIdx.x;
    int b = bn >> 8, n = bn & 255;

    float gamma = fmaxf(expf(*lg), 0.01f);
    float tau   = fmaxf(expf(*lt), 0.01f);
    float scale = 1.0f / (8.0f * tau);
    if (tid < 128) biasr[tid] = logf(expf(-gamma * (float)tid * (1.0f/127.0f)) + 1e-8f);

    for (int idx = tid; idx < 2048; idx += 256) {
        int i = idx >> 4, c4 = idx & 15;
        size_t g = ((size_t)(b*Tt + i)*Nn + n)*Dd + c4*4;
        float4 q  = *(const float4*)(g_Q + g);
        float4 kk = *(const float4*)(g_K + g);
        float4 vv = *(const float4*)(g_V + g);
        uint4 qp; qp.x = f2tf32(q.x); qp.y = f2tf32(q.y); qp.z = f2tf32(q.z); qp.w = f2tf32(q.w);
        uint4 kp; kp.x = f2tf32(kk.x); kp.y = f2tf32(kk.y); kp.z = f2tf32(kk.z); kp.w = f2tf32(kk.w);
        *(uint4*)(Qs + i*68 + c4*4) = qp;
        *(uint4*)(Ks + i*68 + c4*4) = kp;
        Vt[(c4*4+0)*129 + i] = f2tf32(vv.x);
        Vt[(c4*4+1)*129 + i] = f2tf32(vv.y);
        Vt[(c4*4+2)*129 + i] = f2tf32(vv.z);
        Vt[(c4*4+3)*129 + i] = f2tf32(vv.w);
    }
    __syncthreads();

    int w = tid >> 5, lane = tid & 31;
    int qr = lane >> 2, kc = lane & 3;
    int mrow = w*16 + qr;

    // ---- S = Q K^T ----
    unsigned a[8][4];
#pragma unroll
    for (int ks = 0; ks < 8; ks++) {
        a[ks][0] = Qs[mrow*68 + ks*8 + kc];
        a[ks][1] = Qs[(mrow+8)*68 + ks*8 + kc];
        a[ks][2] = Qs[mrow*68 + ks*8 + kc + 4];
        a[ks][3] = Qs[(mrow+8)*68 + ks*8 + kc + 4];
    }
    float c[16][4];
#pragma unroll
    for (int nt = 0; nt < 16; nt++) { c[nt][0]=0.f; c[nt][1]=0.f; c[nt][2]=0.f; c[nt][3]=0.f; }
#pragma unroll
    for (int nt = 0; nt < 16; nt++) {
        int ncol = nt*8 + qr;
#pragma unroll
        for (int ks = 0; ks < 8; ks++) {
            unsigned b0 = Ks[ncol*68 + ks*8 + kc];
            unsigned b1 = Ks[ncol*68 + ks*8 + kc + 4];
            MMA_TF32(c[nt][0],c[nt][1],c[nt][2],c[nt][3],
                     a[ks][0],a[ks][1],a[ks][2],a[ks][3], b0,b1);
        }
    }
    __syncthreads();

    int i1 = mrow, i2 = mrow + 8;
#pragma unroll
    for (int nt = 0; nt < 16; nt++) {
        int j0 = nt*8 + 2*kc;
        int d10 = i1 - j0;     d10 = d10 < 0 ? -d10 : d10;
        int d11 = i1 - j0 - 1; d11 = d11 < 0 ? -d11 : d11;
        int d20 = i2 - j0;     d20 = d20 < 0 ? -d20 : d20;
        int d21 = i2 - j0 - 1; d21 = d21 < 0 ? -d21 : d21;
        Ps[i1*132 + j0]     = c[nt][0]*scale + biasr[d10];
        Ps[i1*132 + j0 + 1] = c[nt][1]*scale + biasr[d11];
        Ps[i2*132 + j0]     = c[nt][2]*scale + biasr[d20];
        Ps[i2*132 + j0 + 1] = c[nt][3]*scale + biasr[d21];
    }
    __syncthreads();

    // ---- softmax rows, write P as tf32 bits ----
    for (int rr = 0; rr < 16; rr++) {
        int i = w*16 + rr;
        float v0 = Ps[i*132 + lane], v1 = Ps[i*132 + lane + 32],
              v2 = Ps[i*132 + lane + 64], v3 = Ps[i*132 + lane + 96];
        float mx = fmaxf(fmaxf(v0, v1), fmaxf(v2, v3));
#pragma unroll
        for (int off = 16; off > 0; off >>= 1) mx = fmaxf(mx, __shfl_xor_sync(0xffffffff, mx, off));
        float e0 = __expf(v0 - mx), e1 = __expf(v1 - mx), e2 = __expf(v2 - mx), e3 = __expf(v3 - mx);
        float su = (e0 + e1) + (e2 + e3);
#pragma unroll
        for (int off = 16; off > 0; off >>= 1) su += __shfl_xor_sync(0xffffffff, su, off);
        float inv = 1.0f / su;
        Pu[i*132 + lane]      = f2tf32(e0 * inv);
        Pu[i*132 + lane + 32] = f2tf32(e1 * inv);
        Pu[i*132 + lane + 64] = f2tf32(e2 * inv);
        Pu[i*132 + lane + 96] = f2tf32(e3 * inv);
    }
    __syncthreads();

    // ---- out = P @ V ----
    float c2[8][4];
#pragma unroll
    for (int nt = 0; nt < 8; nt++) { c2[nt][0]=0.f; c2[nt][1]=0.f; c2[nt][2]=0.f; c2[nt][3]=0.f; }
#pragma unroll
    for (int ks = 0; ks < 16; ks++) {
        unsigned a0 = Pu[mrow*132 + ks*8 + kc];
        unsigned a1 = Pu[(mrow+8)*132 + ks*8 + kc];
        unsigned a2 = Pu[mrow*132 + ks*8 + kc + 4];
        unsigned a3 = Pu[(mrow+8)*132 + ks*8 + kc + 4];
#pragma unroll
        for (int nt = 0; nt < 8; nt++) {
            unsigned b0 = Vt[(nt*8+qr)*129 + ks*8 + kc];
            unsigned b1 = Vt[(nt*8+qr)*129 + ks*8 + kc + 4];
            MMA_TF32(c2[nt][0],c2[nt][1],c2[nt][2],c2[nt][3], a0,a1,a2,a3, b0,b1);
        }
    }
#pragma unroll
    for (int nt = 0; nt < 8; nt++) {
        int d = nt*8 + 2*kc;
        float2 o0; o0.x = c2[nt][0]; o0.y = c2[nt][1];
        float2 o1; o1.x = c2[nt][2]; o1.y = c2[nt][3];
        *(float2*)(g_ALN + ((size_t)(b*Tt + mrow)*Nn + n)*Dd + d)     = o0;
        *(float2*)(g_ALN + ((size_t)(b*Tt + mrow + 8)*Nn + n)*Dd + d) = o1;
    }
}

// ---------------- GCN + residual + LN1, tf32 tensor core ----------------
__global__ void __launch_bounds__(256, 2) k_gcn(const float* __restrict__ Wg,
                                                const float* __restrict__ bg,
                                                const float* __restrict__ ln1g,
                                                const float* __restrict__ ln1b) {
    extern __shared__ float sg[];
    unsigned* As  = (unsigned*)sg;
    unsigned* Bs  = As + 8704;
    unsigned* Tmp = As + 12864;
    unsigned* Wgs = As + 21568;
    float* h2 = sg;   // overlays As

    int tid = threadIdx.x;
    int blk = blockIdx.x;
    int bt = blk >> 1, half = blk & 1;
    int m0g = half * 128;
    int b = bt >> 7, t = bt & 127;
    const float* Xbt = g_ALN + (size_t)bt * 16384;

    int w = tid >> 5, lane = tid & 31;
    int qr = lane >> 2, kc = lane & 3;
    int mrow = w*16 + qr;

    for (int idx = tid; idx < 1024; idx += 256) {
        int r = idx >> 4, c4 = idx & 15;
        float4 wv = *(const float4*)(Wg + (size_t)r*64 + c4*4);
        uint4 pv; pv.x = f2tf32(wv.x); pv.y = f2tf32(wv.y);
        pv.z = f2tf32(wv.z); pv.w = f2tf32(wv.w);
        *(uint4*)(Wgs + r*68 + c4*4) = pv;
    }

    float c1[8][4];
#pragma unroll
    for (int nt = 0; nt < 8; nt++) { c1[nt][0]=0.f; c1[nt][1]=0.f; c1[nt][2]=0.f; c1[nt][3]=0.f; }

    for (int ch = 0; ch < 4; ch++) {
        __syncthreads();
        for (int idx = tid; idx < 2048; idx += 256) {
            int r = idx >> 4, c4 = idx & 15;
            *(uint4*)(As + r*68 + c4*4) =
                *(const uint4*)(g_ADPu + (size_t)(m0g + r)*256 + ch*64 + c4*4);
        }
        for (int idx = tid; idx < 1024; idx += 256) {
            int nn = idx >> 4, c4 = idx & 15;
            float4 xv = *(const float4*)(Xbt + (size_t)(ch*64 + nn)*64 + c4*4);
            Bs[(c4*4+0)*65 + nn] = f2tf32(xv.x);
            Bs[(c4*4+1)*65 + nn] = f2tf32(xv.y);
            Bs[(c4*4+2)*65 + nn] = f2tf32(xv.z);
            Bs[(c4*4+3)*65 + nn] = f2tf32(xv.w);
        }
        __syncthreads();
#pragma unroll
        for (int ks = 0; ks < 8; ks++) {
            unsigned a0 = As[mrow*68 + ks*8 + kc];
            unsigned a1 = As[(mrow+8)*68 + ks*8 + kc];
            unsigned a2 = As[mrow*68 + ks*8 + kc + 4];
            unsigned a3 = As[(mrow+8)*68 + ks*8 + kc + 4];
#pragma unroll
            for (int nt = 0; nt < 8; nt++) {
                unsigned b0 = Bs[(nt*8+qr)*65 + ks*8 + kc];
                unsigned b1 = Bs[(nt*8+qr)*65 + ks*8 + kc + 4];
                MMA_TF32(c1[nt][0],c1[nt][1],c1[nt][2],c1[nt][3], a0,a1,a2,a3, b0,b1);
            }
        }
    }

#pragma unroll
    for (int nt = 0; nt < 8; nt++) {
        int d0 = nt*8 + 2*kc;
        Tmp[mrow*68 + d0]       = f2tf32(c1[nt][0]);
        Tmp[mrow*68 + d0 + 1]   = f2tf32(c1[nt][1]);
        Tmp[(mrow+8)*68 + d0]     = f2tf32(c1[nt][2]);
        Tmp[(mrow+8)*68 + d0 + 1] = f2tf32(c1[nt][3]);
    }
    __syncwarp();

    float c2[8][4];
#pragma unroll
    for (int nt = 0; nt < 8; nt++) { c2[nt][0]=0.f; c2[nt][1]=0.f; c2[nt][2]=0.f; c2[nt][3]=0.f; }
#pragma unroll
    for (int ks = 0; ks < 8; ks++) {
        unsigned a0 = Tmp[mrow*68 + ks*8 + kc];
        unsigned a1 = Tmp[(mrow+8)*68 + ks*8 + kc];
        unsigned a2 = Tmp[mrow*68 + ks*8 + kc + 4];
        unsigned a3 = Tmp[(mrow+8)*68 + ks*8 + kc + 4];
#pragma unroll
        for (int nt = 0; nt < 8; nt++) {
            unsigned b0 = Wgs[(nt*8+qr)*68 + ks*8 + kc];
            unsigned b1 = Wgs[(nt*8+qr)*68 + ks*8 + kc + 4];
            MMA_TF32(c2[nt][0],c2[nt][1],c2[nt][2],c2[nt][3], a0,a1,a2,a3, b0,b1);
        }
    }
    __syncthreads();

#pragma unroll
    for (int nt = 0; nt < 8; nt++) {
        int e0 = nt*8 + 2*kc;
        float bx = bg[e0], by = bg[e0+1];
        h2[mrow*68 + e0]       = fmaxf(c2[nt][0] + bx, 0.f);
        h2[mrow*68 + e0 + 1]   = fmaxf(c2[nt][1] + by, 0.f);
        h2[(mrow+8)*68 + e0]     = fmaxf(c2[nt][2] + bx, 0.f);
        h2[(mrow+8)*68 + e0 + 1] = fmaxf(c2[nt][3] + by, 0.f);
    }
    __syncthreads();

    float gg0 = ln1g[lane], gg1 = ln1g[lane+32];
    float bb0 = ln1b[lane], bb1 = ln1b[lane+32];
    for (int mm = 0; mm < 16; mm++) {
        int m = w*16 + mm;
        const float* xr = Xbt + (size_t)(m0g + m)*64;
        float u0 = xr[lane]      + h2[m*68 + lane];
        float u1 = xr[lane + 32] + h2[m*68 + lane + 32];
        float su = u0 + u1;
#pragma unroll
        for (int off = 16; off > 0; off >>= 1) su += __shfl_xor_sync(0xffffffff, su, off);
        float mean = su * (1.0f/64.0f);
        float dd0 = u0 - mean, dd1 = u1 - mean;
        float q = dd0*dd0 + dd1*dd1;
#pragma unroll
        for (int off = 16; off > 0; off >>= 1) q += __shfl_xor_sync(0xffffffff, q, off);
        float rs = rsqrtf(q*(1.0f/64.0f) + 1e-5f);
        size_t o = ((size_t)(b*Nn + m0g + m)*Tt + t)*Dd;
        g_X1[o + lane]      = dd0*rs*gg0 + bb0;
        g_X1[o + lane + 32] = dd1*rs*gg1 + bb1;
    }
}

// ---------------- tensor-core GRU: 16 sequences per block, fused LN2+out ----------------
// smem words: Whh tf32 [192][68]=13056 @0, H ping-pong [16][68]x2 @13056,@14144,
// U fp32 [16][68] @15232, mv [16][2] @16320. Total 16352 w = 65408 B.
__global__ void __launch_bounds__(256) k_gru_tc(const float* __restrict__ Whh,
                                                const float* __restrict__ bhh,
                                                const float* __restrict__ ln2g,
                                                const float* __restrict__ ln2b,
                                                float* __restrict__ out) {
    extern __shared__ unsigned su_[];
    unsigned* Whs = su_;
    unsigned* Hb0 = su_ + 13056;
    unsigned* Hb1 = su_ + 14144;
    float* U = (float*)(su_ + 15232);
    float* mv = (float*)(su_ + 16320);

    int tid = threadIdx.x;
    int w = tid >> 5, lane = tid & 31;
    int qr = lane >> 2, kc = lane & 3;
    int s_base = blockIdx.x * 16;          // 16 sequences
    int b = s_base >> 8;
    int node0 = s_base & 255;

    // stage Whh tf32 [192][68]
    for (int idx = tid; idx < 3072; idx += 256) {
        int r = idx >> 4, c4 = idx & 15;
        float4 wv = *(const float4*)(Whh + (size_t)r*64 + c4*4);
        uint4 pv; pv.x = f2tf32(wv.x); pv.y = f2tf32(wv.y);
        pv.z = f2tf32(wv.z); pv.w = f2tf32(wv.w);
        *(uint4*)(Whs + r*68 + c4*4) = pv;
    }
    // zero H buffer 0
    for (int idx = tid; idx < 1088; idx += 256) Hb0[idx] = 0;
    __syncthreads();

    // hoist B fragments: gate g, k-step ks
    unsigned br_[8][2], bz_[8][2], bn_[8][2];
#pragma unroll
    for (int ks = 0; ks < 8; ks++) {
        int nr = (0*64 + w*8 + qr)*68 + ks*8 + kc;
        int nz = (1*64 + w*8 + qr)*68 + ks*8 + kc;
        int nn = (2*64 + w*8 + qr)*68 + ks*8 + kc;
        br_[ks][0] = Whs[nr]; br_[ks][1] = Whs[nr + 4];
        bz_[ks][0] = Whs[nz]; bz_[ks][1] = Whs[nz + 4];
        bn_[ks][0] = Whs[nn]; bn_[ks][1] = Whs[nn + 4];
    }
    int col0 = w*8 + 2*kc;                  // hidden col pair (col0, col0+1)
    float2 bhr = *(const float2*)(bhh + col0);
    float2 bhz = *(const float2*)(bhh + 64 + col0);
    float2 bhn = *(const float2*)(bhh + 128 + col0);
    float2 g2 = *(const float2*)(ln2g + col0);
    float2 b2 = *(const float2*)(ln2b + col0);

    // per-thread gmem bases: rows qr and qr+8
    const float* gi0 = g_GI + ((size_t)(s_base + qr)*Tt)*D3 + col0;
    const float* gi1 = g_GI + ((size_t)(s_base + qr + 8)*Tt)*D3 + col0;
    const float* x10 = g_X1 + ((size_t)(s_base + qr)*Tt)*Dd + col0;
    const float* x11 = g_X1 + ((size_t)(s_base + qr + 8)*Tt)*Dd + col0;
    float* ob = out + (size_t)b*Tt*Nn*Dd + (size_t)node0*Dd + col0;

    float h_old[4] = {0.f, 0.f, 0.f, 0.f};

    for (int t = 0; t < Tt; t++) {
        unsigned* Hc = (t & 1) ? Hb1 : Hb0;
        unsigned* Hn = (t & 1) ? Hb0 : Hb1;

        // gi + x1 loads (overlap with mma)
        float2 gr0 = *(const float2*)(gi0 + (size_t)t*D3);
        float2 gr1 = *(const float2*)(gi1 + (size_t)t*D3);
        float2 gz0 = *(const float2*)(gi0 + (size_t)t*D3 + 64);
        float2 gz1 = *(const float2*)(gi1 + (size_t)t*D3 + 64);
        float2 gn0 = *(const float2*)(gi0 + (size_t)t*D3 + 128);
        float2 gn1 = *(const float2*)(gi1 + (size_t)t*D3 + 128);
        float2 xa  = *(const float2*)(x10 + (size_t)t*Dd);
        float2 xb  = *(const float2*)(x11 + (size_t)t*Dd);

        // A fragments from current H
        unsigned a[8][4];
#pragma unroll
        for (int ks = 0; ks < 8; ks++) {
            a[ks][0] = Hc[qr*68 + ks*8 + kc];
            a[ks][1] = Hc[(qr+8)*68 + ks*8 + kc];
            a[ks][2] = Hc[qr*68 + ks*8 + kc + 4];
            a[ks][3] = Hc[(qr+8)*68 + ks*8 + kc + 4];
        }
        float cr[4] = {0.f,0.f,0.f,0.f}, cz[4] = {0.f,0.f,0.f,0.f}, cn[4] = {0.f,0.f,0.f,0.f};
#pragma unroll
        for (int ks = 0; ks < 8; ks++) {
            MMA_TF32(cr[0],cr[1],cr[2],cr[3], a[ks][0],a[ks][1],a[ks][2],a[ks][3], br_[ks][0],br_[ks][1]);
            MMA_TF32(cz[0],cz[1],cz[2],cz[3], a[ks][0],a[ks][1],a[ks][2],a[ks][3], bz_[ks][0],bz_[ks][1]);
            MMA_TF32(cn[0],cn[1],cn[2],cn[3], a[ks][0],a[ks][1],a[ks][2],a[ks][3], bn_[ks][0],bn_[ks][1]);
        }

        // gates (fragment: [0]=row qr,col0; [1]=row qr,col0+1; [2]=row qr+8,col0; [3]=row qr+8,col0+1)
        float r0 = siga(gr0.x + cr[0] + bhr.x);
        float r1 = siga(gr0.y + cr[1] + bhr.y);
        float r2 = siga(gr1.x + cr[2] + bhr.x);
        float r3 = siga(gr1.y + cr[3] + bhr.y);
        float z0 = siga(gz0.x + cz[0] + bhz.x);
        float z1 = siga(gz0.y + cz[1] + bhz.y);
        float z2 = siga(gz1.x + cz[2] + bhz.x);
        float z3 = siga(gz1.y + cz[3] + bhz.y);
        float n0 = tanha(gn0.x + r0*(cn[0] + bhn.x));
        float n1 = tanha(gn0.y + r1*(cn[1] + bhn.y));
        float n2 = tanha(gn1.x + r2*(cn[2] + bhn.x));
        float n3 = tanha(gn1.y + r3*(cn[3] + bhn.y));
        float h0 = (1.f - z0)*n0 + z0*h_old[0];
        float h1 = (1.f - z1)*n1 + z1*h_old[1];
        float h2v = (1.f - z2)*n2 + z2*h_old[2];
        float h3 = (1.f - z3)*n3 + z3*h_old[3];
        h_old[0] = h0; h_old[1] = h1; h_old[2] = h2v; h_old[3] = h3;

        float u0 = xa.x + h0, u1 = xa.y + h1, u2 = xb.x + h2v, u3 = xb.y + h3;

        // write next-H (tf32) and U (fp32)
        uint2 hp0; hp0.x = f2tf32(h0); hp0.y = f2tf32(h1);
        uint2 hp1; hp1.x = f2tf32(h2v); hp1.y = f2tf32(h3);
        *(uint2*)(Hn + qr*68 + col0)     = hp0;
        *(uint2*)(Hn + (qr+8)*68 + col0) = hp1;
        float2 up0; up0.x = u0; up0.y = u1;
        float2 up1; up1.x = u2; up1.y = u3;
        *(float2*)(U + qr*68 + col0)     = up0;
        *(float2*)(U + (qr+8)*68 + col0) = up1;
        __syncthreads();

        // LN stats: warp w reduces rows 2w, 2w+1
#pragma unroll
        for (int rr = 0; rr < 2; rr++) {
            int row = w*2 + rr;
            float v0 = U[row*68 + lane], v1 = U[row*68 + 32 + lane];
            float s = v0 + v1, q = v0*v0 + v1*v1;
#pragma unroll
            for (int off = 16; off > 0; off >>= 1) {
                s += __shfl_xor_sync(0xffffffff, s, off);
                q += __shfl_xor_sync(0xffffffff, q, off);
            }
            if (lane == 0) {
                float mean = s * (1.0f/64.0f);
                float var = q*(1.0f/64.0f) - mean*mean;
                mv[row*2]   = mean;
                mv[row*2+1] = rsqrtf(var + 1e-5f);
            }
        }
        __syncthreads();

        float m0 = mv[qr*2], rs0 = mv[qr*2+1];
        float m1 = mv[(qr+8)*2], rs1 = mv[(qr+8)*2+1];
        float2 o0, o1;
        o0.x = xa.x + (u0 - m0)*rs0*g2.x + b2.x;
        o0.y = xa.y + (u1 - m0)*rs0*g2.y + b2.y;
        o1.x = xb.x + (u2 - m1)*rs1*g2.x + b2.x;
        o1.y = xb.y + (u3 - m1)*rs1*g2.y + b2.y;
        *(float2*)(ob + (size_t)t*Nn*Dd + qr*Dd)     = o0;
        *(float2*)(ob + (size_t)t*Nn*Dd + (qr+8)*Dd) = o1;
    }
}

// ---------------- launcher ----------------
extern "C" void kernel_launch(void* const* d_in, const int* in_sizes, int n_in,
                              void* d_out, int out_size) {
    (void)in_sizes; (void)n_in; (void)out_size;
    const float* H_i  = (const float*)d_in[0];
    const float* H_j  = (const float*)d_in[1];
    const float* Wq   = (const float*)d_in[2];
    const float* bq   = (const float*)d_in[3];
    const float* Wk   = (const float*)d_in[4];
    const float* bk   = (const float*)d_in[5];
    const float* Wv   = (const float*)d_in[6];
    const float* bv   = (const float*)d_in[7];
    const float* lgam = (const float*)d_in[8];
    const float* ltau = (const float*)d_in[9];
    const float* e1   = (const float*)d_in[10];
    const float* e2   = (const float*)d_in[11];
    const float* Wg   = (const float*)d_in[12];
    const float* bg   = (const float*)d_in[13];
    const float* ln1g = (const float*)d_in[14];
    const float* ln1b = (const float*)d_in[15];
    const float* Wih  = (const float*)d_in[16];
    const float* Whh  = (const float*)d_in[17];
    const float* bih  = (const float*)d_in[18];
    const float* bhh  = (const float*)d_in[19];
    const float* ln2g = (const float*)d_in[20];
    const float* ln2b = (const float*)d_in[21];
    float* out = (float*)d_out;

    float *pQ, *pK, *pV, *pGI, *pX1;
    cudaGetSymbolAddress((void**)&pQ,  g_Q);
    cudaGetSymbolAddress((void**)&pK,  g_K);
    cudaGetSymbolAddress((void**)&pV,  g_V);
    cudaGetSymbolAddress((void**)&pGI, g_GI);
    cudaGetSymbolAddress((void**)&pX1, g_X1);

    const int LIN_SMEM  = (128+64)*68*4;  // 52224 B
    const int ATTN_SMEM = 25792 * 4;      // 103168 B
    const int GCN_SMEM  = 25920 * 4;      // 103680 B
    const int GRU_SMEM  = 16352 * 4;      // 65408 B
    cudaFuncSetAttribute(k_lin_tf32, cudaFuncAttributeMaxDynamicSharedMemorySize, LIN_SMEM);
    cudaFuncSetAttribute(k_attn, cudaFuncAttributeMaxDynamicSharedMemorySize, ATTN_SMEM);
    cudaFuncSetAttribute(k_gcn,  cudaFuncAttributeMaxDynamicSharedMemorySize, GCN_SMEM);
    cudaFuncSetAttribute(k_gru_tc, cudaFuncAttributeMaxDynamicSharedMemorySize, GRU_SMEM);

    k_adj<<<256, 256>>>(e1, e2);
    k_lin_tf32<<<dim3(MROWS/128, 1), 256, LIN_SMEM>>>(H_i, Wq, bq, pQ, 64);
    k_lin_tf32<<<dim3(MROWS/128, 1), 256, LIN_SMEM>>>(H_j, Wk, bk, pK, 64);
    k_lin_tf32<<<dim3(MROWS/128, 1), 256, LIN_SMEM>>>(H_j, Wv, bv, pV, 64);
    k_attn<<<Bb*Nn, 256, ATTN_SMEM>>>(lgam, ltau);
    k_gcn<<<Bb*Tt*2, 256, GCN_SMEM>>>(Wg, bg, ln1g, ln1b);
    k_lin_tf32<<<dim3(MROWS/128, 3), 256, LIN_SMEM>>>(pX1, Wih, bih, pGI, 192);
    k_gru_tc<<<Bb*Nn/16, 256, GRU_SMEM>>>(Whh, bhh, ln2g, ln2b, out);
}

// round 7
// speedup vs baseline: 3.0376x; 1.3220x over previous
#include <cuda_runtime.h>
#include <math.h>

#define Bb 8
#define Tt 128
#define Nn 256
#define Dd 64
#define D3 192
#define BTND 16777216   // 8*128*256*64

// ---------------- device scratch ----------------
__device__ float g_ALN[BTND];          // aligner output, [B,T,N,D]
__device__ float g_X1[BTND];           // post-ln1, [B,N,T,D]
__device__ unsigned g_ADPu[Nn*Nn];     // adjacency, tf32 bits, row-major [m][n]

__device__ __forceinline__ unsigned f2tf32(float f) {
    unsigned u;
    asm("cvt.rna.tf32.f32 %0, %1;" : "=r"(u) : "f"(f));
    return u;
}
__device__ __forceinline__ float tanha(float x) {
    float y;
    asm("tanh.approx.f32 %0, %1;" : "=f"(y) : "f"(x));
    return y;
}
__device__ __forceinline__ float siga(float x) { return 0.5f*tanha(0.5f*x) + 0.5f; }

#define MMA_TF32(c0,c1,c2,c3,a0,a1,a2,a3,b0,b1) \
    asm volatile("mma.sync.aligned.m16n8k8.row.col.f32.tf32.tf32.f32 " \
        "{%0,%1,%2,%3}, {%4,%5,%6,%7}, {%8,%9}, {%0,%1,%2,%3};" \
        : "+f"(c0), "+f"(c1), "+f"(c2), "+f"(c3) \
        : "r"(a0), "r"(a1), "r"(a2), "r"(a3), "r"(b0), "r"(b1))

// ---------------- adjacency ----------------
__global__ void k_adj(const float* __restrict__ e1, const float* __restrict__ e2) {
    int m = blockIdx.x;
    int n = threadIdx.x;            // 256 threads
    float a = 0.f;
#pragma unroll
    for (int k = 0; k < 32; k++) a = fmaf(e1[m*32 + k], e2[k*256 + n], a);
    a = fmaxf(a, 0.f);
    __shared__ float red[256];
    red[n] = a; __syncthreads();
    for (int s = 128; s > 0; s >>= 1) { if (n < s) red[n] = fmaxf(red[n], red[n+s]); __syncthreads(); }
    float mx = red[0]; __syncthreads();
    float e = expf(a - mx);
    red[n] = e; __syncthreads();
    for (int s = 128; s > 0; s >>= 1) { if (n < s) red[n] += red[n+s]; __syncthreads(); }
    g_ADPu[m*256 + n] = f2tf32(e / red[0]);
}

// shared fragment helpers -----------------------------------------------------
// 128x64x64 GEMM piece: warp computes rows [mrow, mrow+8], all 64 cols, from
// As [128][68] row-major tf32, Bs [64][68] row-major (out-col major) tf32.
__device__ __forceinline__ void gemm_c8(const unsigned* __restrict__ As,
                                        const unsigned* __restrict__ Bs,
                                        int mrow, int qr, int kc, float c[8][4]) {
    unsigned a[8][4];
#pragma unroll
    for (int ks = 0; ks < 8; ks++) {
        a[ks][0] = As[mrow*68 + ks*8 + kc];
        a[ks][1] = As[(mrow+8)*68 + ks*8 + kc];
        a[ks][2] = As[mrow*68 + ks*8 + kc + 4];
        a[ks][3] = As[(mrow+8)*68 + ks*8 + kc + 4];
    }
#pragma unroll
    for (int nt = 0; nt < 8; nt++) {
        c[nt][0]=0.f; c[nt][1]=0.f; c[nt][2]=0.f; c[nt][3]=0.f;
        int ncol = nt*8 + qr;
#pragma unroll
        for (int ks = 0; ks < 8; ks++) {
            unsigned b0 = Bs[ncol*68 + ks*8 + kc];
            unsigned b1 = Bs[ncol*68 + ks*8 + kc + 4];
            MMA_TF32(c[nt][0],c[nt][1],c[nt][2],c[nt][3],
                     a[ks][0],a[ks][1],a[ks][2],a[ks][3], b0,b1);
        }
    }
}

// ---------------- fused QKV + temporal attention ----------------
// smem words (170752 B total):
//  [0,16896): Hs [128][68] @0, Ws [64][68] @8704  (later Ps [128][132] fp32 / Pu tf32)
//  Qs @16896 [128][68], Ks @25600 [128][68], Vt @34304 [64][129], biasr @42560 [128]
__global__ void __launch_bounds__(256, 1) k_attn(
        const float* __restrict__ Hi, const float* __restrict__ Hj,
        const float* __restrict__ Wq, const float* __restrict__ bq,
        const float* __restrict__ Wk, const float* __restrict__ bk,
        const float* __restrict__ Wv, const float* __restrict__ bv,
        const float* __restrict__ lg, const float* __restrict__ lt) {
    extern __shared__ float sm[];
    unsigned* Hs = (unsigned*)sm;
    unsigned* Ws = Hs + 8704;
    float*    Ps = sm;
    unsigned* Pu = (unsigned*)sm;
    unsigned* Qs = Hs + 16896;
    unsigned* Ks = Hs + 25600;
    unsigned* Vt = Hs + 34304;
    float* biasr = sm + 42560;

    int tid = threadIdx.x;
    int bn = blockIdx.x;
    int b = bn >> 8, n = bn & 255;

    float gamma = fmaxf(expf(*lg), 0.01f);
    float tau   = fmaxf(expf(*lt), 0.01f);
    float scale = 1.0f / (8.0f * tau);
    if (tid < 128) biasr[tid] = logf(expf(-gamma * (float)tid * (1.0f/127.0f)) + 1e-8f);

    int w = tid >> 5, lane = tid & 31;
    int qr = lane >> 2, kc = lane & 3;
    int mrow = w*16 + qr;

    // ---- load H_j tile + Wk ----
    for (int idx = tid; idx < 2048; idx += 256) {
        int i = idx >> 4, c4 = idx & 15;
        float4 hv = *(const float4*)(Hj + ((size_t)(b*Tt + i)*Nn + n)*Dd + c4*4);
        uint4 pv; pv.x=f2tf32(hv.x); pv.y=f2tf32(hv.y); pv.z=f2tf32(hv.z); pv.w=f2tf32(hv.w);
        *(uint4*)(Hs + i*68 + c4*4) = pv;
    }
    for (int idx = tid; idx < 1024; idx += 256) {
        int r = idx >> 4, c4 = idx & 15;
        float4 wv = *(const float4*)(Wk + (size_t)r*64 + c4*4);
        uint4 pv; pv.x=f2tf32(wv.x); pv.y=f2tf32(wv.y); pv.z=f2tf32(wv.z); pv.w=f2tf32(wv.w);
        *(uint4*)(Ws + r*68 + c4*4) = pv;
    }
    __syncthreads();

    // ---- K = Hj @ Wk^T + bk -> Ks ----
    {
        float c[8][4];
        gemm_c8(Hs, Ws, mrow, qr, kc, c);
#pragma unroll
        for (int nt = 0; nt < 8; nt++) {
            int d = nt*8 + 2*kc;
            float bx = bk[d], by = bk[d+1];
            Ks[mrow*68 + d]       = f2tf32(c[nt][0] + bx);
            Ks[mrow*68 + d + 1]   = f2tf32(c[nt][1] + by);
            Ks[(mrow+8)*68 + d]     = f2tf32(c[nt][2] + bx);
            Ks[(mrow+8)*68 + d + 1] = f2tf32(c[nt][3] + by);
        }
    }
    __syncthreads();
    // ---- load Wv ----
    for (int idx = tid; idx < 1024; idx += 256) {
        int r = idx >> 4, c4 = idx & 15;
        float4 wv = *(const float4*)(Wv + (size_t)r*64 + c4*4);
        uint4 pv; pv.x=f2tf32(wv.x); pv.y=f2tf32(wv.y); pv.z=f2tf32(wv.z); pv.w=f2tf32(wv.w);
        *(uint4*)(Ws + r*68 + c4*4) = pv;
    }
    __syncthreads();
    // ---- V = Hj @ Wv^T + bv -> Vt (d-major) ----
    {
        float c[8][4];
        gemm_c8(Hs, Ws, mrow, qr, kc, c);
#pragma unroll
        for (int nt = 0; nt < 8; nt++) {
            int d = nt*8 + 2*kc;
            float bx = bv[d], by = bv[d+1];
            Vt[d*129 + mrow]         = f2tf32(c[nt][0] + bx);
            Vt[(d+1)*129 + mrow]     = f2tf32(c[nt][1] + by);
            Vt[d*129 + mrow + 8]     = f2tf32(c[nt][2] + bx);
            Vt[(d+1)*129 + mrow + 8] = f2tf32(c[nt][3] + by);
        }
    }
    __syncthreads();
    // ---- load H_i + Wq ----
    for (int idx = tid; idx < 2048; idx += 256) {
        int i = idx >> 4, c4 = idx & 15;
        float4 hv = *(const float4*)(Hi + ((size_t)(b*Tt + i)*Nn + n)*Dd + c4*4);
        uint4 pv; pv.x=f2tf32(hv.x); pv.y=f2tf32(hv.y); pv.z=f2tf32(hv.z); pv.w=f2tf32(hv.w);
        *(uint4*)(Hs + i*68 + c4*4) = pv;
    }
    for (int idx = tid; idx < 1024; idx += 256) {
        int r = idx >> 4, c4 = idx & 15;
        float4 wv = *(const float4*)(Wq + (size_t)r*64 + c4*4);
        uint4 pv; pv.x=f2tf32(wv.x); pv.y=f2tf32(wv.y); pv.z=f2tf32(wv.z); pv.w=f2tf32(wv.w);
        *(uint4*)(Ws + r*68 + c4*4) = pv;
    }
    __syncthreads();
    // ---- Q = Hi @ Wq^T + bq -> Qs ----
    {
        float c[8][4];
        gemm_c8(Hs, Ws, mrow, qr, kc, c);
#pragma unroll
        for (int nt = 0; nt < 8; nt++) {
            int d = nt*8 + 2*kc;
            float bx = bq[d], by = bq[d+1];
            Qs[mrow*68 + d]       = f2tf32(c[nt][0] + bx);
            Qs[mrow*68 + d + 1]   = f2tf32(c[nt][1] + by);
            Qs[(mrow+8)*68 + d]     = f2tf32(c[nt][2] + bx);
            Qs[(mrow+8)*68 + d + 1] = f2tf32(c[nt][3] + by);
        }
    }
    __syncthreads();   // Hs/Ws dead; Ps may overlay

    // ---- S = Q K^T ----
    unsigned a[8][4];
#pragma unroll
    for (int ks = 0; ks < 8; ks++) {
        a[ks][0] = Qs[mrow*68 + ks*8 + kc];
        a[ks][1] = Qs[(mrow+8)*68 + ks*8 + kc];
        a[ks][2] = Qs[mrow*68 + ks*8 + kc + 4];
        a[ks][3] = Qs[(mrow+8)*68 + ks*8 + kc + 4];
    }
    float c[16][4];
#pragma unroll
    for (int nt = 0; nt < 16; nt++) { c[nt][0]=0.f; c[nt][1]=0.f; c[nt][2]=0.f; c[nt][3]=0.f; }
#pragma unroll
    for (int nt = 0; nt < 16; nt++) {
        int ncol = nt*8 + qr;
#pragma unroll
        for (int ks = 0; ks < 8; ks++) {
            unsigned b0 = Ks[ncol*68 + ks*8 + kc];
            unsigned b1 = Ks[ncol*68 + ks*8 + kc + 4];
            MMA_TF32(c[nt][0],c[nt][1],c[nt][2],c[nt][3],
                     a[ks][0],a[ks][1],a[ks][2],a[ks][3], b0,b1);
        }
    }

    int i1 = mrow, i2 = mrow + 8;
#pragma unroll
    for (int nt = 0; nt < 16; nt++) {
        int j0 = nt*8 + 2*kc;
        int d10 = i1 - j0;     d10 = d10 < 0 ? -d10 : d10;
        int d11 = i1 - j0 - 1; d11 = d11 < 0 ? -d11 : d11;
        int d20 = i2 - j0;     d20 = d20 < 0 ? -d20 : d20;
        int d21 = i2 - j0 - 1; d21 = d21 < 0 ? -d21 : d21;
        Ps[i1*132 + j0]     = c[nt][0]*scale + biasr[d10];
        Ps[i1*132 + j0 + 1] = c[nt][1]*scale + biasr[d11];
        Ps[i2*132 + j0]     = c[nt][2]*scale + biasr[d20];
        Ps[i2*132 + j0 + 1] = c[nt][3]*scale + biasr[d21];
    }
    __syncthreads();

    // ---- softmax rows, write P tf32 ----
    for (int rr = 0; rr < 16; rr++) {
        int i = w*16 + rr;
        float v0 = Ps[i*132 + lane], v1 = Ps[i*132 + lane + 32],
              v2 = Ps[i*132 + lane + 64], v3 = Ps[i*132 + lane + 96];
        float mx = fmaxf(fmaxf(v0, v1), fmaxf(v2, v3));
#pragma unroll
        for (int off = 16; off > 0; off >>= 1) mx = fmaxf(mx, __shfl_xor_sync(0xffffffff, mx, off));
        float e0 = __expf(v0 - mx), e1 = __expf(v1 - mx), e2 = __expf(v2 - mx), e3 = __expf(v3 - mx);
        float su = (e0 + e1) + (e2 + e3);
#pragma unroll
        for (int off = 16; off > 0; off >>= 1) su += __shfl_xor_sync(0xffffffff, su, off);
        float inv = 1.0f / su;
        Pu[i*132 + lane]      = f2tf32(e0 * inv);
        Pu[i*132 + lane + 32] = f2tf32(e1 * inv);
        Pu[i*132 + lane + 64] = f2tf32(e2 * inv);
        Pu[i*132 + lane + 96] = f2tf32(e3 * inv);
    }
    __syncthreads();

    // ---- out = P @ V ----
    float c2[8][4];
#pragma unroll
    for (int nt = 0; nt < 8; nt++) { c2[nt][0]=0.f; c2[nt][1]=0.f; c2[nt][2]=0.f; c2[nt][3]=0.f; }
#pragma unroll
    for (int ks = 0; ks < 16; ks++) {
        unsigned a0 = Pu[mrow*132 + ks*8 + kc];
        unsigned a1 = Pu[(mrow+8)*132 + ks*8 + kc];
        unsigned a2 = Pu[mrow*132 + ks*8 + kc + 4];
        unsigned a3 = Pu[(mrow+8)*132 + ks*8 + kc + 4];
#pragma unroll
        for (int nt = 0; nt < 8; nt++) {
            unsigned b0 = Vt[(nt*8+qr)*129 + ks*8 + kc];
            unsigned b1 = Vt[(nt*8+qr)*129 + ks*8 + kc + 4];
            MMA_TF32(c2[nt][0],c2[nt][1],c2[nt][2],c2[nt][3], a0,a1,a2,a3, b0,b1);
        }
    }
#pragma unroll
    for (int nt = 0; nt < 8; nt++) {
        int d = nt*8 + 2*kc;
        float2 o0; o0.x = c2[nt][0]; o0.y = c2[nt][1];
        float2 o1; o1.x = c2[nt][2]; o1.y = c2[nt][3];
        *(float2*)(g_ALN + ((size_t)(b*Tt + mrow)*Nn + n)*Dd + d)     = o0;
        *(float2*)(g_ALN + ((size_t)(b*Tt + mrow + 8)*Nn + n)*Dd + d) = o1;
    }
}

// ---------------- GCN + residual + LN1, tf32 tensor core ----------------
__global__ void __launch_bounds__(256, 2) k_gcn(const float* __restrict__ Wg,
                                                const float* __restrict__ bg,
                                                const float* __restrict__ ln1g,
                                                const float* __restrict__ ln1b) {
    extern __shared__ float sg[];
    unsigned* As  = (unsigned*)sg;
    unsigned* Bs  = As + 8704;
    unsigned* Tmp = As + 12864;
    unsigned* Wgs = As + 21568;
    float* h2 = sg;   // overlays As

    int tid = threadIdx.x;
    int blk = blockIdx.x;
    int bt = blk >> 1, half = blk & 1;
    int m0g = half * 128;
    int b = bt >> 7, t = bt & 127;
    const float* Xbt = g_ALN + (size_t)bt * 16384;

    int w = tid >> 5, lane = tid & 31;
    int qr = lane >> 2, kc = lane & 3;
    int mrow = w*16 + qr;

    for (int idx = tid; idx < 1024; idx += 256) {
        int r = idx >> 4, c4 = idx & 15;
        float4 wv = *(const float4*)(Wg + (size_t)r*64 + c4*4);
        uint4 pv; pv.x = f2tf32(wv.x); pv.y = f2tf32(wv.y);
        pv.z = f2tf32(wv.z); pv.w = f2tf32(wv.w);
        *(uint4*)(Wgs + r*68 + c4*4) = pv;
    }

    float c1[8][4];
#pragma unroll
    for (int nt = 0; nt < 8; nt++) { c1[nt][0]=0.f; c1[nt][1]=0.f; c1[nt][2]=0.f; c1[nt][3]=0.f; }

    for (int ch = 0; ch < 4; ch++) {
        __syncthreads();
        for (int idx = tid; idx < 2048; idx += 256) {
            int r = idx >> 4, c4 = idx & 15;
            *(uint4*)(As + r*68 + c4*4) =
                *(const uint4*)(g_ADPu + (size_t)(m0g + r)*256 + ch*64 + c4*4);
        }
        for (int idx = tid; idx < 1024; idx += 256) {
            int nn = idx >> 4, c4 = idx & 15;
            float4 xv = *(const float4*)(Xbt + (size_t)(ch*64 + nn)*64 + c4*4);
            Bs[(c4*4+0)*65 + nn] = f2tf32(xv.x);
            Bs[(c4*4+1)*65 + nn] = f2tf32(xv.y);
            Bs[(c4*4+2)*65 + nn] = f2tf32(xv.z);
            Bs[(c4*4+3)*65 + nn] = f2tf32(xv.w);
        }
        __syncthreads();
#pragma unroll
        for (int ks = 0; ks < 8; ks++) {
            unsigned a0 = As[mrow*68 + ks*8 + kc];
            unsigned a1 = As[(mrow+8)*68 + ks*8 + kc];
            unsigned a2 = As[mrow*68 + ks*8 + kc + 4];
            unsigned a3 = As[(mrow+8)*68 + ks*8 + kc + 4];
#pragma unroll
            for (int nt = 0; nt < 8; nt++) {
                unsigned b0 = Bs[(nt*8+qr)*65 + ks*8 + kc];
                unsigned b1 = Bs[(nt*8+qr)*65 + ks*8 + kc + 4];
                MMA_TF32(c1[nt][0],c1[nt][1],c1[nt][2],c1[nt][3], a0,a1,a2,a3, b0,b1);
            }
        }
    }

#pragma unroll
    for (int nt = 0; nt < 8; nt++) {
        int d0 = nt*8 + 2*kc;
        Tmp[mrow*68 + d0]       = f2tf32(c1[nt][0]);
        Tmp[mrow*68 + d0 + 1]   = f2tf32(c1[nt][1]);
        Tmp[(mrow+8)*68 + d0]     = f2tf32(c1[nt][2]);
        Tmp[(mrow+8)*68 + d0 + 1] = f2tf32(c1[nt][3]);
    }
    __syncwarp();

    float c2[8][4];
#pragma unroll
    for (int nt = 0; nt < 8; nt++) { c2[nt][0]=0.f; c2[nt][1]=0.f; c2[nt][2]=0.f; c2[nt][3]=0.f; }
#pragma unroll
    for (int ks = 0; ks < 8; ks++) {
        unsigned a0 = Tmp[mrow*68 + ks*8 + kc];
        unsigned a1 = Tmp[(mrow+8)*68 + ks*8 + kc];
        unsigned a2 = Tmp[mrow*68 + ks*8 + kc + 4];
        unsigned a3 = Tmp[(mrow+8)*68 + ks*8 + kc + 4];
#pragma unroll
        for (int nt = 0; nt < 8; nt++) {
            unsigned b0 = Wgs[(nt*8+qr)*68 + ks*8 + kc];
            unsigned b1 = Wgs[(nt*8+qr)*68 + ks*8 + kc + 4];
            MMA_TF32(c2[nt][0],c2[nt][1],c2[nt][2],c2[nt][3], a0,a1,a2,a3, b0,b1);
        }
    }
    __syncthreads();

#pragma unroll
    for (int nt = 0; nt < 8; nt++) {
        int e0 = nt*8 + 2*kc;
        float bx = bg[e0], by = bg[e0+1];
        h2[mrow*68 + e0]       = fmaxf(c2[nt][0] + bx, 0.f);
        h2[mrow*68 + e0 + 1]   = fmaxf(c2[nt][1] + by, 0.f);
        h2[(mrow+8)*68 + e0]     = fmaxf(c2[nt][2] + bx, 0.f);
        h2[(mrow+8)*68 + e0 + 1] = fmaxf(c2[nt][3] + by, 0.f);
    }
    __syncthreads();

    float gg0 = ln1g[lane], gg1 = ln1g[lane+32];
    float bb0 = ln1b[lane], bb1 = ln1b[lane+32];
    for (int mm = 0; mm < 16; mm++) {
        int m = w*16 + mm;
        const float* xr = Xbt + (size_t)(m0g + m)*64;
        float u0 = xr[lane]      + h2[m*68 + lane];
        float u1 = xr[lane + 32] + h2[m*68 + lane + 32];
        float su = u0 + u1;
#pragma unroll
        for (int off = 16; off > 0; off >>= 1) su += __shfl_xor_sync(0xffffffff, su, off);
        float mean = su * (1.0f/64.0f);
        float dd0 = u0 - mean, dd1 = u1 - mean;
        float q = dd0*dd0 + dd1*dd1;
#pragma unroll
        for (int off = 16; off > 0; off >>= 1) q += __shfl_xor_sync(0xffffffff, q, off);
        float rs = rsqrtf(q*(1.0f/64.0f) + 1e-5f);
        size_t o = ((size_t)(b*Nn + m0g + m)*Tt + t)*Dd;
        g_X1[o + lane]      = dd0*rs*gg0 + bb0;
        g_X1[o + lane + 32] = dd1*rs*gg1 + bb1;
    }
}

// ---------------- tensor-core GRU with fused gi GEMM + LN2 + out ----------------
// smem words: Whs [192][68] @0, Wis [192][68] @13056, Hb0 @26112, Hb1 @27200,
// X1s @28288 (1088), U fp32 @29376 (1088), mv @30464 (32). Total 30496 w = 121984 B.
__global__ void __launch_bounds__(256) k_gru_tc(const float* __restrict__ Whh,
                                                const float* __restrict__ bhh,
                                                const float* __restrict__ Wih,
                                                const float* __restrict__ bih,
                                                const float* __restrict__ ln2g,
                                                const float* __restrict__ ln2b,
                                                float* __restrict__ out) {
    extern __shared__ unsigned su_[];
    unsigned* Whs = su_;
    unsigned* Wis = su_ + 13056;
    unsigned* Hb0 = su_ + 26112;
    unsigned* Hb1 = su_ + 27200;
    unsigned* X1s = su_ + 28288;
    float* U  = (float*)(su_ + 29376);
    float* mv = (float*)(su_ + 30464);

    int tid = threadIdx.x;
    int w = tid >> 5, lane = tid & 31;
    int qr = lane >> 2, kc = lane & 3;
    int s_base = blockIdx.x * 16;
    int b = s_base >> 8;
    int node0 = s_base & 255;

    for (int idx = tid; idx < 3072; idx += 256) {
        int r = idx >> 4, c4 = idx & 15;
        float4 wv = *(const float4*)(Whh + (size_t)r*64 + c4*4);
        uint4 pv; pv.x = f2tf32(wv.x); pv.y = f2tf32(wv.y);
        pv.z = f2tf32(wv.z); pv.w = f2tf32(wv.w);
        *(uint4*)(Whs + r*68 + c4*4) = pv;
        float4 iv = *(const float4*)(Wih + (size_t)r*64 + c4*4);
        uint4 qv; qv.x = f2tf32(iv.x); qv.y = f2tf32(iv.y);
        qv.z = f2tf32(iv.z); qv.w = f2tf32(iv.w);
        *(uint4*)(Wis + r*68 + c4*4) = qv;
    }
    for (int idx = tid; idx < 1088; idx += 256) Hb0[idx] = 0;
    __syncthreads();

    // hoist Whh B fragments
    unsigned br_[8][2], bz_[8][2], bn_[8][2];
#pragma unroll
    for (int ks = 0; ks < 8; ks++) {
        int nr = (0*64 + w*8 + qr)*68 + ks*8 + kc;
        int nz = (1*64 + w*8 + qr)*68 + ks*8 + kc;
        int nn = (2*64 + w*8 + qr)*68 + ks*8 + kc;
        br_[ks][0] = Whs[nr]; br_[ks][1] = Whs[nr + 4];
        bz_[ks][0] = Whs[nz]; bz_[ks][1] = Whs[nz + 4];
        bn_[ks][0] = Whs[nn]; bn_[ks][1] = Whs[nn + 4];
    }
    int col0 = w*8 + 2*kc;
    float2 bhr = *(const float2*)(bhh + col0);
    float2 bhz = *(const float2*)(bhh + 64 + col0);
    float2 bhn = *(const float2*)(bhh + 128 + col0);
    float2 bir = *(const float2*)(bih + col0);
    float2 biz = *(const float2*)(bih + 64 + col0);
    float2 bin_ = *(const float2*)(bih + 128 + col0);
    float2 g2 = *(const float2*)(ln2g + col0);
    float2 b2 = *(const float2*)(ln2b + col0);

    const float* x10 = g_X1 + ((size_t)(s_base + qr)*Tt)*Dd + col0;
    const float* x11 = g_X1 + ((size_t)(s_base + qr + 8)*Tt)*Dd + col0;
    float* ob = out + (size_t)b*Tt*Nn*Dd + (size_t)node0*Dd + col0;

    float h_old[4] = {0.f, 0.f, 0.f, 0.f};

    for (int t = 0; t < Tt; t++) {
        unsigned* Hc = (t & 1) ? Hb1 : Hb0;
        unsigned* Hn = (t & 1) ? Hb0 : Hb1;

        float2 xa = *(const float2*)(x10 + (size_t)t*Dd);
        float2 xb = *(const float2*)(x11 + (size_t)t*Dd);
        // stage x1 tile (tf32)
        uint2 xp0; xp0.x = f2tf32(xa.x); xp0.y = f2tf32(xa.y);
        uint2 xp1; xp1.x = f2tf32(xb.x); xp1.y = f2tf32(xb.y);
        *(uint2*)(X1s + qr*68 + col0)     = xp0;
        *(uint2*)(X1s + (qr+8)*68 + col0) = xp1;
        __syncthreads();

        // gi = x1 @ Wih^T (A from X1s, B from Wis smem)
        float gr_[4] = {0.f,0.f,0.f,0.f}, gz_[4] = {0.f,0.f,0.f,0.f}, gn_[4] = {0.f,0.f,0.f,0.f};
        {
            unsigned ax[8][4];
#pragma unroll
            for (int ks = 0; ks < 8; ks++) {
                ax[ks][0] = X1s[qr*68 + ks*8 + kc];
                ax[ks][1] = X1s[(qr+8)*68 + ks*8 + kc];
                ax[ks][2] = X1s[qr*68 + ks*8 + kc + 4];
                ax[ks][3] = X1s[(qr+8)*68 + ks*8 + kc + 4];
            }
#pragma unroll
            for (int ks = 0; ks < 8; ks++) {
                int nr = (0*64 + w*8 + qr)*68 + ks*8 + kc;
                int nz = (1*64 + w*8 + qr)*68 + ks*8 + kc;
                int nn = (2*64 + w*8 + qr)*68 + ks*8 + kc;
                MMA_TF32(gr_[0],gr_[1],gr_[2],gr_[3], ax[ks][0],ax[ks][1],ax[ks][2],ax[ks][3], Wis[nr], Wis[nr+4]);
                MMA_TF32(gz_[0],gz_[1],gz_[2],gz_[3], ax[ks][0],ax[ks][1],ax[ks][2],ax[ks][3], Wis[nz], Wis[nz+4]);
                MMA_TF32(gn_[0],gn_[1],gn_[2],gn_[3], ax[ks][0],ax[ks][1],ax[ks][2],ax[ks][3], Wis[nn], Wis[nn+4]);
            }
        }
        // hh = h @ Whh^T (A from Hc, hoisted B)
        float cr[4] = {0.f,0.f,0.f,0.f}, cz[4] = {0.f,0.f,0.f,0.f}, cn[4] = {0.f,0.f,0.f,0.f};
        {
            unsigned a[8][4];
#pragma unroll
            for (int ks = 0; ks < 8; ks++) {
                a[ks][0] = Hc[qr*68 + ks*8 + kc];
                a[ks][1] = Hc[(qr+8)*68 + ks*8 + kc];
                a[ks][2] = Hc[qr*68 + ks*8 + kc + 4];
                a[ks][3] = Hc[(qr+8)*68 + ks*8 + kc + 4];
            }
#pragma unroll
            for (int ks = 0; ks < 8; ks++) {
                MMA_TF32(cr[0],cr[1],cr[2],cr[3], a[ks][0],a[ks][1],a[ks][2],a[ks][3], br_[ks][0],br_[ks][1]);
                MMA_TF32(cz[0],cz[1],cz[2],cz[3], a[ks][0],a[ks][1],a[ks][2],a[ks][3], bz_[ks][0],bz_[ks][1]);
                MMA_TF32(cn[0],cn[1],cn[2],cn[3], a[ks][0],a[ks][1],a[ks][2],a[ks][3], bn_[ks][0],bn_[ks][1]);
            }
        }

        float r0 = siga(gr_[0] + bir.x + cr[0] + bhr.x);
        float r1 = siga(gr_[1] + bir.y + cr[1] + bhr.y);
        float r2 = siga(gr_[2] + bir.x + cr[2] + bhr.x);
        float r3 = siga(gr_[3] + bir.y + cr[3] + bhr.y);
        float z0 = siga(gz_[0] + biz.x + cz[0] + bhz.x);
        float z1 = siga(gz_[1] + biz.y + cz[1] + bhz.y);
        float z2 = siga(gz_[2] + biz.x + cz[2] + bhz.x);
        float z3 = siga(gz_[3] + biz.y + cz[3] + bhz.y);
        float n0 = tanha(gn_[0] + bin_.x + r0*(cn[0] + bhn.x));
        float n1 = tanha(gn_[1] + bin_.y + r1*(cn[1] + bhn.y));
        float n2 = tanha(gn_[2] + bin_.x + r2*(cn[2] + bhn.x));
        float n3 = tanha(gn_[3] + bin_.y + r3*(cn[3] + bhn.y));
        float h0 = (1.f - z0)*n0 + z0*h_old[0];
        float h1 = (1.f - z1)*n1 + z1*h_old[1];
        float h2v = (1.f - z2)*n2 + z2*h_old[2];
        float h3 = (1.f - z3)*n3 + z3*h_old[3];
        h_old[0] = h0; h_old[1] = h1; h_old[2] = h2v; h_old[3] = h3;

        float u0 = xa.x + h0, u1 = xa.y + h1, u2 = xb.x + h2v, u3 = xb.y + h3;

        uint2 hp0; hp0.x = f2tf32(h0); hp0.y = f2tf32(h1);
        uint2 hp1; hp1.x = f2tf32(h2v); hp1.y = f2tf32(h3);
        *(uint2*)(Hn + qr*68 + col0)     = hp0;
        *(uint2*)(Hn + (qr+8)*68 + col0) = hp1;
        float2 up0; up0.x = u0; up0.y = u1;
        float2 up1; up1.x = u2; up1.y = u3;
        *(float2*)(U + qr*68 + col0)     = up0;
        *(float2*)(U + (qr+8)*68 + col0) = up1;
        __syncthreads();

#pragma unroll
        for (int rr = 0; rr < 2; rr++) {
            int row = w*2 + rr;
            float v0 = U[row*68 + lane], v1 = U[row*68 + 32 + lane];
            float s = v0 + v1, q = v0*v0 + v1*v1;
#pragma unroll
            for (int off = 16; off > 0; off >>= 1) {
                s += __shfl_xor_sync(0xffffffff, s, off);
                q += __shfl_xor_sync(0xffffffff, q, off);
            }
            if (lane == 0) {
                float mean = s * (1.0f/64.0f);
                float var = q*(1.0f/64.0f) - mean*mean;
                mv[row*2]   = mean;
                mv[row*2+1] = rsqrtf(var + 1e-5f);
            }
        }
        __syncthreads();

        float m0 = mv[qr*2], rs0 = mv[qr*2+1];
        float m1 = mv[(qr+8)*2], rs1 = mv[(qr+8)*2+1];
        float2 o0, o1;
        o0.x = xa.x + (u0 - m0)*rs0*g2.x + b2.x;
        o0.y = xa.y + (u1 - m0)*rs0*g2.y + b2.y;
        o1.x = xb.x + (u2 - m1)*rs1*g2.x + b2.x;
        o1.y = xb.y + (u3 - m1)*rs1*g2.y + b2.y;
        *(float2*)(ob + (size_t)t*Nn*Dd + qr*Dd)     = o0;
        *(float2*)(ob + (size_t)t*Nn*Dd + (qr+8)*Dd) = o1;
    }
}

// ---------------- launcher ----------------
extern "C" void kernel_launch(void* const* d_in, const int* in_sizes, int n_in,
                              void* d_out, int out_size) {
    (void)in_sizes; (void)n_in; (void)out_size;
    const float* H_i  = (const float*)d_in[0];
    const float* H_j  = (const float*)d_in[1];
    const float* Wq   = (const float*)d_in[2];
    const float* bq   = (const float*)d_in[3];
    const float* Wk   = (const float*)d_in[4];
    const float* bk   = (const float*)d_in[5];
    const float* Wv   = (const float*)d_in[6];
    const float* bv   = (const float*)d_in[7];
    const float* lgam = (const float*)d_in[8];
    const float* ltau = (const float*)d_in[9];
    const float* e1   = (const float*)d_in[10];
    const float* e2   = (const float*)d_in[11];
    const float* Wg   = (const float*)d_in[12];
    const float* bg   = (const float*)d_in[13];
    const float* ln1g = (const float*)d_in[14];
    const float* ln1b = (const float*)d_in[15];
    const float* Wih  = (const float*)d_in[16];
    const float* Whh  = (const float*)d_in[17];
    const float* bih  = (const float*)d_in[18];
    const float* bhh  = (const float*)d_in[19];
    const float* ln2g = (const float*)d_in[20];
    const float* ln2b = (const float*)d_in[21];
    float* out = (float*)d_out;

    const int ATTN_SMEM = 42688 * 4;   // 170752 B
    const int GCN_SMEM  = 25920 * 4;   // 103680 B
    const int GRU_SMEM  = 30496 * 4;   // 121984 B
    cudaFuncSetAttribute(k_attn, cudaFuncAttributeMaxDynamicSharedMemorySize, ATTN_SMEM);
    cudaFuncSetAttribute(k_gcn,  cudaFuncAttributeMaxDynamicSharedMemorySize, GCN_SMEM);
    cudaFuncSetAttribute(k_gru_tc, cudaFuncAttributeMaxDynamicSharedMemorySize, GRU_SMEM);

    k_adj<<<256, 256>>>(e1, e2);
    k_attn<<<Bb*Nn, 256, ATTN_SMEM>>>(H_i, H_j, Wq, bq, Wk, bk, Wv, bv, lgam, ltau);
    k_gcn<<<Bb*Tt*2, 256, GCN_SMEM>>>(Wg, bg, ln1g, ln1b);
    k_gru_tc<<<Bb*Nn/16, 256, GRU_SMEM>>>(Whh, bhh, Wih, bih, ln2g, ln2b, out);
}

// round 8
// speedup vs baseline: 3.1662x; 1.0423x over previous
#include <cuda_runtime.h>
#include <math.h>

#define Bb 8
#define Tt 128
#define Nn 256
#define Dd 64
#define D3 192
#define BTND 16777216   // 8*128*256*64

// ---------------- device scratch ----------------
__device__ float g_ALN[BTND];          // aligner output, [B,T,N,D]
__device__ float g_X1[BTND];           // post-ln1, [B,N,T,D]
__device__ unsigned g_ADPu[Nn*Nn];     // adjacency, tf32 bits, row-major [m][n]

__device__ __forceinline__ unsigned f2tf32(float f) {
    unsigned u;
    asm("cvt.rna.tf32.f32 %0, %1;" : "=r"(u) : "f"(f));
    return u;
}
__device__ __forceinline__ float tanha(float x) {
    float y;
    asm("tanh.approx.f32 %0, %1;" : "=f"(y) : "f"(x));
    return y;
}
__device__ __forceinline__ float siga(float x) { return 0.5f*tanha(0.5f*x) + 0.5f; }

#define MMA_TF32(c0,c1,c2,c3,a0,a1,a2,a3,b0,b1) \
    asm volatile("mma.sync.aligned.m16n8k8.row.col.f32.tf32.tf32.f32 " \
        "{%0,%1,%2,%3}, {%4,%5,%6,%7}, {%8,%9}, {%0,%1,%2,%3};" \
        : "+f"(c0), "+f"(c1), "+f"(c2), "+f"(c3) \
        : "r"(a0), "r"(a1), "r"(a2), "r"(a3), "r"(b0), "r"(b1))

// ---------------- adjacency ----------------
__global__ void k_adj(const float* __restrict__ e1, const float* __restrict__ e2) {
    int m = blockIdx.x;
    int n = threadIdx.x;            // 256 threads
    float a = 0.f;
#pragma unroll
    for (int k = 0; k < 32; k++) a = fmaf(e1[m*32 + k], e2[k*256 + n], a);
    a = fmaxf(a, 0.f);
    __shared__ float red[256];
    red[n] = a; __syncthreads();
    for (int s = 128; s > 0; s >>= 1) { if (n < s) red[n] = fmaxf(red[n], red[n+s]); __syncthreads(); }
    float mx = red[0]; __syncthreads();
    float e = expf(a - mx);
    red[n] = e; __syncthreads();
    for (int s = 128; s > 0; s >>= 1) { if (n < s) red[n] += red[n+s]; __syncthreads(); }
    g_ADPu[m*256 + n] = f2tf32(e / red[0]);
}

// shared fragment helper ------------------------------------------------------
__device__ __forceinline__ void gemm_c8(const unsigned* __restrict__ As,
                                        const unsigned* __restrict__ Bs,
                                        int mrow, int qr, int kc, float c[8][4]) {
    unsigned a[8][4];
#pragma unroll
    for (int ks = 0; ks < 8; ks++) {
        a[ks][0] = As[mrow*68 + ks*8 + kc];
        a[ks][1] = As[(mrow+8)*68 + ks*8 + kc];
        a[ks][2] = As[mrow*68 + ks*8 + kc + 4];
        a[ks][3] = As[(mrow+8)*68 + ks*8 + kc + 4];
    }
#pragma unroll
    for (int nt = 0; nt < 8; nt++) {
        c[nt][0]=0.f; c[nt][1]=0.f; c[nt][2]=0.f; c[nt][3]=0.f;
        int ncol = nt*8 + qr;
#pragma unroll
        for (int ks = 0; ks < 8; ks++) {
            unsigned b0 = Bs[ncol*68 + ks*8 + kc];
            unsigned b1 = Bs[ncol*68 + ks*8 + kc + 4];
            MMA_TF32(c[nt][0],c[nt][1],c[nt][2],c[nt][3],
                     a[ks][0],a[ks][1],a[ks][2],a[ks][3], b0,b1);
        }
    }
}

// ---------------- fused QKV + temporal attention ----------------
__global__ void __launch_bounds__(256, 1) k_attn(
        const float* __restrict__ Hi, const float* __restrict__ Hj,
        const float* __restrict__ Wq, const float* __restrict__ bq,
        const float* __restrict__ Wk, const float* __restrict__ bk,
        const float* __restrict__ Wv, const float* __restrict__ bv,
        const float* __restrict__ lg, const float* __restrict__ lt) {
    extern __shared__ float sm[];
    unsigned* Hs = (unsigned*)sm;
    unsigned* Ws = Hs + 8704;
    float*    Ps = sm;
    unsigned* Pu = (unsigned*)sm;
    unsigned* Qs = Hs + 16896;
    unsigned* Ks = Hs + 25600;
    unsigned* Vt = Hs + 34304;
    float* biasr = sm + 42560;

    int tid = threadIdx.x;
    int bn = blockIdx.x;
    int b = bn >> 8, n = bn & 255;

    float gamma = fmaxf(expf(*lg), 0.01f);
    float tau   = fmaxf(expf(*lt), 0.01f);
    float scale = 1.0f / (8.0f * tau);
    if (tid < 128) biasr[tid] = logf(expf(-gamma * (float)tid * (1.0f/127.0f)) + 1e-8f);

    int w = tid >> 5, lane = tid & 31;
    int qr = lane >> 2, kc = lane & 3;
    int mrow = w*16 + qr;

    for (int idx = tid; idx < 2048; idx += 256) {
        int i = idx >> 4, c4 = idx & 15;
        float4 hv = *(const float4*)(Hj + ((size_t)(b*Tt + i)*Nn + n)*Dd + c4*4);
        uint4 pv; pv.x=f2tf32(hv.x); pv.y=f2tf32(hv.y); pv.z=f2tf32(hv.z); pv.w=f2tf32(hv.w);
        *(uint4*)(Hs + i*68 + c4*4) = pv;
    }
    for (int idx = tid; idx < 1024; idx += 256) {
        int r = idx >> 4, c4 = idx & 15;
        float4 wv = *(const float4*)(Wk + (size_t)r*64 + c4*4);
        uint4 pv; pv.x=f2tf32(wv.x); pv.y=f2tf32(wv.y); pv.z=f2tf32(wv.z); pv.w=f2tf32(wv.w);
        *(uint4*)(Ws + r*68 + c4*4) = pv;
    }
    __syncthreads();

    {
        float c[8][4];
        gemm_c8(Hs, Ws, mrow, qr, kc, c);
#pragma unroll
        for (int nt = 0; nt < 8; nt++) {
            int d = nt*8 + 2*kc;
            float bx = bk[d], by = bk[d+1];
            Ks[mrow*68 + d]       = f2tf32(c[nt][0] + bx);
            Ks[mrow*68 + d + 1]   = f2tf32(c[nt][1] + by);
            Ks[(mrow+8)*68 + d]     = f2tf32(c[nt][2] + bx);
            Ks[(mrow+8)*68 + d + 1] = f2tf32(c[nt][3] + by);
        }
    }
    __syncthreads();
    for (int idx = tid; idx < 1024; idx += 256) {
        int r = idx >> 4, c4 = idx & 15;
        float4 wv = *(const float4*)(Wv + (size_t)r*64 + c4*4);
        uint4 pv; pv.x=f2tf32(wv.x); pv.y=f2tf32(wv.y); pv.z=f2tf32(wv.z); pv.w=f2tf32(wv.w);
        *(uint4*)(Ws + r*68 + c4*4) = pv;
    }
    __syncthreads();
    {
        float c[8][4];
        gemm_c8(Hs, Ws, mrow, qr, kc, c);
#pragma unroll
        for (int nt = 0; nt < 8; nt++) {
            int d = nt*8 + 2*kc;
            float bx = bv[d], by = bv[d+1];
            Vt[d*129 + mrow]         = f2tf32(c[nt][0] + bx);
            Vt[(d+1)*129 + mrow]     = f2tf32(c[nt][1] + by);
            Vt[d*129 + mrow + 8]     = f2tf32(c[nt][2] + bx);
            Vt[(d+1)*129 + mrow + 8] = f2tf32(c[nt][3] + by);
        }
    }
    __syncthreads();
    for (int idx = tid; idx < 2048; idx += 256) {
        int i = idx >> 4, c4 = idx & 15;
        float4 hv = *(const float4*)(Hi + ((size_t)(b*Tt + i)*Nn + n)*Dd + c4*4);
        uint4 pv; pv.x=f2tf32(hv.x); pv.y=f2tf32(hv.y); pv.z=f2tf32(hv.z); pv.w=f2tf32(hv.w);
        *(uint4*)(Hs + i*68 + c4*4) = pv;
    }
    for (int idx = tid; idx < 1024; idx += 256) {
        int r = idx >> 4, c4 = idx & 15;
        float4 wv = *(const float4*)(Wq + (size_t)r*64 + c4*4);
        uint4 pv; pv.x=f2tf32(wv.x); pv.y=f2tf32(wv.y); pv.z=f2tf32(wv.z); pv.w=f2tf32(wv.w);
        *(uint4*)(Ws + r*68 + c4*4) = pv;
    }
    __syncthreads();
    {
        float c[8][4];
        gemm_c8(Hs, Ws, mrow, qr, kc, c);
#pragma unroll
        for (int nt = 0; nt < 8; nt++) {
            int d = nt*8 + 2*kc;
            float bx = bq[d], by = bq[d+1];
            Qs[mrow*68 + d]       = f2tf32(c[nt][0] + bx);
            Qs[mrow*68 + d + 1]   = f2tf32(c[nt][1] + by);
            Qs[(mrow+8)*68 + d]     = f2tf32(c[nt][2] + bx);
            Qs[(mrow+8)*68 + d + 1] = f2tf32(c[nt][3] + by);
        }
    }
    __syncthreads();

    unsigned a[8][4];
#pragma unroll
    for (int ks = 0; ks < 8; ks++) {
        a[ks][0] = Qs[mrow*68 + ks*8 + kc];
        a[ks][1] = Qs[(mrow+8)*68 + ks*8 + kc];
        a[ks][2] = Qs[mrow*68 + ks*8 + kc + 4];
        a[ks][3] = Qs[(mrow+8)*68 + ks*8 + kc + 4];
    }
    float c[16][4];
#pragma unroll
    for (int nt = 0; nt < 16; nt++) { c[nt][0]=0.f; c[nt][1]=0.f; c[nt][2]=0.f; c[nt][3]=0.f; }
#pragma unroll
    for (int nt = 0; nt < 16; nt++) {
        int ncol = nt*8 + qr;
#pragma unroll
        for (int ks = 0; ks < 8; ks++) {
            unsigned b0 = Ks[ncol*68 + ks*8 + kc];
            unsigned b1 = Ks[ncol*68 + ks*8 + kc + 4];
            MMA_TF32(c[nt][0],c[nt][1],c[nt][2],c[nt][3],
                     a[ks][0],a[ks][1],a[ks][2],a[ks][3], b0,b1);
        }
    }

    int i1 = mrow, i2 = mrow + 8;
#pragma unroll
    for (int nt = 0; nt < 16; nt++) {
        int j0 = nt*8 + 2*kc;
        int d10 = i1 - j0;     d10 = d10 < 0 ? -d10 : d10;
        int d11 = i1 - j0 - 1; d11 = d11 < 0 ? -d11 : d11;
        int d20 = i2 - j0;     d20 = d20 < 0 ? -d20 : d20;
        int d21 = i2 - j0 - 1; d21 = d21 < 0 ? -d21 : d21;
        Ps[i1*132 + j0]     = c[nt][0]*scale + biasr[d10];
        Ps[i1*132 + j0 + 1] = c[nt][1]*scale + biasr[d11];
        Ps[i2*132 + j0]     = c[nt][2]*scale + biasr[d20];
        Ps[i2*132 + j0 + 1] = c[nt][3]*scale + biasr[d21];
    }
    __syncthreads();

    for (int rr = 0; rr < 16; rr++) {
        int i = w*16 + rr;
        float v0 = Ps[i*132 + lane], v1 = Ps[i*132 + lane + 32],
              v2 = Ps[i*132 + lane + 64], v3 = Ps[i*132 + lane + 96];
        float mx = fmaxf(fmaxf(v0, v1), fmaxf(v2, v3));
#pragma unroll
        for (int off = 16; off > 0; off >>= 1) mx = fmaxf(mx, __shfl_xor_sync(0xffffffff, mx, off));
        float e0 = __expf(v0 - mx), e1 = __expf(v1 - mx), e2 = __expf(v2 - mx), e3 = __expf(v3 - mx);
        float su = (e0 + e1) + (e2 + e3);
#pragma unroll
        for (int off = 16; off > 0; off >>= 1) su += __shfl_xor_sync(0xffffffff, su, off);
        float inv = 1.0f / su;
        Pu[i*132 + lane]      = f2tf32(e0 * inv);
        Pu[i*132 + lane + 32] = f2tf32(e1 * inv);
        Pu[i*132 + lane + 64] = f2tf32(e2 * inv);
        Pu[i*132 + lane + 96] = f2tf32(e3 * inv);
    }
    __syncthreads();

    float c2[8][4];
#pragma unroll
    for (int nt = 0; nt < 8; nt++) { c2[nt][0]=0.f; c2[nt][1]=0.f; c2[nt][2]=0.f; c2[nt][3]=0.f; }
#pragma unroll
    for (int ks = 0; ks < 16; ks++) {
        unsigned a0 = Pu[mrow*132 + ks*8 + kc];
        unsigned a1 = Pu[(mrow+8)*132 + ks*8 + kc];
        unsigned a2 = Pu[mrow*132 + ks*8 + kc + 4];
        unsigned a3 = Pu[(mrow+8)*132 + ks*8 + kc + 4];
#pragma unroll
        for (int nt = 0; nt < 8; nt++) {
            unsigned b0 = Vt[(nt*8+qr)*129 + ks*8 + kc];
            unsigned b1 = Vt[(nt*8+qr)*129 + ks*8 + kc + 4];
            MMA_TF32(c2[nt][0],c2[nt][1],c2[nt][2],c2[nt][3], a0,a1,a2,a3, b0,b1);
        }
    }
#pragma unroll
    for (int nt = 0; nt < 8; nt++) {
        int d = nt*8 + 2*kc;
        float2 o0; o0.x = c2[nt][0]; o0.y = c2[nt][1];
        float2 o1; o1.x = c2[nt][2]; o1.y = c2[nt][3];
        *(float2*)(g_ALN + ((size_t)(b*Tt + mrow)*Nn + n)*Dd + d)     = o0;
        *(float2*)(g_ALN + ((size_t)(b*Tt + mrow + 8)*Nn + n)*Dd + d) = o1;
    }
}

// ---------------- GCN + residual + LN1, tf32 tensor core ----------------
__global__ void __launch_bounds__(256, 2) k_gcn(const float* __restrict__ Wg,
                                                const float* __restrict__ bg,
                                                const float* __restrict__ ln1g,
                                                const float* __restrict__ ln1b) {
    extern __shared__ float sg[];
    unsigned* As  = (unsigned*)sg;
    unsigned* Bs  = As + 8704;
    unsigned* Tmp = As + 12864;
    unsigned* Wgs = As + 21568;
    float* h2 = sg;   // overlays As

    int tid = threadIdx.x;
    int blk = blockIdx.x;
    int bt = blk >> 1, half = blk & 1;
    int m0g = half * 128;
    int b = bt >> 7, t = bt & 127;
    const float* Xbt = g_ALN + (size_t)bt * 16384;

    int w = tid >> 5, lane = tid & 31;
    int qr = lane >> 2, kc = lane & 3;
    int mrow = w*16 + qr;

    for (int idx = tid; idx < 1024; idx += 256) {
        int r = idx >> 4, c4 = idx & 15;
        float4 wv = *(const float4*)(Wg + (size_t)r*64 + c4*4);
        uint4 pv; pv.x = f2tf32(wv.x); pv.y = f2tf32(wv.y);
        pv.z = f2tf32(wv.z); pv.w = f2tf32(wv.w);
        *(uint4*)(Wgs + r*68 + c4*4) = pv;
    }

    float c1[8][4];
#pragma unroll
    for (int nt = 0; nt < 8; nt++) { c1[nt][0]=0.f; c1[nt][1]=0.f; c1[nt][2]=0.f; c1[nt][3]=0.f; }

    for (int ch = 0; ch < 4; ch++) {
        __syncthreads();
        for (int idx = tid; idx < 2048; idx += 256) {
            int r = idx >> 4, c4 = idx & 15;
            *(uint4*)(As + r*68 + c4*4) =
                *(const uint4*)(g_ADPu + (size_t)(m0g + r)*256 + ch*64 + c4*4);
        }
        for (int idx = tid; idx < 1024; idx += 256) {
            int nn = idx >> 4, c4 = idx & 15;
            float4 xv = *(const float4*)(Xbt + (size_t)(ch*64 + nn)*64 + c4*4);
            Bs[(c4*4+0)*65 + nn] = f2tf32(xv.x);
            Bs[(c4*4+1)*65 + nn] = f2tf32(xv.y);
            Bs[(c4*4+2)*65 + nn] = f2tf32(xv.z);
            Bs[(c4*4+3)*65 + nn] = f2tf32(xv.w);
        }
        __syncthreads();
#pragma unroll
        for (int ks = 0; ks < 8; ks++) {
            unsigned a0 = As[mrow*68 + ks*8 + kc];
            unsigned a1 = As[(mrow+8)*68 + ks*8 + kc];
            unsigned a2 = As[mrow*68 + ks*8 + kc + 4];
            unsigned a3 = As[(mrow+8)*68 + ks*8 + kc + 4];
#pragma unroll
            for (int nt = 0; nt < 8; nt++) {
                unsigned b0 = Bs[(nt*8+qr)*65 + ks*8 + kc];
                unsigned b1 = Bs[(nt*8+qr)*65 + ks*8 + kc + 4];
                MMA_TF32(c1[nt][0],c1[nt][1],c1[nt][2],c1[nt][3], a0,a1,a2,a3, b0,b1);
            }
        }
    }

#pragma unroll
    for (int nt = 0; nt < 8; nt++) {
        int d0 = nt*8 + 2*kc;
        Tmp[mrow*68 + d0]       = f2tf32(c1[nt][0]);
        Tmp[mrow*68 + d0 + 1]   = f2tf32(c1[nt][1]);
        Tmp[(mrow+8)*68 + d0]     = f2tf32(c1[nt][2]);
        Tmp[(mrow+8)*68 + d0 + 1] = f2tf32(c1[nt][3]);
    }
    __syncwarp();

    float c2[8][4];
#pragma unroll
    for (int nt = 0; nt < 8; nt++) { c2[nt][0]=0.f; c2[nt][1]=0.f; c2[nt][2]=0.f; c2[nt][3]=0.f; }
#pragma unroll
    for (int ks = 0; ks < 8; ks++) {
        unsigned a0 = Tmp[mrow*68 + ks*8 + kc];
        unsigned a1 = Tmp[(mrow+8)*68 + ks*8 + kc];
        unsigned a2 = Tmp[mrow*68 + ks*8 + kc + 4];
        unsigned a3 = Tmp[(mrow+8)*68 + ks*8 + kc + 4];
#pragma unroll
        for (int nt = 0; nt < 8; nt++) {
            unsigned b0 = Wgs[(nt*8+qr)*68 + ks*8 + kc];
            unsigned b1 = Wgs[(nt*8+qr)*68 + ks*8 + kc + 4];
            MMA_TF32(c2[nt][0],c2[nt][1],c2[nt][2],c2[nt][3], a0,a1,a2,a3, b0,b1);
        }
    }
    __syncthreads();

#pragma unroll
    for (int nt = 0; nt < 8; nt++) {
        int e0 = nt*8 + 2*kc;
        float bx = bg[e0], by = bg[e0+1];
        h2[mrow*68 + e0]       = fmaxf(c2[nt][0] + bx, 0.f);
        h2[mrow*68 + e0 + 1]   = fmaxf(c2[nt][1] + by, 0.f);
        h2[(mrow+8)*68 + e0]     = fmaxf(c2[nt][2] + bx, 0.f);
        h2[(mrow+8)*68 + e0 + 1] = fmaxf(c2[nt][3] + by, 0.f);
    }
    __syncthreads();

    float gg0 = ln1g[lane], gg1 = ln1g[lane+32];
    float bb0 = ln1b[lane], bb1 = ln1b[lane+32];
    for (int mm = 0; mm < 16; mm++) {
        int m = w*16 + mm;
        const float* xr = Xbt + (size_t)(m0g + m)*64;
        float u0 = xr[lane]      + h2[m*68 + lane];
        float u1 = xr[lane + 32] + h2[m*68 + lane + 32];
        float su = u0 + u1;
#pragma unroll
        for (int off = 16; off > 0; off >>= 1) su += __shfl_xor_sync(0xffffffff, su, off);
        float mean = su * (1.0f/64.0f);
        float dd0 = u0 - mean, dd1 = u1 - mean;
        float q = dd0*dd0 + dd1*dd1;
#pragma unroll
        for (int off = 16; off > 0; off >>= 1) q += __shfl_xor_sync(0xffffffff, q, off);
        float rs = rsqrtf(q*(1.0f/64.0f) + 1e-5f);
        size_t o = ((size_t)(b*Nn + m0g + m)*Tt + t)*Dd;
        g_X1[o + lane]      = dd0*rs*gg0 + bb0;
        g_X1[o + lane + 32] = dd1*rs*gg1 + bb1;
    }
}

// ---------------- tensor-core GRU: chunked gi precompute, 1 barrier/step ----------------
// smem (words): staging Whs[192][68]@0, Wis[192][68]@13056 (26112 total).
// After fragment hoist, region reused: X1s[4][16][68]@0 (4352), Hb0@4352, Hb1@5440,
// U0 fp32 @6528, U1 @7616 (each 1088). smem = 26112 w = 104448 B.
__global__ void __launch_bounds__(256) k_gru_tc(const float* __restrict__ Whh,
                                                const float* __restrict__ bhh,
                                                const float* __restrict__ Wih,
                                                const float* __restrict__ bih,
                                                const float* __restrict__ ln2g,
                                                const float* __restrict__ ln2b,
                                                float* __restrict__ out) {
    extern __shared__ unsigned su_[];
    unsigned* Whs = su_;
    unsigned* Wis = su_ + 13056;
    unsigned* X1s = su_;
    unsigned* Hb0 = su_ + 4352;
    unsigned* Hb1 = su_ + 5440;
    float* U0 = (float*)(su_ + 6528);
    float* U1 = (float*)(su_ + 7616);

    int tid = threadIdx.x;
    int w = tid >> 5, lane = tid & 31;
    int qr = lane >> 2, kc = lane & 3;
    int s_base = blockIdx.x * 16;
    int b = s_base >> 8;
    int node0 = s_base & 255;

    // stage weights
    for (int idx = tid; idx < 3072; idx += 256) {
        int r = idx >> 4, c4 = idx & 15;
        float4 wv = *(const float4*)(Whh + (size_t)r*64 + c4*4);
        uint4 pv; pv.x = f2tf32(wv.x); pv.y = f2tf32(wv.y);
        pv.z = f2tf32(wv.z); pv.w = f2tf32(wv.w);
        *(uint4*)(Whs + r*68 + c4*4) = pv;
        float4 iv = *(const float4*)(Wih + (size_t)r*64 + c4*4);
        uint4 qv; qv.x = f2tf32(iv.x); qv.y = f2tf32(iv.y);
        qv.z = f2tf32(iv.z); qv.w = f2tf32(iv.w);
        *(uint4*)(Wis + r*68 + c4*4) = qv;
    }
    __syncthreads();

    // hoist ALL weight fragments to registers
    unsigned br_[8][2], bz_[8][2], bn_[8][2];
    unsigned wr_[8][2], wz_[8][2], wn_[8][2];
#pragma unroll
    for (int ks = 0; ks < 8; ks++) {
        int nr = (0*64 + w*8 + qr)*68 + ks*8 + kc;
        int nz = (1*64 + w*8 + qr)*68 + ks*8 + kc;
        int nn = (2*64 + w*8 + qr)*68 + ks*8 + kc;
        br_[ks][0] = Whs[nr]; br_[ks][1] = Whs[nr + 4];
        bz_[ks][0] = Whs[nz]; bz_[ks][1] = Whs[nz + 4];
        bn_[ks][0] = Whs[nn]; bn_[ks][1] = Whs[nn + 4];
        wr_[ks][0] = Wis[nr]; wr_[ks][1] = Wis[nr + 4];
        wz_[ks][0] = Wis[nz]; wz_[ks][1] = Wis[nz + 4];
        wn_[ks][0] = Wis[nn]; wn_[ks][1] = Wis[nn + 4];
    }
    __syncthreads();   // staging region now reusable

    for (int idx = tid; idx < 1088; idx += 256) Hb0[idx] = 0;
    // covered by chunk-top barrier below

    int col0 = w*8 + 2*kc;
    float2 bhr = *(const float2*)(bhh + col0);
    float2 bhz = *(const float2*)(bhh + 64 + col0);
    float2 bhn = *(const float2*)(bhh + 128 + col0);
    float2 bir = *(const float2*)(bih + col0);
    float2 biz = *(const float2*)(bih + 64 + col0);
    float2 bin_ = *(const float2*)(bih + 128 + col0);
    float g2a = ln2g[lane], g2b = ln2g[lane+32];
    float b2a = ln2b[lane], b2b = ln2b[lane+32];

    const float* x10 = g_X1 + ((size_t)(s_base + qr)*Tt)*Dd + col0;
    const float* x11 = g_X1 + ((size_t)(s_base + qr + 8)*Tt)*Dd + col0;

    float h_old[4] = {0.f, 0.f, 0.f, 0.f};

    for (int tc = 0; tc < Tt; tc += 4) {
        // stage x1 chunk (tf32)
        for (int idx = tid; idx < 4096; idx += 256) {
            int s = idx >> 10, rem = idx & 1023, row = rem >> 6, col = rem & 63;
            float v = g_X1[(size_t)(s_base + row)*Tt*Dd + (size_t)(tc + s)*Dd + col];
            X1s[s*1088 + row*68 + col] = f2tf32(v);
        }
        __syncthreads();

        // gi for 4 steps -> registers
        float gr_[4][4], gz_[4][4], gn_[4][4];
#pragma unroll
        for (int s = 0; s < 4; s++) {
            const unsigned* Xc = X1s + s*1088;
            unsigned ax[8][4];
#pragma unroll
            for (int ks = 0; ks < 8; ks++) {
                ax[ks][0] = Xc[qr*68 + ks*8 + kc];
                ax[ks][1] = Xc[(qr+8)*68 + ks*8 + kc];
                ax[ks][2] = Xc[qr*68 + ks*8 + kc + 4];
                ax[ks][3] = Xc[(qr+8)*68 + ks*8 + kc + 4];
            }
            gr_[s][0]=0.f; gr_[s][1]=0.f; gr_[s][2]=0.f; gr_[s][3]=0.f;
            gz_[s][0]=0.f; gz_[s][1]=0.f; gz_[s][2]=0.f; gz_[s][3]=0.f;
            gn_[s][0]=0.f; gn_[s][1]=0.f; gn_[s][2]=0.f; gn_[s][3]=0.f;
#pragma unroll
            for (int ks = 0; ks < 8; ks++) {
                MMA_TF32(gr_[s][0],gr_[s][1],gr_[s][2],gr_[s][3], ax[ks][0],ax[ks][1],ax[ks][2],ax[ks][3], wr_[ks][0],wr_[ks][1]);
                MMA_TF32(gz_[s][0],gz_[s][1],gz_[s][2],gz_[s][3], ax[ks][0],ax[ks][1],ax[ks][2],ax[ks][3], wz_[ks][0],wz_[ks][1]);
                MMA_TF32(gn_[s][0],gn_[s][1],gn_[s][2],gn_[s][3], ax[ks][0],ax[ks][1],ax[ks][2],ax[ks][3], wn_[ks][0],wn_[ks][1]);
            }
        }

        // serial 4 steps, 1 barrier each
#pragma unroll
        for (int s = 0; s < 4; s++) {
            int t = tc + s;
            unsigned* Hc = (t & 1) ? Hb1 : Hb0;
            unsigned* Hn = (t & 1) ? Hb0 : Hb1;
            float* Un = (t & 1) ? U1 : U0;

            float2 xa = *(const float2*)(x10 + (size_t)t*Dd);
            float2 xb = *(const float2*)(x11 + (size_t)t*Dd);

            float cr[4] = {0.f,0.f,0.f,0.f}, cz[4] = {0.f,0.f,0.f,0.f}, cn[4] = {0.f,0.f,0.f,0.f};
            {
                unsigned a[8][4];
#pragma unroll
                for (int ks = 0; ks < 8; ks++) {
                    a[ks][0] = Hc[qr*68 + ks*8 + kc];
                    a[ks][1] = Hc[(qr+8)*68 + ks*8 + kc];
                    a[ks][2] = Hc[qr*68 + ks*8 + kc + 4];
                    a[ks][3] = Hc[(qr+8)*68 + ks*8 + kc + 4];
                }
#pragma unroll
                for (int ks = 0; ks < 8; ks++) {
                    MMA_TF32(cr[0],cr[1],cr[2],cr[3], a[ks][0],a[ks][1],a[ks][2],a[ks][3], br_[ks][0],br_[ks][1]);
                    MMA_TF32(cz[0],cz[1],cz[2],cz[3], a[ks][0],a[ks][1],a[ks][2],a[ks][3], bz_[ks][0],bz_[ks][1]);
                    MMA_TF32(cn[0],cn[1],cn[2],cn[3], a[ks][0],a[ks][1],a[ks][2],a[ks][3], bn_[ks][0],bn_[ks][1]);
                }
            }

            float r0 = siga(gr_[s][0] + bir.x + cr[0] + bhr.x);
            float r1 = siga(gr_[s][1] + bir.y + cr[1] + bhr.y);
            float r2 = siga(gr_[s][2] + bir.x + cr[2] + bhr.x);
            float r3 = siga(gr_[s][3] + bir.y + cr[3] + bhr.y);
            float z0 = siga(gz_[s][0] + biz.x + cz[0] + bhz.x);
            float z1 = siga(gz_[s][1] + biz.y + cz[1] + bhz.y);
            float z2 = siga(gz_[s][2] + biz.x + cz[2] + bhz.x);
            float z3 = siga(gz_[s][3] + biz.y + cz[3] + bhz.y);
            float n0 = tanha(gn_[s][0] + bin_.x + r0*(cn[0] + bhn.x));
            float n1 = tanha(gn_[s][1] + bin_.y + r1*(cn[1] + bhn.y));
            float n2 = tanha(gn_[s][2] + bin_.x + r2*(cn[2] + bhn.x));
            float n3 = tanha(gn_[s][3] + bin_.y + r3*(cn[3] + bhn.y));
            float h0 = (1.f - z0)*n0 + z0*h_old[0];
            float h1 = (1.f - z1)*n1 + z1*h_old[1];
            float h2v = (1.f - z2)*n2 + z2*h_old[2];
            float h3 = (1.f - z3)*n3 + z3*h_old[3];
            h_old[0] = h0; h_old[1] = h1; h_old[2] = h2v; h_old[3] = h3;

            uint2 hp0; hp0.x = f2tf32(h0); hp0.y = f2tf32(h1);
            uint2 hp1; hp1.x = f2tf32(h2v); hp1.y = f2tf32(h3);
            *(uint2*)(Hn + qr*68 + col0)     = hp0;
            *(uint2*)(Hn + (qr+8)*68 + col0) = hp1;
            float2 up0; up0.x = xa.x + h0; up0.y = xa.y + h1;
            float2 up1; up1.x = xb.x + h2v; up1.y = xb.y + h3;
            *(float2*)(Un + qr*68 + col0)     = up0;
            *(float2*)(Un + (qr+8)*68 + col0) = up1;
            __syncthreads();

            // LN + residual + output: warp w owns rows 2w, 2w+1
#pragma unroll
            for (int rr = 0; rr < 2; rr++) {
                int row = w*2 + rr;
                float v0 = Un[row*68 + lane], v1 = Un[row*68 + lane + 32];
                float sv = v0 + v1, qv = v0*v0 + v1*v1;
#pragma unroll
                for (int off = 16; off > 0; off >>= 1) {
                    sv += __shfl_xor_sync(0xffffffff, sv, off);
                    qv += __shfl_xor_sync(0xffffffff, qv, off);
                }
                float mean = sv * (1.0f/64.0f);
                float var = qv*(1.0f/64.0f) - mean*mean;
                float rs = rsqrtf(var + 1e-5f);
                const float* xr = g_X1 + (size_t)(s_base + row)*Tt*Dd + (size_t)t*Dd;
                float x0v = xr[lane], x1v = xr[lane + 32];
                size_t oo = (size_t)b*Tt*Nn*Dd + (size_t)t*Nn*Dd + (size_t)(node0 + row)*Dd;
                out[oo + lane]      = x0v + (v0 - mean)*rs*g2a + b2a;
                out[oo + lane + 32] = x1v + (v1 - mean)*rs*g2b + b2b;
            }
        }
    }
}

// ---------------- launcher ----------------
extern "C" void kernel_launch(void* const* d_in, const int* in_sizes, int n_in,
                              void* d_out, int out_size) {
    (void)in_sizes; (void)n_in; (void)out_size;
    const float* H_i  = (const float*)d_in[0];
    const float* H_j  = (const float*)d_in[1];
    const float* Wq   = (const float*)d_in[2];
    const float* bq   = (const float*)d_in[3];
    const float* Wk   = (const float*)d_in[4];
    const float* bk   = (const float*)d_in[5];
    const float* Wv   = (const float*)d_in[6];
    const float* bv   = (const float*)d_in[7];
    const float* lgam = (const float*)d_in[8];
    const float* ltau = (const float*)d_in[9];
    const float* e1   = (const float*)d_in[10];
    const float* e2   = (const float*)d_in[11];
    const float* Wg   = (const float*)d_in[12];
    const float* bg   = (const float*)d_in[13];
    const float* ln1g = (const float*)d_in[14];
    const float* ln1b = (const float*)d_in[15];
    const float* Wih  = (const float*)d_in[16];
    const float* Whh  = (const float*)d_in[17];
    const float* bih  = (const float*)d_in[18];
    const float* bhh  = (const float*)d_in[19];
    const float* ln2g = (const float*)d_in[20];
    const float* ln2b = (const float*)d_in[21];
    float* out = (float*)d_out;

    const int ATTN_SMEM = 42688 * 4;   // 170752 B
    const int GCN_SMEM  = 25920 * 4;   // 103680 B
    const int GRU_SMEM  = 26112 * 4;   // 104448 B
    cudaFuncSetAttribute(k_attn, cudaFuncAttributeMaxDynamicSharedMemorySize, ATTN_SMEM);
    cudaFuncSetAttribute(k_gcn,  cudaFuncAttributeMaxDynamicSharedMemorySize, GCN_SMEM);
    cudaFuncSetAttribute(k_gru_tc, cudaFuncAttributeMaxDynamicSharedMemorySize, GRU_SMEM);

    k_adj<<<256, 256>>>(e1, e2);
    k_attn<<<Bb*Nn, 256, ATTN_SMEM>>>(H_i, H_j, Wq, bq, Wk, bk, Wv, bv, lgam, ltau);
    k_gcn<<<Bb*Tt*2, 256, GCN_SMEM>>>(Wg, bg, ln1g, ln1b);
    k_gru_tc<<<Bb*Nn/16, 256, GRU_SMEM>>>(Whh, bhh, Wih, bih, ln2g, ln2b, out);
}

// round 9
// speedup vs baseline: 3.2521x; 1.0271x over previous
#include <cuda_runtime.h>
#include <math.h>

#define Bb 8
#define Tt 128
#define Nn 256
#define Dd 64
#define D3 192
#define BTND 16777216   // 8*128*256*64

// ---------------- device scratch ----------------
__device__ float g_ALN[BTND];          // aligner output, [B,T,N,D]
__device__ float g_X1[BTND];           // post-ln1, [B,N,T,D]
__device__ unsigned g_ADPu[Nn*Nn];     // adjacency, tf32 bits, row-major [m][n]

__device__ __forceinline__ unsigned f2tf32(float f) {
    unsigned u;
    asm("cvt.rna.tf32.f32 %0, %1;" : "=r"(u) : "f"(f));
    return u;
}
__device__ __forceinline__ float tanha(float x) {
    float y;
    asm("tanh.approx.f32 %0, %1;" : "=f"(y) : "f"(x));
    return y;
}
__device__ __forceinline__ float siga(float x) { return 0.5f*tanha(0.5f*x) + 0.5f; }

#define MMA_TF32(c0,c1,c2,c3,a0,a1,a2,a3,b0,b1) \
    asm volatile("mma.sync.aligned.m16n8k8.row.col.f32.tf32.tf32.f32 " \
        "{%0,%1,%2,%3}, {%4,%5,%6,%7}, {%8,%9}, {%0,%1,%2,%3};" \
        : "+f"(c0), "+f"(c1), "+f"(c2), "+f"(c3) \
        : "r"(a0), "r"(a1), "r"(a2), "r"(a3), "r"(b0), "r"(b1))

// ---------------- adjacency ----------------
__global__ void k_adj(const float* __restrict__ e1, const float* __restrict__ e2) {
    int m = blockIdx.x;
    int n = threadIdx.x;            // 256 threads
    float a = 0.f;
#pragma unroll
    for (int k = 0; k < 32; k++) a = fmaf(e1[m*32 + k], e2[k*256 + n], a);
    a = fmaxf(a, 0.f);
    __shared__ float red[256];
    red[n] = a; __syncthreads();
    for (int s = 128; s > 0; s >>= 1) { if (n < s) red[n] = fmaxf(red[n], red[n+s]); __syncthreads(); }
    float mx = red[0]; __syncthreads();
    float e = expf(a - mx);
    red[n] = e; __syncthreads();
    for (int s = 128; s > 0; s >>= 1) { if (n < s) red[n] += red[n+s]; __syncthreads(); }
    g_ADPu[m*256 + n] = f2tf32(e / red[0]);
}

// shared fragment helper ------------------------------------------------------
__device__ __forceinline__ void gemm_c8(const unsigned* __restrict__ As,
                                        const unsigned* __restrict__ Bs,
                                        int mrow, int qr, int kc, float c[8][4]) {
    unsigned a[8][4];
#pragma unroll
    for (int ks = 0; ks < 8; ks++) {
        a[ks][0] = As[mrow*68 + ks*8 + kc];
        a[ks][1] = As[(mrow+8)*68 + ks*8 + kc];
        a[ks][2] = As[mrow*68 + ks*8 + kc + 4];
        a[ks][3] = As[(mrow+8)*68 + ks*8 + kc + 4];
    }
#pragma unroll
    for (int nt = 0; nt < 8; nt++) {
        c[nt][0]=0.f; c[nt][1]=0.f; c[nt][2]=0.f; c[nt][3]=0.f;
        int ncol = nt*8 + qr;
#pragma unroll
        for (int ks = 0; ks < 8; ks++) {
            unsigned b0 = Bs[ncol*68 + ks*8 + kc];
            unsigned b1 = Bs[ncol*68 + ks*8 + kc + 4];
            MMA_TF32(c[nt][0],c[nt][1],c[nt][2],c[nt][3],
                     a[ks][0],a[ks][1],a[ks][2],a[ks][3], b0,b1);
        }
    }
}

// ---------------- fused QKV + temporal attention ----------------
__global__ void __launch_bounds__(256, 1) k_attn(
        const float* __restrict__ Hi, const float* __restrict__ Hj,
        const float* __restrict__ Wq, const float* __restrict__ bq,
        const float* __restrict__ Wk, const float* __restrict__ bk,
        const float* __restrict__ Wv, const float* __restrict__ bv,
        const float* __restrict__ lg, const float* __restrict__ lt) {
    extern __shared__ float sm[];
    unsigned* Hs = (unsigned*)sm;
    unsigned* Ws = Hs + 8704;
    float*    Ps = sm;
    unsigned* Pu = (unsigned*)sm;
    unsigned* Qs = Hs + 16896;
    unsigned* Ks = Hs + 25600;
    unsigned* Vt = Hs + 34304;
    float* biasr = sm + 42560;

    int tid = threadIdx.x;
    int bn = blockIdx.x;
    int b = bn >> 8, n = bn & 255;

    float gamma = fmaxf(expf(*lg), 0.01f);
    float tau   = fmaxf(expf(*lt), 0.01f);
    float scale = 1.0f / (8.0f * tau);
    if (tid < 128) biasr[tid] = logf(expf(-gamma * (float)tid * (1.0f/127.0f)) + 1e-8f);

    int w = tid >> 5, lane = tid & 31;
    int qr = lane >> 2, kc = lane & 3;
    int mrow = w*16 + qr;

    for (int idx = tid; idx < 2048; idx += 256) {
        int i = idx >> 4, c4 = idx & 15;
        float4 hv = *(const float4*)(Hj + ((size_t)(b*Tt + i)*Nn + n)*Dd + c4*4);
        uint4 pv; pv.x=f2tf32(hv.x); pv.y=f2tf32(hv.y); pv.z=f2tf32(hv.z); pv.w=f2tf32(hv.w);
        *(uint4*)(Hs + i*68 + c4*4) = pv;
    }
    for (int idx = tid; idx < 1024; idx += 256) {
        int r = idx >> 4, c4 = idx & 15;
        float4 wv = *(const float4*)(Wk + (size_t)r*64 + c4*4);
        uint4 pv; pv.x=f2tf32(wv.x); pv.y=f2tf32(wv.y); pv.z=f2tf32(wv.z); pv.w=f2tf32(wv.w);
        *(uint4*)(Ws + r*68 + c4*4) = pv;
    }
    __syncthreads();

    {
        float c[8][4];
        gemm_c8(Hs, Ws, mrow, qr, kc, c);
#pragma unroll
        for (int nt = 0; nt < 8; nt++) {
            int d = nt*8 + 2*kc;
            float bx = bk[d], by = bk[d+1];
            Ks[mrow*68 + d]       = f2tf32(c[nt][0] + bx);
            Ks[mrow*68 + d + 1]   = f2tf32(c[nt][1] + by);
            Ks[(mrow+8)*68 + d]     = f2tf32(c[nt][2] + bx);
            Ks[(mrow+8)*68 + d + 1] = f2tf32(c[nt][3] + by);
        }
    }
    __syncthreads();
    for (int idx = tid; idx < 1024; idx += 256) {
        int r = idx >> 4, c4 = idx & 15;
        float4 wv = *(const float4*)(Wv + (size_t)r*64 + c4*4);
        uint4 pv; pv.x=f2tf32(wv.x); pv.y=f2tf32(wv.y); pv.z=f2tf32(wv.z); pv.w=f2tf32(wv.w);
        *(uint4*)(Ws + r*68 + c4*4) = pv;
    }
    __syncthreads();
    {
        float c[8][4];
        gemm_c8(Hs, Ws, mrow, qr, kc, c);
#pragma unroll
        for (int nt = 0; nt < 8; nt++) {
            int d = nt*8 + 2*kc;
            float bx = bv[d], by = bv[d+1];
            Vt[d*129 + mrow]         = f2tf32(c[nt][0] + bx);
            Vt[(d+1)*129 + mrow]     = f2tf32(c[nt][1] + by);
            Vt[d*129 + mrow + 8]     = f2tf32(c[nt][2] + bx);
            Vt[(d+1)*129 + mrow + 8] = f2tf32(c[nt][3] + by);
        }
    }
    __syncthreads();
    for (int idx = tid; idx < 2048; idx += 256) {
        int i = idx >> 4, c4 = idx & 15;
        float4 hv = *(const float4*)(Hi + ((size_t)(b*Tt + i)*Nn + n)*Dd + c4*4);
        uint4 pv; pv.x=f2tf32(hv.x); pv.y=f2tf32(hv.y); pv.z=f2tf32(hv.z); pv.w=f2tf32(hv.w);
        *(uint4*)(Hs + i*68 + c4*4) = pv;
    }
    for (int idx = tid; idx < 1024; idx += 256) {
        int r = idx >> 4, c4 = idx & 15;
        float4 wv = *(const float4*)(Wq + (size_t)r*64 + c4*4);
        uint4 pv; pv.x=f2tf32(wv.x); pv.y=f2tf32(wv.y); pv.z=f2tf32(wv.z); pv.w=f2tf32(wv.w);
        *(uint4*)(Ws + r*68 + c4*4) = pv;
    }
    __syncthreads();
    {
        float c[8][4];
        gemm_c8(Hs, Ws, mrow, qr, kc, c);
#pragma unroll
        for (int nt = 0; nt < 8; nt++) {
            int d = nt*8 + 2*kc;
            float bx = bq[d], by = bq[d+1];
            Qs[mrow*68 + d]       = f2tf32(c[nt][0] + bx);
            Qs[mrow*68 + d + 1]   = f2tf32(c[nt][1] + by);
            Qs[(mrow+8)*68 + d]     = f2tf32(c[nt][2] + bx);
            Qs[(mrow+8)*68 + d + 1] = f2tf32(c[nt][3] + by);
        }
    }
    __syncthreads();

    unsigned a[8][4];
#pragma unroll
    for (int ks = 0; ks < 8; ks++) {
        a[ks][0] = Qs[mrow*68 + ks*8 + kc];
        a[ks][1] = Qs[(mrow+8)*68 + ks*8 + kc];
        a[ks][2] = Qs[mrow*68 + ks*8 + kc + 4];
        a[ks][3] = Qs[(mrow+8)*68 + ks*8 + kc + 4];
    }
    float c[16][4];
#pragma unroll
    for (int nt = 0; nt < 16; nt++) { c[nt][0]=0.f; c[nt][1]=0.f; c[nt][2]=0.f; c[nt][3]=0.f; }
#pragma unroll
    for (int nt = 0; nt < 16; nt++) {
        int ncol = nt*8 + qr;
#pragma unroll
        for (int ks = 0; ks < 8; ks++) {
            unsigned b0 = Ks[ncol*68 + ks*8 + kc];
            unsigned b1 = Ks[ncol*68 + ks*8 + kc + 4];
            MMA_TF32(c[nt][0],c[nt][1],c[nt][2],c[nt][3],
                     a[ks][0],a[ks][1],a[ks][2],a[ks][3], b0,b1);
        }
    }

    int i1 = mrow, i2 = mrow + 8;
#pragma unroll
    for (int nt = 0; nt < 16; nt++) {
        int j0 = nt*8 + 2*kc;
        int d10 = i1 - j0;     d10 = d10 < 0 ? -d10 : d10;
        int d11 = i1 - j0 - 1; d11 = d11 < 0 ? -d11 : d11;
        int d20 = i2 - j0;     d20 = d20 < 0 ? -d20 : d20;
        int d21 = i2 - j0 - 1; d21 = d21 < 0 ? -d21 : d21;
        Ps[i1*132 + j0]     = c[nt][0]*scale + biasr[d10];
        Ps[i1*132 + j0 + 1] = c[nt][1]*scale + biasr[d11];
        Ps[i2*132 + j0]     = c[nt][2]*scale + biasr[d20];
        Ps[i2*132 + j0 + 1] = c[nt][3]*scale + biasr[d21];
    }
    __syncthreads();

    for (int rr = 0; rr < 16; rr++) {
        int i = w*16 + rr;
        float v0 = Ps[i*132 + lane], v1 = Ps[i*132 + lane + 32],
              v2 = Ps[i*132 + lane + 64], v3 = Ps[i*132 + lane + 96];
        float mx = fmaxf(fmaxf(v0, v1), fmaxf(v2, v3));
#pragma unroll
        for (int off = 16; off > 0; off >>= 1) mx = fmaxf(mx, __shfl_xor_sync(0xffffffff, mx, off));
        float e0 = __expf(v0 - mx), e1 = __expf(v1 - mx), e2 = __expf(v2 - mx), e3 = __expf(v3 - mx);
        float su = (e0 + e1) + (e2 + e3);
#pragma unroll
        for (int off = 16; off > 0; off >>= 1) su += __shfl_xor_sync(0xffffffff, su, off);
        float inv = 1.0f / su;
        Pu[i*132 + lane]      = f2tf32(e0 * inv);
        Pu[i*132 + lane + 32] = f2tf32(e1 * inv);
        Pu[i*132 + lane + 64] = f2tf32(e2 * inv);
        Pu[i*132 + lane + 96] = f2tf32(e3 * inv);
    }
    __syncthreads();

    float c2[8][4];
#pragma unroll
    for (int nt = 0; nt < 8; nt++) { c2[nt][0]=0.f; c2[nt][1]=0.f; c2[nt][2]=0.f; c2[nt][3]=0.f; }
#pragma unroll
    for (int ks = 0; ks < 16; ks++) {
        unsigned a0 = Pu[mrow*132 + ks*8 + kc];
        unsigned a1 = Pu[(mrow+8)*132 + ks*8 + kc];
        unsigned a2 = Pu[mrow*132 + ks*8 + kc + 4];
        unsigned a3 = Pu[(mrow+8)*132 + ks*8 + kc + 4];
#pragma unroll
        for (int nt = 0; nt < 8; nt++) {
            unsigned b0 = Vt[(nt*8+qr)*129 + ks*8 + kc];
            unsigned b1 = Vt[(nt*8+qr)*129 + ks*8 + kc + 4];
            MMA_TF32(c2[nt][0],c2[nt][1],c2[nt][2],c2[nt][3], a0,a1,a2,a3, b0,b1);
        }
    }
#pragma unroll
    for (int nt = 0; nt < 8; nt++) {
        int d = nt*8 + 2*kc;
        float2 o0; o0.x = c2[nt][0]; o0.y = c2[nt][1];
        float2 o1; o1.x = c2[nt][2]; o1.y = c2[nt][3];
        *(float2*)(g_ALN + ((size_t)(b*Tt + mrow)*Nn + n)*Dd + d)     = o0;
        *(float2*)(g_ALN + ((size_t)(b*Tt + mrow + 8)*Nn + n)*Dd + d) = o1;
    }
}

// ---------------- GCN + residual + LN1, tf32 tensor core ----------------
__global__ void __launch_bounds__(256, 2) k_gcn(const float* __restrict__ Wg,
                                                const float* __restrict__ bg,
                                                const float* __restrict__ ln1g,
                                                const float* __restrict__ ln1b) {
    extern __shared__ float sg[];
    unsigned* As  = (unsigned*)sg;
    unsigned* Bs  = As + 8704;
    unsigned* Tmp = As + 12864;
    unsigned* Wgs = As + 21568;
    float* h2 = sg;   // overlays As

    int tid = threadIdx.x;
    int blk = blockIdx.x;
    int bt = blk >> 1, half = blk & 1;
    int m0g = half * 128;
    int b = bt >> 7, t = bt & 127;
    const float* Xbt = g_ALN + (size_t)bt * 16384;

    int w = tid >> 5, lane = tid & 31;
    int qr = lane >> 2, kc = lane & 3;
    int mrow = w*16 + qr;

    for (int idx = tid; idx < 1024; idx += 256) {
        int r = idx >> 4, c4 = idx & 15;
        float4 wv = *(const float4*)(Wg + (size_t)r*64 + c4*4);
        uint4 pv; pv.x = f2tf32(wv.x); pv.y = f2tf32(wv.y);
        pv.z = f2tf32(wv.z); pv.w = f2tf32(wv.w);
        *(uint4*)(Wgs + r*68 + c4*4) = pv;
    }

    float c1[8][4];
#pragma unroll
    for (int nt = 0; nt < 8; nt++) { c1[nt][0]=0.f; c1[nt][1]=0.f; c1[nt][2]=0.f; c1[nt][3]=0.f; }

    for (int ch = 0; ch < 4; ch++) {
        __syncthreads();
        for (int idx = tid; idx < 2048; idx += 256) {
            int r = idx >> 4, c4 = idx & 15;
            *(uint4*)(As + r*68 + c4*4) =
                *(const uint4*)(g_ADPu + (size_t)(m0g + r)*256 + ch*64 + c4*4);
        }
        for (int idx = tid; idx < 1024; idx += 256) {
            int nn = idx >> 4, c4 = idx & 15;
            float4 xv = *(const float4*)(Xbt + (size_t)(ch*64 + nn)*64 + c4*4);
            Bs[(c4*4+0)*65 + nn] = f2tf32(xv.x);
            Bs[(c4*4+1)*65 + nn] = f2tf32(xv.y);
            Bs[(c4*4+2)*65 + nn] = f2tf32(xv.z);
            Bs[(c4*4+3)*65 + nn] = f2tf32(xv.w);
        }
        __syncthreads();
#pragma unroll
        for (int ks = 0; ks < 8; ks++) {
            unsigned a0 = As[mrow*68 + ks*8 + kc];
            unsigned a1 = As[(mrow+8)*68 + ks*8 + kc];
            unsigned a2 = As[mrow*68 + ks*8 + kc + 4];
            unsigned a3 = As[(mrow+8)*68 + ks*8 + kc + 4];
#pragma unroll
            for (int nt = 0; nt < 8; nt++) {
                unsigned b0 = Bs[(nt*8+qr)*65 + ks*8 + kc];
                unsigned b1 = Bs[(nt*8+qr)*65 + ks*8 + kc + 4];
                MMA_TF32(c1[nt][0],c1[nt][1],c1[nt][2],c1[nt][3], a0,a1,a2,a3, b0,b1);
            }
        }
    }

#pragma unroll
    for (int nt = 0; nt < 8; nt++) {
        int d0 = nt*8 + 2*kc;
        Tmp[mrow*68 + d0]       = f2tf32(c1[nt][0]);
        Tmp[mrow*68 + d0 + 1]   = f2tf32(c1[nt][1]);
        Tmp[(mrow+8)*68 + d0]     = f2tf32(c1[nt][2]);
        Tmp[(mrow+8)*68 + d0 + 1] = f2tf32(c1[nt][3]);
    }
    __syncwarp();

    float c2[8][4];
#pragma unroll
    for (int nt = 0; nt < 8; nt++) { c2[nt][0]=0.f; c2[nt][1]=0.f; c2[nt][2]=0.f; c2[nt][3]=0.f; }
#pragma unroll
    for (int ks = 0; ks < 8; ks++) {
        unsigned a0 = Tmp[mrow*68 + ks*8 + kc];
        unsigned a1 = Tmp[(mrow+8)*68 + ks*8 + kc];
        unsigned a2 = Tmp[mrow*68 + ks*8 + kc + 4];
        unsigned a3 = Tmp[(mrow+8)*68 + ks*8 + kc + 4];
#pragma unroll
        for (int nt = 0; nt < 8; nt++) {
            unsigned b0 = Wgs[(nt*8+qr)*68 + ks*8 + kc];
            unsigned b1 = Wgs[(nt*8+qr)*68 + ks*8 + kc + 4];
            MMA_TF32(c2[nt][0],c2[nt][1],c2[nt][2],c2[nt][3], a0,a1,a2,a3, b0,b1);
        }
    }
    __syncthreads();

#pragma unroll
    for (int nt = 0; nt < 8; nt++) {
        int e0 = nt*8 + 2*kc;
        float bx = bg[e0], by = bg[e0+1];
        h2[mrow*68 + e0]       = fmaxf(c2[nt][0] + bx, 0.f);
        h2[mrow*68 + e0 + 1]   = fmaxf(c2[nt][1] + by, 0.f);
        h2[(mrow+8)*68 + e0]     = fmaxf(c2[nt][2] + bx, 0.f);
        h2[(mrow+8)*68 + e0 + 1] = fmaxf(c2[nt][3] + by, 0.f);
    }
    __syncthreads();

    float gg0 = ln1g[lane], gg1 = ln1g[lane+32];
    float bb0 = ln1b[lane], bb1 = ln1b[lane+32];
    for (int mm = 0; mm < 16; mm++) {
        int m = w*16 + mm;
        const float* xr = Xbt + (size_t)(m0g + m)*64;
        float u0 = xr[lane]      + h2[m*68 + lane];
        float u1 = xr[lane + 32] + h2[m*68 + lane + 32];
        float su = u0 + u1;
#pragma unroll
        for (int off = 16; off > 0; off >>= 1) su += __shfl_xor_sync(0xffffffff, su, off);
        float mean = su * (1.0f/64.0f);
        float dd0 = u0 - mean, dd1 = u1 - mean;
        float q = dd0*dd0 + dd1*dd1;
#pragma unroll
        for (int off = 16; off > 0; off >>= 1) q += __shfl_xor_sync(0xffffffff, q, off);
        float rs = rsqrtf(q*(1.0f/64.0f) + 1e-5f);
        size_t o = ((size_t)(b*Nn + m0g + m)*Tt + t)*Dd;
        g_X1[o + lane]      = dd0*rs*gg0 + bb0;
        g_X1[o + lane + 32] = dd1*rs*gg1 + bb1;
    }
}

// ---------------- tensor-core GRU: all per-step x from smem ----------------
// smem (words): staging Whs[192][68]@0, Wis[192][68]@13056 (26112 total).
// After hoist, reuse: X1s tf32 [4][16][68]@0 (4352), X1f fp32 @4352 (4352),
// Hb0@8704 (1088), Hb1@9792, U0@10880, U1@11968 -> 13056 <= 26112.
__global__ void __launch_bounds__(256) k_gru_tc(const float* __restrict__ Whh,
                                                const float* __restrict__ bhh,
                                                const float* __restrict__ Wih,
                                                const float* __restrict__ bih,
                                                const float* __restrict__ ln2g,
                                                const float* __restrict__ ln2b,
                                                float* __restrict__ out) {
    extern __shared__ unsigned su_[];
    unsigned* Whs = su_;
    unsigned* Wis = su_ + 13056;
    unsigned* X1s = su_;
    float*    X1f = (float*)(su_ + 4352);
    unsigned* Hb0 = su_ + 8704;
    unsigned* Hb1 = su_ + 9792;
    float* U0 = (float*)(su_ + 10880);
    float* U1 = (float*)(su_ + 11968);

    int tid = threadIdx.x;
    int w = tid >> 5, lane = tid & 31;
    int qr = lane >> 2, kc = lane & 3;
    int s_base = blockIdx.x * 16;
    int b = s_base >> 8;
    int node0 = s_base & 255;

    // stage weights
    for (int idx = tid; idx < 3072; idx += 256) {
        int r = idx >> 4, c4 = idx & 15;
        float4 wv = *(const float4*)(Whh + (size_t)r*64 + c4*4);
        uint4 pv; pv.x = f2tf32(wv.x); pv.y = f2tf32(wv.y);
        pv.z = f2tf32(wv.z); pv.w = f2tf32(wv.w);
        *(uint4*)(Whs + r*68 + c4*4) = pv;
        float4 iv = *(const float4*)(Wih + (size_t)r*64 + c4*4);
        uint4 qv; qv.x = f2tf32(iv.x); qv.y = f2tf32(iv.y);
        qv.z = f2tf32(iv.z); qv.w = f2tf32(iv.w);
        *(uint4*)(Wis + r*68 + c4*4) = qv;
    }
    __syncthreads();

    // hoist ALL weight fragments to registers
    unsigned br_[8][2], bz_[8][2], bn_[8][2];
    unsigned wr_[8][2], wz_[8][2], wn_[8][2];
#pragma unroll
    for (int ks = 0; ks < 8; ks++) {
        int nr = (0*64 + w*8 + qr)*68 + ks*8 + kc;
        int nz = (1*64 + w*8 + qr)*68 + ks*8 + kc;
        int nn = (2*64 + w*8 + qr)*68 + ks*8 + kc;
        br_[ks][0] = Whs[nr]; br_[ks][1] = Whs[nr + 4];
        bz_[ks][0] = Whs[nz]; bz_[ks][1] = Whs[nz + 4];
        bn_[ks][0] = Whs[nn]; bn_[ks][1] = Whs[nn + 4];
        wr_[ks][0] = Wis[nr]; wr_[ks][1] = Wis[nr + 4];
        wz_[ks][0] = Wis[nz]; wz_[ks][1] = Wis[nz + 4];
        wn_[ks][0] = Wis[nn]; wn_[ks][1] = Wis[nn + 4];
    }
    __syncthreads();   // staging region now reusable

    for (int idx = tid; idx < 1088; idx += 256) Hb0[idx] = 0;
    // covered by chunk-top barrier below

    int col0 = w*8 + 2*kc;
    float2 bhr = *(const float2*)(bhh + col0);
    float2 bhz = *(const float2*)(bhh + 64 + col0);
    float2 bhn = *(const float2*)(bhh + 128 + col0);
    float2 bir = *(const float2*)(bih + col0);
    float2 biz = *(const float2*)(bih + 64 + col0);
    float2 bin_ = *(const float2*)(bih + 128 + col0);
    float g2a = ln2g[lane], g2b = ln2g[lane+32];
    float b2a = ln2b[lane], b2b = ln2b[lane+32];

    float h_old[4] = {0.f, 0.f, 0.f, 0.f};

    for (int tc = 0; tc < Tt; tc += 4) {
        __syncthreads();   // fence previous chunk's X1f reads before restaging

        // stage x1 chunk: tf32 for mma, fp32 for residual/LN
        for (int idx = tid; idx < 4096; idx += 256) {
            int s = idx >> 10, rem = idx & 1023, row = rem >> 6, col = rem & 63;
            float v = g_X1[(size_t)(s_base + row)*Tt*Dd + (size_t)(tc + s)*Dd + col];
            X1s[s*1088 + row*68 + col] = f2tf32(v);
            X1f[s*1088 + row*68 + col] = v;
        }
        __syncthreads();

        // gi for 4 steps -> registers
        float gr_[4][4], gz_[4][4], gn_[4][4];
#pragma unroll
        for (int s = 0; s < 4; s++) {
            const unsigned* Xc = X1s + s*1088;
            unsigned ax[8][4];
#pragma unroll
            for (int ks = 0; ks < 8; ks++) {
                ax[ks][0] = Xc[qr*68 + ks*8 + kc];
                ax[ks][1] = Xc[(qr+8)*68 + ks*8 + kc];
                ax[ks][2] = Xc[qr*68 + ks*8 + kc + 4];
                ax[ks][3] = Xc[(qr+8)*68 + ks*8 + kc + 4];
            }
            gr_[s][0]=0.f; gr_[s][1]=0.f; gr_[s][2]=0.f; gr_[s][3]=0.f;
            gz_[s][0]=0.f; gz_[s][1]=0.f; gz_[s][2]=0.f; gz_[s][3]=0.f;
            gn_[s][0]=0.f; gn_[s][1]=0.f; gn_[s][2]=0.f; gn_[s][3]=0.f;
#pragma unroll
            for (int ks = 0; ks < 8; ks++) {
                MMA_TF32(gr_[s][0],gr_[s][1],gr_[s][2],gr_[s][3], ax[ks][0],ax[ks][1],ax[ks][2],ax[ks][3], wr_[ks][0],wr_[ks][1]);
                MMA_TF32(gz_[s][0],gz_[s][1],gz_[s][2],gz_[s][3], ax[ks][0],ax[ks][1],ax[ks][2],ax[ks][3], wz_[ks][0],wz_[ks][1]);
                MMA_TF32(gn_[s][0],gn_[s][1],gn_[s][2],gn_[s][3], ax[ks][0],ax[ks][1],ax[ks][2],ax[ks][3], wn_[ks][0],wn_[ks][1]);
            }
        }

        // serial 4 steps, 1 barrier each; all x reads from smem
#pragma unroll
        for (int s = 0; s < 4; s++) {
            int t = tc + s;
            unsigned* Hc = (t & 1) ? Hb1 : Hb0;
            unsigned* Hn = (t & 1) ? Hb0 : Hb1;
            float* Un = (t & 1) ? U1 : U0;
            const float* Xf = X1f + s*1088;

            float2 xa = *(const float2*)(Xf + qr*68 + col0);
            float2 xb = *(const float2*)(Xf + (qr+8)*68 + col0);

            float cr[4] = {0.f,0.f,0.f,0.f}, cz[4] = {0.f,0.f,0.f,0.f}, cn[4] = {0.f,0.f,0.f,0.f};
            {
                unsigned a[8][4];
#pragma unroll
                for (int ks = 0; ks < 8; ks++) {
                    a[ks][0] = Hc[qr*68 + ks*8 + kc];
                    a[ks][1] = Hc[(qr+8)*68 + ks*8 + kc];
                    a[ks][2] = Hc[qr*68 + ks*8 + kc + 4];
                    a[ks][3] = Hc[(qr+8)*68 + ks*8 + kc + 4];
                }
#pragma unroll
                for (int ks = 0; ks < 8; ks++) {
                    MMA_TF32(cr[0],cr[1],cr[2],cr[3], a[ks][0],a[ks][1],a[ks][2],a[ks][3], br_[ks][0],br_[ks][1]);
                    MMA_TF32(cz[0],cz[1],cz[2],cz[3], a[ks][0],a[ks][1],a[ks][2],a[ks][3], bz_[ks][0],bz_[ks][1]);
                    MMA_TF32(cn[0],cn[1],cn[2],cn[3], a[ks][0],a[ks][1],a[ks][2],a[ks][3], bn_[ks][0],bn_[ks][1]);
                }
            }

            float r0 = siga(gr_[s][0] + bir.x + cr[0] + bhr.x);
            float r1 = siga(gr_[s][1] + bir.y + cr[1] + bhr.y);
            float r2 = siga(gr_[s][2] + bir.x + cr[2] + bhr.x);
            float r3 = siga(gr_[s][3] + bir.y + cr[3] + bhr.y);
            float z0 = siga(gz_[s][0] + biz.x + cz[0] + bhz.x);
            float z1 = siga(gz_[s][1] + biz.y + cz[1] + bhz.y);
            float z2 = siga(gz_[s][2] + biz.x + cz[2] + bhz.x);
            float z3 = siga(gz_[s][3] + biz.y + cz[3] + bhz.y);
            float n0 = tanha(gn_[s][0] + bin_.x + r0*(cn[0] + bhn.x));
            float n1 = tanha(gn_[s][1] + bin_.y + r1*(cn[1] + bhn.y));
            float n2 = tanha(gn_[s][2] + bin_.x + r2*(cn[2] + bhn.x));
            float n3 = tanha(gn_[s][3] + bin_.y + r3*(cn[3] + bhn.y));
            float h0 = (1.f - z0)*n0 + z0*h_old[0];
            float h1 = (1.f - z1)*n1 + z1*h_old[1];
            float h2v = (1.f - z2)*n2 + z2*h_old[2];
            float h3 = (1.f - z3)*n3 + z3*h_old[3];
            h_old[0] = h0; h_old[1] = h1; h_old[2] = h2v; h_old[3] = h3;

            uint2 hp0; hp0.x = f2tf32(h0); hp0.y = f2tf32(h1);
            uint2 hp1; hp1.x = f2tf32(h2v); hp1.y = f2tf32(h3);
            *(uint2*)(Hn + qr*68 + col0)     = hp0;
            *(uint2*)(Hn + (qr+8)*68 + col0) = hp1;
            float2 up0; up0.x = xa.x + h0; up0.y = xa.y + h1;
            float2 up1; up1.x = xb.x + h2v; up1.y = xb.y + h3;
            *(float2*)(Un + qr*68 + col0)     = up0;
            *(float2*)(Un + (qr+8)*68 + col0) = up1;
            __syncthreads();

            // LN + residual + output: warp w owns rows 2w, 2w+1; x from smem
#pragma unroll
            for (int rr = 0; rr < 2; rr++) {
                int row = w*2 + rr;
                float v0 = Un[row*68 + lane], v1 = Un[row*68 + lane + 32];
                float sv = v0 + v1, qv = v0*v0 + v1*v1;
#pragma unroll
                for (int off = 16; off > 0; off >>= 1) {
                    sv += __shfl_xor_sync(0xffffffff, sv, off);
                    qv += __shfl_xor_sync(0xffffffff, qv, off);
                }
                float mean = sv * (1.0f/64.0f);
                float var = qv*(1.0f/64.0f) - mean*mean;
                float rs = rsqrtf(var + 1e-5f);
                float x0v = Xf[row*68 + lane], x1v = Xf[row*68 + lane + 32];
                size_t oo = (size_t)b*Tt*Nn*Dd + (size_t)t*Nn*Dd + (size_t)(node0 + row)*Dd;
                out[oo + lane]      = x0v + (v0 - mean)*rs*g2a + b2a;
                out[oo + lane + 32] = x1v + (v1 - mean)*rs*g2b + b2b;
            }
        }
    }
}

// ---------------- launcher ----------------
extern "C" void kernel_launch(void* const* d_in, const int* in_sizes, int n_in,
                              void* d_out, int out_size) {
    (void)in_sizes; (void)n_in; (void)out_size;
    const float* H_i  = (const float*)d_in[0];
    const float* H_j  = (const float*)d_in[1];
    const float* Wq   = (const float*)d_in[2];
    const float* bq   = (const float*)d_in[3];
    const float* Wk   = (const float*)d_in[4];
    const float* bk   = (const float*)d_in[5];
    const float* Wv   = (const float*)d_in[6];
    const float* bv   = (const float*)d_in[7];
    const float* lgam = (const float*)d_in[8];
    const float* ltau = (const float*)d_in[9];
    const float* e1   = (const float*)d_in[10];
    const float* e2   = (const float*)d_in[11];
    const float* Wg   = (const float*)d_in[12];
    const float* bg   = (const float*)d_in[13];
    const float* ln1g = (const float*)d_in[14];
    const float* ln1b = (const float*)d_in[15];
    const float* Wih  = (const float*)d_in[16];
    const float* Whh  = (const float*)d_in[17];
    const float* bih  = (const float*)d_in[18];
    const float* bhh  = (const float*)d_in[19];
    const float* ln2g = (const float*)d_in[20];
    const float* ln2b = (const float*)d_in[21];
    float* out = (float*)d_out;

    const int ATTN_SMEM = 42688 * 4;   // 170752 B
    const int GCN_SMEM  = 25920 * 4;   // 103680 B
    const int GRU_SMEM  = 26112 * 4;   // 104448 B
    cudaFuncSetAttribute(k_attn, cudaFuncAttributeMaxDynamicSharedMemorySize, ATTN_SMEM);
    cudaFuncSetAttribute(k_gcn,  cudaFuncAttributeMaxDynamicSharedMemorySize, GCN_SMEM);
    cudaFuncSetAttribute(k_gru_tc, cudaFuncAttributeMaxDynamicSharedMemorySize, GRU_SMEM);

    k_adj<<<256, 256>>>(e1, e2);
    k_attn<<<Bb*Nn, 256, ATTN_SMEM>>>(H_i, H_j, Wq, bq, Wk, bk, Wv, bv, lgam, ltau);
    k_gcn<<<Bb*Tt*2, 256, GCN_SMEM>>>(Wg, bg, ln1g, ln1b);
    k_gru_tc<<<Bb*Nn/16, 256, GRU_SMEM>>>(Whh, bhh, Wih, bih, ln2g, ln2b, out);
}